// round 8
// baseline (speedup 1.0000x reference)
#include <cuda_runtime.h>
#include <cuda_bf16.h>
#include <math.h>
#include <cstdint>

// Problem constants
#define BB 2
#define TT 2048
#define CC 2048
#define HH 16
#define HKV 8
#define DD 128
#define NROW (BB*TT)          // 4096

// ---------------- scratch (device globals; no allocation allowed) ----------
__device__ float g_qkv[(size_t)NROW * 4096];   // cols: 0-2047 q, 2048-3071 k, 3072-4095 v
__device__ float g_o[(size_t)NROW * CC];

__device__ __align__(16) int8_t g_xq0[(size_t)NROW * CC];
__device__ __align__(16) int8_t g_xq1[(size_t)NROW * CC];
__device__ __align__(16) int8_t g_oq0[(size_t)NROW * CC];
__device__ __align__(16) int8_t g_oq1[(size_t)NROW * CC];
__device__ __align__(16) int8_t g_wq0[(size_t)4096 * CC];   // [Wq|Wk|Wv]^T rows
__device__ __align__(16) int8_t g_wq1[(size_t)4096 * CC];
__device__ __align__(16) int8_t g_wpq0[(size_t)CC * CC];
__device__ __align__(16) int8_t g_wpq1[(size_t)CC * CC];
__device__ float g_sx[NROW];
__device__ float g_so[NROW];
__device__ float g_sw[4096];
__device__ float g_swp[CC];
__device__ unsigned g_cmw[4096];
__device__ unsigned g_cmwp[CC];

// head-major bf16 hi/lo Q/K/V for attention
__device__ __align__(16) __nv_bfloat16 g_qh[(size_t)BB * HH * TT * DD];
__device__ __align__(16) __nv_bfloat16 g_ql[(size_t)BB * HH * TT * DD];
__device__ __align__(16) __nv_bfloat16 g_kh[(size_t)BB * HKV * TT * DD];
__device__ __align__(16) __nv_bfloat16 g_kl[(size_t)BB * HKV * TT * DD];
__device__ __align__(16) __nv_bfloat16 g_vh[(size_t)BB * HKV * TT * DD];
__device__ __align__(16) __nv_bfloat16 g_vl[(size_t)BB * HKV * TT * DD];

// ======================= low-level helpers ==================================
__device__ __forceinline__ uint32_t smem_u32(const void* p) {
    uint32_t a;
    asm("{ .reg .u64 t; cvta.to.shared.u64 t, %1; cvt.u32.u64 %0, t; }"
        : "=r"(a) : "l"(p));
    return a;
}
__device__ __forceinline__ void ldsm4(uint32_t* r, uint32_t addr) {
    asm volatile("ldmatrix.sync.aligned.m8n8.x4.shared.b16 {%0,%1,%2,%3}, [%4];"
        : "=r"(r[0]), "=r"(r[1]), "=r"(r[2]), "=r"(r[3]) : "r"(addr));
}
__device__ __forceinline__ void ldsm4t(uint32_t* r, uint32_t addr) {
    asm volatile("ldmatrix.sync.aligned.m8n8.x4.trans.shared.b16 {%0,%1,%2,%3}, [%4];"
        : "=r"(r[0]), "=r"(r[1]), "=r"(r[2]), "=r"(r[3]) : "r"(addr));
}
__device__ __forceinline__ void mma_bf16(float* d, const uint32_t* a, const uint32_t* b) {
    asm volatile(
        "mma.sync.aligned.m16n8k16.row.col.f32.bf16.bf16.f32 "
        "{%0,%1,%2,%3}, {%4,%5,%6,%7}, {%8,%9}, {%0,%1,%2,%3};"
        : "+f"(d[0]), "+f"(d[1]), "+f"(d[2]), "+f"(d[3])
        : "r"(a[0]), "r"(a[1]), "r"(a[2]), "r"(a[3]), "r"(b[0]), "r"(b[1]));
}
__device__ __forceinline__ void mma_s8(int* d, const uint32_t* a, const uint32_t* b) {
    asm volatile(
        "mma.sync.aligned.m16n8k32.row.col.s32.s8.s8.s32 "
        "{%0,%1,%2,%3}, {%4,%5,%6,%7}, {%8,%9}, {%0,%1,%2,%3};"
        : "+r"(d[0]), "+r"(d[1]), "+r"(d[2]), "+r"(d[3])
        : "r"(a[0]), "r"(a[1]), "r"(a[2]), "r"(a[3]), "r"(b[0]), "r"(b[1]));
}
__device__ __forceinline__ void cp_async16(uint32_t dst, const void* src) {
    asm volatile("cp.async.cg.shared.global [%0], [%1], 16;\n" :: "r"(dst), "l"(src));
}
#define CP_COMMIT() asm volatile("cp.async.commit_group;\n" ::: "memory")
#define CP_WAIT2()  asm volatile("cp.async.wait_group 2;\n" ::: "memory")
#define CP_WAIT1()  asm volatile("cp.async.wait_group 1;\n" ::: "memory")
#define CP_WAIT0()  asm volatile("cp.async.wait_group 0;\n" ::: "memory")

__device__ __forceinline__ __nv_bfloat162 bfpair(float a, float b) {
    __nv_bfloat162 r; r.x = __float2bfloat16(a); r.y = __float2bfloat16(b); return r;
}
__device__ __forceinline__ void packsplit(float a, float b, uint32_t& hi, uint32_t& lo) {
    __nv_bfloat16 ha = __float2bfloat16(a), hb = __float2bfloat16(b);
    __nv_bfloat162 H; H.x = ha; H.y = hb;
    __nv_bfloat162 L;
    L.x = __float2bfloat16(a - __bfloat162float(ha));
    L.y = __float2bfloat16(b - __bfloat162float(hb));
    hi = *(uint32_t*)&H; lo = *(uint32_t*)&L;
}
__device__ __forceinline__ uint32_t pack4(int a, int b, int c, int d) {
    return (uint32_t)(a & 0xff) | ((uint32_t)(b & 0xff) << 8) |
           ((uint32_t)(c & 0xff) << 16) | ((uint32_t)(d & 0xff) << 24);
}

// ======================= quantization kernels ================================
// per-row int8 2-slice quantization. in: [rows, K] fp32.
__global__ void rowquant_kernel(const float* __restrict__ in,
                                int8_t* __restrict__ q0, int8_t* __restrict__ q1,
                                float* __restrict__ sout, int K)
{
    __shared__ float red[8];
    const int row = blockIdx.x;
    const int tid = threadIdx.x;
    const float* p = in + (size_t)row * K;

    float4 v0 = *(const float4*)(p + tid * 8);
    float4 v1 = *(const float4*)(p + tid * 8 + 4);
    float m = fmaxf(fmaxf(fmaxf(fabsf(v0.x), fabsf(v0.y)), fmaxf(fabsf(v0.z), fabsf(v0.w))),
                    fmaxf(fmaxf(fabsf(v1.x), fabsf(v1.y)), fmaxf(fabsf(v1.z), fabsf(v1.w))));
    #pragma unroll
    for (int o = 16; o > 0; o >>= 1) m = fmaxf(m, __shfl_xor_sync(0xffffffffu, m, o));
    if ((tid & 31) == 0) red[tid >> 5] = m;
    __syncthreads();
    m = red[tid & 7];
    #pragma unroll
    for (int o = 4; o > 0; o >>= 1) m = fmaxf(m, __shfl_xor_sync(0xffffffffu, m, o));

    m = fmaxf(m, 1e-20f);
    float s   = m * (1.0f / 127.0f);
    float inv = 127.0f / m;
    if (tid == 0) sout[row] = s;

    int a0[8], a1[8];
    float vv[8] = {v0.x, v0.y, v0.z, v0.w, v1.x, v1.y, v1.z, v1.w};
    #pragma unroll
    for (int i = 0; i < 8; i++) {
        float t = vv[i] * inv;
        a0[i] = __float2int_rn(t);
        a1[i] = __float2int_rn((t - (float)a0[i]) * 128.0f);
    }
    uint2 p0 = make_uint2(pack4(a0[0], a0[1], a0[2], a0[3]), pack4(a0[4], a0[5], a0[6], a0[7]));
    uint2 p1 = make_uint2(pack4(a1[0], a1[1], a1[2], a1[3]), pack4(a1[4], a1[5], a1[6], a1[7]));
    *(uint2*)(q0 + (size_t)row * K + tid * 8) = p0;
    *(uint2*)(q1 + (size_t)row * K + tid * 8) = p1;
}

// column abs-max of W[K,N] (partial over 128 rows, atomicMax on float bits)
__global__ void colmax_kernel(const float* __restrict__ W, unsigned* __restrict__ cm, int N)
{
    int col = blockIdx.x * 256 + threadIdx.x;
    int r0  = blockIdx.y * 128;
    float m = 0.f;
    #pragma unroll 4
    for (int r = 0; r < 128; r++)
        m = fmaxf(m, fabsf(W[(size_t)(r0 + r) * N + col]));
    atomicMax(cm + col, __float_as_uint(m));
}

// W[K,N] -> Q0^T,Q1^T [N,K] int8 + scale per output row
__global__ void transquant_kernel(const float* __restrict__ W, const unsigned* __restrict__ cm,
                                  int8_t* __restrict__ q0t, int8_t* __restrict__ q1t,
                                  float* __restrict__ sout, int K, int N)
{
    __shared__ float t[32][33];
    int n0 = blockIdx.x * 32, k0 = blockIdx.y * 32;
    int tx = threadIdx.x, ty = threadIdx.y;   // (32, 8)
    #pragma unroll
    for (int j = 0; j < 32; j += 8)
        t[ty + j][tx] = W[(size_t)(k0 + ty + j) * N + n0 + tx];
    __syncthreads();
    #pragma unroll
    for (int j = 0; j < 32; j += 8) {
        int n = n0 + ty + j;
        float mx  = fmaxf(__uint_as_float(cm[n]), 1e-20f);
        float s   = mx * (1.0f / 127.0f);
        float inv = 127.0f / mx;
        float v = t[tx][ty + j];
        float fq = v * inv;
        int a0 = __float2int_rn(fq);
        int a1 = __float2int_rn((fq - (float)a0) * 128.0f);
        size_t oidx = (size_t)n * K + k0 + tx;
        q0t[oidx] = (int8_t)a0;
        q1t[oidx] = (int8_t)a1;
        if (k0 + tx == 0) sout[n] = s;
    }
}

// RoPE + bf16 hi/lo split + relayout [b,t,h,d] -> [b,h,t,d]; rs = input row stride
__global__ void rope_split_kernel(const float* __restrict__ in,
                                  __nv_bfloat16* __restrict__ oh,
                                  __nv_bfloat16* __restrict__ ol,
                                  int n_heads, int rs, int total)
{
    int idx = blockIdx.x * blockDim.x + threadIdx.x;
    if (idx >= total) return;
    int j = idx & 63;
    int h = (idx >> 6) % n_heads;
    int r = idx / (64 * n_heads);
    int b = r >> 11;
    int t = r & (TT - 1);

    float e = (float)(2 * j) * (1.0f / 128.0f);
    float inv = 1.0f / powf(10000.0f, e);
    float f = (float)t * inv;
    float c = cosf(f), s = sinf(f);

    const float* p = in + (size_t)r * rs + h * DD;
    float x1 = p[j], x2 = p[j + 64];
    float y1 = x1 * c - x2 * s;
    float y2 = x2 * c + x1 * s;

    size_t ob = ((size_t)(b * n_heads + h) * TT + t) * DD + j;
    __nv_bfloat16 h1 = __float2bfloat16(y1);
    __nv_bfloat16 h2 = __float2bfloat16(y2);
    oh[ob]      = h1;
    oh[ob + 64] = h2;
    ol[ob]      = __float2bfloat16(y1 - __bfloat162float(h1));
    ol[ob + 64] = __float2bfloat16(y2 - __bfloat162float(h2));
}

// V: bf16 hi/lo split + relayout [b,t,hk,d] -> [b,hk,t,d]; rs = input row stride
__global__ void v_split_kernel(const float* __restrict__ in,
                               __nv_bfloat16* __restrict__ oh,
                               __nv_bfloat16* __restrict__ ol, int rs, int total4)
{
    int idx = blockIdx.x * blockDim.x + threadIdx.x;
    if (idx >= total4) return;
    int c4 = idx & 31;
    int h  = (idx >> 5) & 7;
    int r  = idx >> 8;
    int b  = r >> 11;
    int t  = r & (TT - 1);
    float4 v = *(const float4*)(in + (size_t)r * rs + h * DD + c4 * 4);
    size_t ob = ((size_t)(b * HKV + h) * TT + t) * DD + c4 * 4;
    __nv_bfloat16 h0 = __float2bfloat16(v.x), h1 = __float2bfloat16(v.y);
    __nv_bfloat16 h2 = __float2bfloat16(v.z), h3 = __float2bfloat16(v.w);
    __nv_bfloat162 p0; p0.x = h0; p0.y = h1;
    __nv_bfloat162 p1; p1.x = h2; p1.y = h3;
    *(__nv_bfloat162*)(oh + ob)     = p0;
    *(__nv_bfloat162*)(oh + ob + 2) = p1;
    *(__nv_bfloat162*)(ol + ob)     = bfpair(v.x - __bfloat162float(h0),
                                             v.y - __bfloat162float(h1));
    *(__nv_bfloat162*)(ol + ob + 2) = bfpair(v.z - __bfloat162float(h2),
                                             v.w - __bfloat162float(h3));
}

// ======================= int8 2-slice GEMM (128x128 CTA, 3-stage) ===========
// C[M,N] = sa[m]*sb[n]*(Q0a.Q0b + (Q0a.Q1b + Q1a.Q0b)/128)
#define GBM 128
#define GBN 128
#define GBK 64                              // int8 elements per k-tile
#define GEMM_THREADS 256
#define ROW_BYTES 80                        // 64B data + 16B pad
#define ARR_SZ (128 * ROW_BYTES)            // 10240 per array
#define STAGE_BYTES (4 * ARR_SZ)            // Aq0, Aq1, Bq0, Bq1 = 40960
#define GEMM_SMEM (3 * STAGE_BYTES)         // 122880

__global__ void __launch_bounds__(GEMM_THREADS, 1)
gemm_s8_kernel(const int8_t* __restrict__ Aq0, const int8_t* __restrict__ Aq1,
               const int8_t* __restrict__ Bq0, const int8_t* __restrict__ Bq1,
               const float* __restrict__ sa, const float* __restrict__ sb,
               float* __restrict__ C, int M, int N, int K)
{
    extern __shared__ char smg[];
    const uint32_t sbase = smem_u32(smg);
    const int tid  = threadIdx.x;
    const int lane = tid & 31;
    const int wid  = tid >> 5;
    const int warp_m = wid >> 2;     // 0..1 (64 rows)
    const int warp_n = wid & 3;      // 0..3 (32 cols)
    const int m0 = blockIdx.y * GBM;
    const int n0 = blockIdx.x * GBN;

    const int8_t* gsrc[4] = { Aq0, Aq1, Bq0, Bq1 };

    auto load_stage = [&](int kt) {
        const uint32_t sdst = sbase + (kt % 3) * STAGE_BYTES;
        const int kofs = kt * GBK;
        #pragma unroll
        for (int i = 0; i < 8; i++) {
            int task = tid + GEMM_THREADS * i;   // 0..2047
            int arr = task >> 9;                 // 0..3
            int rem = task & 511;
            int row = rem >> 2, c = rem & 3;
            int grow = (arr < 2) ? (m0 + row) : (n0 + row);
            cp_async16(sdst + arr * ARR_SZ + row * ROW_BYTES + c * 16,
                       gsrc[arr] + (size_t)grow * K + kofs + c * 16);
        }
        CP_COMMIT();
    };

    int acc0[4][4][4], acc1[4][4][4];
    #pragma unroll
    for (int i = 0; i < 4; i++)
        #pragma unroll
        for (int j = 0; j < 4; j++)
            #pragma unroll
            for (int r = 0; r < 4; r++) { acc0[i][j][r] = 0; acc1[i][j][r] = 0; }

    const int ktiles = K / GBK;

    load_stage(0);
    load_stage(1);

    const uint32_t a_row_b = (uint32_t)(warp_m * 64 + (lane & 15)) * ROW_BYTES
                           + ((lane >> 4) * 16);
    const uint32_t b_row_b = (uint32_t)(warp_n * 32 + ((lane >> 4) & 1) * 8 + (lane & 7)) * ROW_BYTES
                           + (((lane >> 3) & 1) * 16);

    for (int kt = 0; kt < ktiles; kt++) {
        if (kt + 2 < ktiles) { load_stage(kt + 2); CP_WAIT2(); }
        else if (kt + 1 < ktiles) { CP_WAIT1(); }
        else { CP_WAIT0(); }
        __syncthreads();

        const uint32_t st = sbase + (kt % 3) * STAGE_BYTES;
        #pragma unroll
        for (int s = 0; s < 2; s++) {          // two k32 steps (32 bytes each)
            const uint32_t koff = s * 32;
            uint32_t a0[4][4], a1[4][4];
            #pragma unroll
            for (int mt = 0; mt < 4; mt++) {
                uint32_t ad = st + a_row_b + mt * (16 * ROW_BYTES) + koff;
                ldsm4(a0[mt], ad);                   // Aq0
                ldsm4(a1[mt], ad + ARR_SZ);          // Aq1
            }
            uint32_t b0[2][4], b1[2][4];
            #pragma unroll
            for (int np = 0; np < 2; np++) {
                uint32_t bd = st + 2 * ARR_SZ + b_row_b + np * (16 * ROW_BYTES) + koff;
                ldsm4(b0[np], bd);                   // Bq0
                ldsm4(b1[np], bd + ARR_SZ);          // Bq1
            }
            #pragma unroll
            for (int mt = 0; mt < 4; mt++)
                #pragma unroll
                for (int nt = 0; nt < 4; nt++) {
                    const uint32_t* b0p = &b0[nt >> 1][(nt & 1) * 2];
                    const uint32_t* b1p = &b1[nt >> 1][(nt & 1) * 2];
                    mma_s8(acc0[mt][nt], a0[mt], b0p);
                    mma_s8(acc1[mt][nt], a0[mt], b1p);
                    mma_s8(acc1[mt][nt], a1[mt], b0p);
                }
        }
        __syncthreads();
    }

    // epilogue: dequantize + store fp32
    #pragma unroll
    for (int mt = 0; mt < 4; mt++) {
        int r0 = m0 + warp_m * 64 + mt * 16 + (lane >> 2);
        float sa0 = sa[r0], sa1 = sa[r0 + 8];
        #pragma unroll
        for (int nt = 0; nt < 4; nt++) {
            int cbase = n0 + warp_n * 32 + nt * 8 + (lane & 3) * 2;
            float sb0 = sb[cbase], sb1 = sb[cbase + 1];
            float v00 = sa0 * sb0 * ((float)acc0[mt][nt][0] + (float)acc1[mt][nt][0] * 0.0078125f);
            float v01 = sa0 * sb1 * ((float)acc0[mt][nt][1] + (float)acc1[mt][nt][1] * 0.0078125f);
            float v10 = sa1 * sb0 * ((float)acc0[mt][nt][2] + (float)acc1[mt][nt][2] * 0.0078125f);
            float v11 = sa1 * sb1 * ((float)acc0[mt][nt][3] + (float)acc1[mt][nt][3] * 0.0078125f);
            *(float2*)(C + (size_t)r0 * N + cbase)       = make_float2(v00, v01);
            *(float2*)(C + (size_t)(r0 + 8) * N + cbase) = make_float2(v10, v11);
        }
    }
}

// ================= Flash attention on HMMA (8 warps x 16 rows) ==============
#define ABQ 128
#define ABK 64
#define AROW 136
#define AQH 0
#define AQL (ABQ*AROW)
#define AKH (2*ABQ*AROW)
#define AKL (AKH + ABK*AROW)
#define AVH (AKL + ABK*AROW)
#define AVL (AVH + ABK*AROW)
#define ASM_ELEMS (AVL + ABK*AROW)
#define ASM_BYTES (ASM_ELEMS*2)        // 139264
#define ATTN_SCALE 0.08838834764831843f

__global__ void __launch_bounds__(256, 1)
attn_mma_kernel(const __nv_bfloat16* __restrict__ Qh, const __nv_bfloat16* __restrict__ Ql,
                const __nv_bfloat16* __restrict__ Kh, const __nv_bfloat16* __restrict__ Kl,
                const __nv_bfloat16* __restrict__ Vh, const __nv_bfloat16* __restrict__ Vl,
                float* __restrict__ O)
{
    extern __shared__ __align__(1024) char smA[];
    const uint32_t sb = smem_u32(smA);

    const int tid  = threadIdx.x;
    const int lane = tid & 31;
    const int w    = tid >> 5;
    const int qi   = gridDim.x - 1 - blockIdx.x;
    const int h    = blockIdx.y;
    const int b    = blockIdx.z;
    const int hk   = h >> 1;
    const int qbase = qi * ABQ;

    const size_t qb0 = ((size_t)(b * HH + h) * TT + qbase) * DD;
    const size_t kb0 = ((size_t)(b * HKV + hk) * TT) * DD;
    const __nv_bfloat16* kvsrc[4] = { Kh, Kl, Vh, Vl };

    #pragma unroll
    for (int i = 0; i < 16; i++) {
        int task = tid + 256 * i;
        int arr = task >> 11;
        int rem = task & 2047;
        int row = rem >> 4;
        int c   = rem & 15;
        const __nv_bfloat16* src = (arr ? Ql : Qh) + qb0 + (size_t)row * DD + c * 8;
        cp_async16(sb + 2 * (uint32_t)((arr ? AQL : AQH) + row * AROW) + c * 16, src);
    }
    CP_COMMIT();

    float m0 = -INFINITY, m1 = -INFINITY, l0 = 0.f, l1 = 0.f;
    float oacc[16][4];
    #pragma unroll
    for (int j = 0; j < 16; j++)
        #pragma unroll
        for (int r = 0; r < 4; r++) oacc[j][r] = 0.f;

    const uint32_t qA_h = sb + 2*(uint32_t)(AQH + (w*16 + (lane & 15))*AROW) + (lane >> 4)*16;
    const uint32_t qA_l = qA_h + 2*(uint32_t)(AQL - AQH);
    const int krow  = ((lane >> 4) & 1)*8 + (lane & 7);
    const int kcolh = ((lane >> 3) & 1)*16;
    const int vrow  = ((lane >> 3) & 1)*8 + (lane & 7);
    const int vcolh = (lane >> 4)*16;

    const int ntiles = 2*qi + 2;
    const int qr0 = qbase + w*16 + (lane >> 2);

    for (int t = 0; t < ntiles; t++) {
        const int k0 = t * ABK;
        __syncthreads();

        #pragma unroll
        for (int i = 0; i < 8; i++) {
            int task = tid + 256 * i;
            int arr = task >> 10;
            int rem = task & 1023;
            int row = rem >> 4;
            int c   = rem & 15;
            cp_async16(sb + 2*(uint32_t)(AKH + arr*(ABK*AROW) + row*AROW) + c*16,
                       kvsrc[arr] + kb0 + (size_t)(k0 + row)*DD + c*8);
        }
        CP_COMMIT();
        #pragma unroll
        for (int i = 8; i < 16; i++) {
            int task = tid + 256 * i;
            int arr = task >> 10;
            int rem = task & 1023;
            int row = rem >> 4;
            int c   = rem & 15;
            cp_async16(sb + 2*(uint32_t)(AKH + arr*(ABK*AROW) + row*AROW) + c*16,
                       kvsrc[arr] + kb0 + (size_t)(k0 + row)*DD + c*8);
        }
        CP_COMMIT();

        CP_WAIT1();
        __syncthreads();

        float sacc[8][4];
        #pragma unroll
        for (int j = 0; j < 8; j++)
            #pragma unroll
            for (int r = 0; r < 4; r++) sacc[j][r] = 0.f;

        #pragma unroll
        for (int s = 0; s < 8; s++) {
            uint32_t ah[4], al[4];
            ldsm4(ah, qA_h + s*32);
            ldsm4(al, qA_l + s*32);
            #pragma unroll
            for (int jj = 0; jj < 4; jj++) {
                uint32_t kh[4], kl[4];
                uint32_t ka = sb + 2*(uint32_t)(AKH + (16*jj + krow)*AROW) + s*32 + kcolh;
                ldsm4(kh, ka);
                ldsm4(kl, ka + 2*(uint32_t)(AKL - AKH));
                mma_bf16(sacc[2*jj],   ah, &kh[0]);
                mma_bf16(sacc[2*jj],   ah, &kl[0]);
                mma_bf16(sacc[2*jj],   al, &kh[0]);
                mma_bf16(sacc[2*jj+1], ah, &kh[2]);
                mma_bf16(sacc[2*jj+1], ah, &kl[2]);
                mma_bf16(sacc[2*jj+1], al, &kh[2]);
            }
        }

        CP_WAIT0();
        __syncthreads();

        const bool domask = (t >= ntiles - 2);
        float mx0 = -INFINITY, mx1 = -INFINITY;
        #pragma unroll
        for (int j = 0; j < 8; j++) {
            #pragma unroll
            for (int r = 0; r < 4; r++) {
                float sv = sacc[j][r] * ATTN_SCALE;
                if (domask) {
                    int col = k0 + 8*j + (lane & 3)*2 + (r & 1);
                    int qr  = qr0 + ((r >= 2) ? 8 : 0);
                    if (col > qr) sv = -INFINITY;
                }
                sacc[j][r] = sv;
                if (r < 2) mx0 = fmaxf(mx0, sv); else mx1 = fmaxf(mx1, sv);
            }
        }
        mx0 = fmaxf(mx0, __shfl_xor_sync(0xffffffffu, mx0, 1));
        mx0 = fmaxf(mx0, __shfl_xor_sync(0xffffffffu, mx0, 2));
        mx1 = fmaxf(mx1, __shfl_xor_sync(0xffffffffu, mx1, 1));
        mx1 = fmaxf(mx1, __shfl_xor_sync(0xffffffffu, mx1, 2));

        float m0n = fmaxf(m0, mx0), m1n = fmaxf(m1, mx1);
        float a0 = __expf(m0 - m0n), a1 = __expf(m1 - m1n);
        float ls0 = 0.f, ls1 = 0.f;
        #pragma unroll
        for (int j = 0; j < 8; j++) {
            float p0 = __expf(sacc[j][0] - m0n);
            float p1 = __expf(sacc[j][1] - m0n);
            float p2 = __expf(sacc[j][2] - m1n);
            float p3 = __expf(sacc[j][3] - m1n);
            sacc[j][0] = p0; sacc[j][1] = p1; sacc[j][2] = p2; sacc[j][3] = p3;
            ls0 += p0 + p1; ls1 += p2 + p3;
        }
        ls0 += __shfl_xor_sync(0xffffffffu, ls0, 1);
        ls0 += __shfl_xor_sync(0xffffffffu, ls0, 2);
        ls1 += __shfl_xor_sync(0xffffffffu, ls1, 1);
        ls1 += __shfl_xor_sync(0xffffffffu, ls1, 2);

        l0 = l0 * a0 + ls0;
        l1 = l1 * a1 + ls1;
        m0 = m0n; m1 = m1n;
        #pragma unroll
        for (int j = 0; j < 16; j++) {
            oacc[j][0] *= a0; oacc[j][1] *= a0;
            oacc[j][2] *= a1; oacc[j][3] *= a1;
        }

        #pragma unroll
        for (int s2 = 0; s2 < 4; s2++) {
            uint32_t ahp[4], alp[4];
            packsplit(sacc[2*s2][0],   sacc[2*s2][1],   ahp[0], alp[0]);
            packsplit(sacc[2*s2][2],   sacc[2*s2][3],   ahp[1], alp[1]);
            packsplit(sacc[2*s2+1][0], sacc[2*s2+1][1], ahp[2], alp[2]);
            packsplit(sacc[2*s2+1][2], sacc[2*s2+1][3], ahp[3], alp[3]);
            uint32_t va = sb + 2*(uint32_t)(AVH + (16*s2 + vrow)*AROW) + vcolh;
            #pragma unroll
            for (int dd = 0; dd < 8; dd++) {
                uint32_t vh[4], vl[4];
                ldsm4t(vh, va + dd*32);
                ldsm4t(vl, va + dd*32 + 2*(uint32_t)(AVL - AVH));
                mma_bf16(oacc[2*dd],   ahp, &vh[0]);
                mma_bf16(oacc[2*dd],   ahp, &vl[0]);
                mma_bf16(oacc[2*dd],   alp, &vh[0]);
                mma_bf16(oacc[2*dd+1], ahp, &vh[2]);
                mma_bf16(oacc[2*dd+1], ahp, &vl[2]);
                mma_bf16(oacc[2*dd+1], alp, &vh[2]);
            }
        }
    }

    // epilogue: normalize + write fp32 O ([b,t,h*d] layout)
    float i0 = 1.f / l0, i1 = 1.f / l1;
    const int row0 = qbase + w*16 + (lane >> 2);
    const int col0 = (lane & 3)*2;
    #pragma unroll
    for (int j = 0; j < 16; j++) {
        int col = j*8 + col0;
        size_t base0 = ((size_t)(b*TT + row0)*HH + h)*DD + col;
        size_t base1 = base0 + (size_t)8*HH*DD;
        *(float2*)(O + base0) = make_float2(oacc[j][0]*i0, oacc[j][1]*i0);
        *(float2*)(O + base1) = make_float2(oacc[j][2]*i1, oacc[j][3]*i1);
    }
}

// ---------------- host entry -------------------------------------------------
extern "C" void kernel_launch(void* const* d_in, const int* in_sizes, int n_in,
                              void* d_out, int out_size)
{
    const float* x  = (const float*)d_in[0];
    const float* Wq = (const float*)d_in[1];
    const float* Wk = (const float*)d_in[2];
    const float* Wv = (const float*)d_in[3];
    const float* Wp = (const float*)d_in[4];
    float* out = (float*)d_out;

    float *qkv, *o, *sx, *so, *sw, *swp;
    int8_t *xq0, *xq1, *oq0, *oq1, *wq0, *wq1, *wpq0, *wpq1;
    unsigned *cmw, *cmwp;
    __nv_bfloat16 *qh, *ql, *kh, *kl, *vh, *vl;
    cudaGetSymbolAddress((void**)&qkv, g_qkv);
    cudaGetSymbolAddress((void**)&o, g_o);
    cudaGetSymbolAddress((void**)&xq0, g_xq0); cudaGetSymbolAddress((void**)&xq1, g_xq1);
    cudaGetSymbolAddress((void**)&oq0, g_oq0); cudaGetSymbolAddress((void**)&oq1, g_oq1);
    cudaGetSymbolAddress((void**)&wq0, g_wq0); cudaGetSymbolAddress((void**)&wq1, g_wq1);
    cudaGetSymbolAddress((void**)&wpq0, g_wpq0); cudaGetSymbolAddress((void**)&wpq1, g_wpq1);
    cudaGetSymbolAddress((void**)&sx, g_sx);   cudaGetSymbolAddress((void**)&so, g_so);
    cudaGetSymbolAddress((void**)&sw, g_sw);   cudaGetSymbolAddress((void**)&swp, g_swp);
    cudaGetSymbolAddress((void**)&cmw, g_cmw); cudaGetSymbolAddress((void**)&cmwp, g_cmwp);
    cudaGetSymbolAddress((void**)&qh, g_qh);   cudaGetSymbolAddress((void**)&ql, g_ql);
    cudaGetSymbolAddress((void**)&kh, g_kh);   cudaGetSymbolAddress((void**)&kl, g_kl);
    cudaGetSymbolAddress((void**)&vh, g_vh);   cudaGetSymbolAddress((void**)&vl, g_vl);

    cudaFuncSetAttribute(gemm_s8_kernel, cudaFuncAttributeMaxDynamicSharedMemorySize, GEMM_SMEM);
    cudaFuncSetAttribute(attn_mma_kernel, cudaFuncAttributeMaxDynamicSharedMemorySize, ASM_BYTES);

    // (0) quantize x rows
    rowquant_kernel<<<NROW, 256>>>(x, xq0, xq1, sx, CC);

    // (1) column maxes of weights
    cudaMemsetAsync(cmw, 0, 4096 * sizeof(unsigned));
    cudaMemsetAsync(cmwp, 0, CC * sizeof(unsigned));
    colmax_kernel<<<dim3(CC/256, CC/128), 256>>>(Wq, cmw, CC);
    colmax_kernel<<<dim3((HKV*DD)/256, CC/128), 256>>>(Wk, cmw + 2048, HKV*DD);
    colmax_kernel<<<dim3((HKV*DD)/256, CC/128), 256>>>(Wv, cmw + 3072, HKV*DD);
    colmax_kernel<<<dim3(CC/256, CC/128), 256>>>(Wp, cmwp, CC);

    // (2) transpose + quantize weights into combined B
    transquant_kernel<<<dim3(CC/32, CC/32), dim3(32, 8)>>>(Wq, cmw, wq0, wq1, sw, CC, CC);
    transquant_kernel<<<dim3((HKV*DD)/32, CC/32), dim3(32, 8)>>>(
        Wk, cmw + 2048, wq0 + (size_t)2048*CC, wq1 + (size_t)2048*CC, sw + 2048, CC, HKV*DD);
    transquant_kernel<<<dim3((HKV*DD)/32, CC/32), dim3(32, 8)>>>(
        Wv, cmw + 3072, wq0 + (size_t)3072*CC, wq1 + (size_t)3072*CC, sw + 3072, CC, HKV*DD);
    transquant_kernel<<<dim3(CC/32, CC/32), dim3(32, 8)>>>(Wp, cmwp, wpq0, wpq1, swp, CC, CC);

    // (3) fused QKV projection: [4096, 2048] x [4096, 2048]^T -> [4096, 4096]
    gemm_s8_kernel<<<dim3(4096/GBN, NROW/GBM), GEMM_THREADS, GEMM_SMEM>>>(
        xq0, xq1, wq0, wq1, sx, sw, qkv, NROW, 4096, CC);

    // (4) RoPE + split + head-major relayout
    {
        int totq = NROW * HH * 64;
        rope_split_kernel<<<(totq + 255) / 256, 256>>>(qkv, qh, ql, HH, 4096, totq);
        int totk = NROW * HKV * 64;
        rope_split_kernel<<<(totk + 255) / 256, 256>>>(qkv + 2048, kh, kl, HKV, 4096, totk);
        int totv = NROW * HKV * 32;
        v_split_kernel<<<(totv + 255) / 256, 256>>>(qkv + 3072, vh, vl, 4096, totv);
    }

    // (5) attention (bf16 HMMA), fp32 O out
    attn_mma_kernel<<<dim3(TT / ABQ, HH, BB), 256, ASM_BYTES>>>(qh, ql, kh, kl, vh, vl, o);

    // (6) quantize O rows, (7) output projection
    rowquant_kernel<<<NROW, 256>>>(o, oq0, oq1, so, CC);
    gemm_s8_kernel<<<dim3(CC/GBN, NROW/GBM), GEMM_THREADS, GEMM_SMEM>>>(
        oq0, oq1, wpq0, wpq1, so, swp, out, NROW, CC, CC);
}

// round 9
// speedup vs baseline: 2.5787x; 2.5787x over previous
#include <cuda_runtime.h>
#include <cuda_bf16.h>
#include <cuda_fp16.h>
#include <math.h>
#include <cstdint>

// Problem constants
#define BB 2
#define TT 2048
#define CC 2048
#define HH 16
#define HKV 8
#define DD 128
#define NROW (BB*TT)          // 4096

// ---------------- scratch (device globals; no allocation allowed) ----------
__device__ float g_qkv[(size_t)NROW * 4096];   // cols: 0-2047 q, 2048-3071 k, 3072-4095 v

__device__ __align__(16) __half g_xh[(size_t)NROW * CC];
__device__ __align__(16) __half g_xl[(size_t)NROW * CC];
__device__ __align__(16) __half g_oh[(size_t)NROW * CC];
__device__ __align__(16) __half g_ol[(size_t)NROW * CC];
__device__ __align__(16) __half g_wqkv[(size_t)4096 * CC];   // [Wq|Wk|Wv]^T
__device__ __align__(16) __half g_wp[(size_t)CC * CC];       // Wp^T

// head-major bf16 hi/lo Q/K/V for attention
__device__ __align__(16) __nv_bfloat16 g_qh[(size_t)BB * HH * TT * DD];
__device__ __align__(16) __nv_bfloat16 g_ql[(size_t)BB * HH * TT * DD];
__device__ __align__(16) __nv_bfloat16 g_kh[(size_t)BB * HKV * TT * DD];
__device__ __align__(16) __nv_bfloat16 g_kl[(size_t)BB * HKV * TT * DD];
__device__ __align__(16) __nv_bfloat16 g_vh[(size_t)BB * HKV * TT * DD];
__device__ __align__(16) __nv_bfloat16 g_vl[(size_t)BB * HKV * TT * DD];

// ======================= low-level helpers ==================================
__device__ __forceinline__ uint32_t smem_u32(const void* p) {
    uint32_t a;
    asm("{ .reg .u64 t; cvta.to.shared.u64 t, %1; cvt.u32.u64 %0, t; }"
        : "=r"(a) : "l"(p));
    return a;
}
__device__ __forceinline__ void ldsm4(uint32_t* r, uint32_t addr) {
    asm volatile("ldmatrix.sync.aligned.m8n8.x4.shared.b16 {%0,%1,%2,%3}, [%4];"
        : "=r"(r[0]), "=r"(r[1]), "=r"(r[2]), "=r"(r[3]) : "r"(addr));
}
__device__ __forceinline__ void ldsm4t(uint32_t* r, uint32_t addr) {
    asm volatile("ldmatrix.sync.aligned.m8n8.x4.trans.shared.b16 {%0,%1,%2,%3}, [%4];"
        : "=r"(r[0]), "=r"(r[1]), "=r"(r[2]), "=r"(r[3]) : "r"(addr));
}
__device__ __forceinline__ void mma_bf16(float* d, const uint32_t* a, const uint32_t* b) {
    asm volatile(
        "mma.sync.aligned.m16n8k16.row.col.f32.bf16.bf16.f32 "
        "{%0,%1,%2,%3}, {%4,%5,%6,%7}, {%8,%9}, {%0,%1,%2,%3};"
        : "+f"(d[0]), "+f"(d[1]), "+f"(d[2]), "+f"(d[3])
        : "r"(a[0]), "r"(a[1]), "r"(a[2]), "r"(a[3]), "r"(b[0]), "r"(b[1]));
}
__device__ __forceinline__ void mma_f16(float* d, const uint32_t* a, const uint32_t* b) {
    asm volatile(
        "mma.sync.aligned.m16n8k16.row.col.f32.f16.f16.f32 "
        "{%0,%1,%2,%3}, {%4,%5,%6,%7}, {%8,%9}, {%0,%1,%2,%3};"
        : "+f"(d[0]), "+f"(d[1]), "+f"(d[2]), "+f"(d[3])
        : "r"(a[0]), "r"(a[1]), "r"(a[2]), "r"(a[3]), "r"(b[0]), "r"(b[1]));
}
__device__ __forceinline__ void cp_async16(uint32_t dst, const void* src) {
    asm volatile("cp.async.cg.shared.global [%0], [%1], 16;\n" :: "r"(dst), "l"(src));
}
#define CP_COMMIT() asm volatile("cp.async.commit_group;\n" ::: "memory")
#define CP_WAIT2()  asm volatile("cp.async.wait_group 2;\n" ::: "memory")
#define CP_WAIT1()  asm volatile("cp.async.wait_group 1;\n" ::: "memory")
#define CP_WAIT0()  asm volatile("cp.async.wait_group 0;\n" ::: "memory")

__device__ __forceinline__ __nv_bfloat162 bfpair(float a, float b) {
    __nv_bfloat162 r; r.x = __float2bfloat16(a); r.y = __float2bfloat16(b); return r;
}
// bf16 hi/lo pack (for attention P operands)
__device__ __forceinline__ void packsplit(float a, float b, uint32_t& hi, uint32_t& lo) {
    __nv_bfloat16 ha = __float2bfloat16(a), hb = __float2bfloat16(b);
    __nv_bfloat162 H; H.x = ha; H.y = hb;
    __nv_bfloat162 L;
    L.x = __float2bfloat16(a - __bfloat162float(ha));
    L.y = __float2bfloat16(b - __bfloat162float(hb));
    hi = *(uint32_t*)&H; lo = *(uint32_t*)&L;
}
// fp16 hi/lo pack (for O -> out-projection A operand)
__device__ __forceinline__ void packsplit_h(float a, float b, uint32_t& hi, uint32_t& lo) {
    __half ha = __float2half(a), hb = __float2half(b);
    __half2 H; H.x = ha; H.y = hb;
    __half2 L;
    L.x = __float2half(a - __half2float(ha));
    L.y = __float2half(b - __half2float(hb));
    hi = *(uint32_t*)&H; lo = *(uint32_t*)&L;
}

// ======================= conversion kernels =================================
// x -> fp16 hi/lo split
__global__ void split_h_kernel(const float4* __restrict__ in,
                               __half2* __restrict__ hi,
                               __half2* __restrict__ lo, int n4)
{
    int i = blockIdx.x * blockDim.x + threadIdx.x;
    if (i >= n4) return;
    float4 v = in[i];
    __half h0 = __float2half(v.x), h1 = __float2half(v.y);
    __half h2 = __float2half(v.z), h3 = __float2half(v.w);
    __half2 ph0; ph0.x = h0; ph0.y = h1;
    __half2 ph1; ph1.x = h2; ph1.y = h3;
    hi[2*i]   = ph0;
    hi[2*i+1] = ph1;
    __half2 pl0, pl1;
    pl0.x = __float2half(v.x - __half2float(h0));
    pl0.y = __float2half(v.y - __half2float(h1));
    pl1.x = __float2half(v.z - __half2float(h2));
    pl1.y = __float2half(v.w - __half2float(h3));
    lo[2*i]   = pl0;
    lo[2*i+1] = pl1;
}

// W: [K, N] row-major -> T: [N, K] row-major fp16 (single rounding)
__global__ void transpose_conv_kernel(const float* __restrict__ W,
                                      __half* __restrict__ T, int K, int N)
{
    __shared__ float t[32][33];
    int n0 = blockIdx.x * 32, k0 = blockIdx.y * 32;
    int tx = threadIdx.x, ty = threadIdx.y;   // (32, 8)
    #pragma unroll
    for (int j = 0; j < 32; j += 8)
        t[ty + j][tx] = W[(size_t)(k0 + ty + j) * N + n0 + tx];
    __syncthreads();
    #pragma unroll
    for (int j = 0; j < 32; j += 8)
        T[(size_t)(n0 + ty + j) * K + k0 + tx] = __float2half(t[tx][ty + j]);
}

// RoPE + bf16 hi/lo split + relayout [b,t,h,d] -> [b,h,t,d]; rs = input row stride
__global__ void rope_split_kernel(const float* __restrict__ in,
                                  __nv_bfloat16* __restrict__ oh,
                                  __nv_bfloat16* __restrict__ ol,
                                  int n_heads, int rs, int total)
{
    int idx = blockIdx.x * blockDim.x + threadIdx.x;
    if (idx >= total) return;
    int j = idx & 63;
    int h = (idx >> 6) % n_heads;
    int r = idx / (64 * n_heads);
    int b = r >> 11;
    int t = r & (TT - 1);

    float e = (float)(2 * j) * (1.0f / 128.0f);
    float inv = 1.0f / powf(10000.0f, e);
    float f = (float)t * inv;
    float c = cosf(f), s = sinf(f);

    const float* p = in + (size_t)r * rs + h * DD;
    float x1 = p[j], x2 = p[j + 64];
    float y1 = x1 * c - x2 * s;
    float y2 = x2 * c + x1 * s;

    size_t ob = ((size_t)(b * n_heads + h) * TT + t) * DD + j;
    __nv_bfloat16 h1 = __float2bfloat16(y1);
    __nv_bfloat16 h2 = __float2bfloat16(y2);
    oh[ob]      = h1;
    oh[ob + 64] = h2;
    ol[ob]      = __float2bfloat16(y1 - __bfloat162float(h1));
    ol[ob + 64] = __float2bfloat16(y2 - __bfloat162float(h2));
}

// V: bf16 hi/lo split + relayout [b,t,hk,d] -> [b,hk,t,d]; rs = input row stride
__global__ void v_split_kernel(const float* __restrict__ in,
                               __nv_bfloat16* __restrict__ oh,
                               __nv_bfloat16* __restrict__ ol, int rs, int total4)
{
    int idx = blockIdx.x * blockDim.x + threadIdx.x;
    if (idx >= total4) return;
    int c4 = idx & 31;
    int h  = (idx >> 5) & 7;
    int r  = idx >> 8;
    int b  = r >> 11;
    int t  = r & (TT - 1);
    float4 v = *(const float4*)(in + (size_t)r * rs + h * DD + c4 * 4);
    size_t ob = ((size_t)(b * HKV + h) * TT + t) * DD + c4 * 4;
    __nv_bfloat16 h0 = __float2bfloat16(v.x), h1 = __float2bfloat16(v.y);
    __nv_bfloat16 h2 = __float2bfloat16(v.z), h3 = __float2bfloat16(v.w);
    __nv_bfloat162 p0; p0.x = h0; p0.y = h1;
    __nv_bfloat162 p1; p1.x = h2; p1.y = h3;
    *(__nv_bfloat162*)(oh + ob)     = p0;
    *(__nv_bfloat162*)(oh + ob + 2) = p1;
    *(__nv_bfloat162*)(ol + ob)     = bfpair(v.x - __bfloat162float(h0),
                                             v.y - __bfloat162float(h1));
    *(__nv_bfloat162*)(ol + ob + 2) = bfpair(v.z - __bfloat162float(h2),
                                             v.w - __bfloat162float(h3));
}

// ============ HMMA fp16 2-pass GEMM (128x256 CTA, 3-stage pipeline) =========
// C[M,N] = (Ahi + Alo)[M,K] @ B^T[N,K]; A fp16 exact 2-slice, B fp16 single.
#define GBM 128
#define GBN 256
#define GBK 32
#define GEMM_THREADS 256
#define ROW_BYTES 80
#define ARR_A (128 * ROW_BYTES)            // 10240
#define ARR_B (256 * ROW_BYTES)            // 20480
#define STAGE_BYTES (2*ARR_A + ARR_B)      // 40960  (Ahi, Alo, B)
#define OFF_AH 0
#define OFF_AL ARR_A
#define OFF_B  (2*ARR_A)
#define GEMM_SMEM (3 * STAGE_BYTES)        // 122880

__global__ void __launch_bounds__(GEMM_THREADS, 1)
gemm_f16_kernel(const __half* __restrict__ Ahi, const __half* __restrict__ Alo,
                const __half* __restrict__ B,
                float* __restrict__ C, int M, int N, int K)
{
    extern __shared__ char smg[];
    const uint32_t sbase = smem_u32(smg);
    const int tid  = threadIdx.x;
    const int lane = tid & 31;
    const int wid  = tid >> 5;
    const int warp_m = wid >> 2;     // 0..1 (64 rows)
    const int warp_n = wid & 3;      // 0..3 (64 cols)
    const int m0 = blockIdx.y * GBM;
    const int n0 = blockIdx.x * GBN;

    // stage loader: 2048 16B-chunks, 8 per thread
    auto load_stage = [&](int kt) {
        const uint32_t sdst = sbase + (kt % 3) * STAGE_BYTES;
        const int kofs = kt * GBK;
        #pragma unroll
        for (int i = 0; i < 8; i++) {
            int task = tid + GEMM_THREADS * i;   // 0..2047
            if (task < 1024) {
                int arr = task >> 9;             // 0 Ahi, 1 Alo
                int rem = task & 511;
                int row = rem >> 2, c = rem & 3;
                const __half* gp = (arr ? Alo : Ahi) + (size_t)(m0+row)*K + kofs + c*8;
                cp_async16(sdst + (arr ? OFF_AL : OFF_AH) + row*ROW_BYTES + c*16, gp);
            } else {
                int t2  = task - 1024;           // 0..1023
                int row = t2 >> 2, c = t2 & 3;
                const __half* gp = B + (size_t)(n0+row)*K + kofs + c*8;
                cp_async16(sdst + OFF_B + row*ROW_BYTES + c*16, gp);
            }
        }
        CP_COMMIT();
    };

    float acc[4][8][4];
    #pragma unroll
    for (int i = 0; i < 4; i++)
        #pragma unroll
        for (int j = 0; j < 8; j++)
            #pragma unroll
            for (int r = 0; r < 4; r++) acc[i][j][r] = 0.f;

    const int ktiles = K / GBK;

    load_stage(0);
    load_stage(1);

    const uint32_t a_row_b = (uint32_t)(warp_m * 64 + (lane & 15)) * ROW_BYTES
                           + ((lane >> 4) * 16);
    const uint32_t b_row_b = (uint32_t)(warp_n * 64 + ((lane >> 4) & 1) * 8 + (lane & 7)) * ROW_BYTES
                           + (((lane >> 3) & 1) * 16);

    for (int kt = 0; kt < ktiles; kt++) {
        if (kt + 2 < ktiles) { load_stage(kt + 2); CP_WAIT2(); }
        else if (kt + 1 < ktiles) { CP_WAIT1(); }
        else { CP_WAIT0(); }
        __syncthreads();

        const uint32_t st = sbase + (kt % 3) * STAGE_BYTES;
        #pragma unroll
        for (int s = 0; s < 2; s++) {          // two k16 steps
            const uint32_t koff = s * 32;
            uint32_t ah[4][4], al[4][4];
            #pragma unroll
            for (int mt = 0; mt < 4; mt++) {
                uint32_t ad = st + OFF_AH + a_row_b + mt * (16 * ROW_BYTES) + koff;
                ldsm4(ah[mt], ad);
                ldsm4(al[mt], ad + ARR_A);
            }
            uint32_t bh[4][4];
            #pragma unroll
            for (int np = 0; np < 4; np++) {
                uint32_t bd = st + OFF_B + b_row_b + np * (16 * ROW_BYTES) + koff;
                ldsm4(bh[np], bd);
            }
            #pragma unroll
            for (int mt = 0; mt < 4; mt++)
                #pragma unroll
                for (int nt = 0; nt < 8; nt++) {
                    const uint32_t* bp = &bh[nt >> 1][(nt & 1) * 2];
                    mma_f16(acc[mt][nt], ah[mt], bp);
                    mma_f16(acc[mt][nt], al[mt], bp);
                }
        }
        __syncthreads();
    }

    #pragma unroll
    for (int mt = 0; mt < 4; mt++) {
        int r0 = m0 + warp_m * 64 + mt * 16 + (lane >> 2);
        #pragma unroll
        for (int nt = 0; nt < 8; nt++) {
            int cbase = n0 + warp_n * 64 + nt * 8 + (lane & 3) * 2;
            float2 v0 = make_float2(acc[mt][nt][0], acc[mt][nt][1]);
            float2 v1 = make_float2(acc[mt][nt][2], acc[mt][nt][3]);
            *(float2*)(C + (size_t)r0 * N + cbase)       = v0;
            *(float2*)(C + (size_t)(r0 + 8) * N + cbase) = v1;
        }
    }
}

// ================= Flash attention on HMMA (8 warps x 16 rows) ==============
#define ABQ 128
#define ABK 64
#define AROW 136
#define AQH 0
#define AQL (ABQ*AROW)
#define AKH (2*ABQ*AROW)
#define AKL (AKH + ABK*AROW)
#define AVH (AKL + ABK*AROW)
#define AVL (AVH + ABK*AROW)
#define ASM_ELEMS (AVL + ABK*AROW)
#define ASM_BYTES (ASM_ELEMS*2)        // 139264
#define ATTN_SCALE 0.08838834764831843f

__global__ void __launch_bounds__(256, 1)
attn_mma_kernel(const __nv_bfloat16* __restrict__ Qh, const __nv_bfloat16* __restrict__ Ql,
                const __nv_bfloat16* __restrict__ Kh, const __nv_bfloat16* __restrict__ Kl,
                const __nv_bfloat16* __restrict__ Vh, const __nv_bfloat16* __restrict__ Vl,
                __half* __restrict__ Ohi, __half* __restrict__ Olo)
{
    extern __shared__ __align__(1024) char smA[];
    const uint32_t sb = smem_u32(smA);

    const int tid  = threadIdx.x;
    const int lane = tid & 31;
    const int w    = tid >> 5;
    const int qi   = gridDim.x - 1 - blockIdx.x;   // big tiles first
    const int h    = blockIdx.y;
    const int b    = blockIdx.z;
    const int hk   = h >> 1;
    const int qbase = qi * ABQ;

    const size_t qb0 = ((size_t)(b * HH + h) * TT + qbase) * DD;
    const size_t kb0 = ((size_t)(b * HKV + hk) * TT) * DD;
    const __nv_bfloat16* kvsrc[4] = { Kh, Kl, Vh, Vl };

    #pragma unroll
    for (int i = 0; i < 16; i++) {
        int task = tid + 256 * i;
        int arr = task >> 11;
        int rem = task & 2047;
        int row = rem >> 4;
        int c   = rem & 15;
        const __nv_bfloat16* src = (arr ? Ql : Qh) + qb0 + (size_t)row * DD + c * 8;
        cp_async16(sb + 2 * (uint32_t)((arr ? AQL : AQH) + row * AROW) + c * 16, src);
    }
    CP_COMMIT();

    float m0 = -INFINITY, m1 = -INFINITY, l0 = 0.f, l1 = 0.f;
    float oacc[16][4];
    #pragma unroll
    for (int j = 0; j < 16; j++)
        #pragma unroll
        for (int r = 0; r < 4; r++) oacc[j][r] = 0.f;

    const uint32_t qA_h = sb + 2*(uint32_t)(AQH + (w*16 + (lane & 15))*AROW) + (lane >> 4)*16;
    const uint32_t qA_l = qA_h + 2*(uint32_t)(AQL - AQH);
    const int krow  = ((lane >> 4) & 1)*8 + (lane & 7);
    const int kcolh = ((lane >> 3) & 1)*16;
    const int vrow  = ((lane >> 3) & 1)*8 + (lane & 7);
    const int vcolh = (lane >> 4)*16;

    const int ntiles = 2*qi + 2;
    const int qr0 = qbase + w*16 + (lane >> 2);

    for (int t = 0; t < ntiles; t++) {
        const int k0 = t * ABK;
        __syncthreads();

        #pragma unroll
        for (int i = 0; i < 8; i++) {
            int task = tid + 256 * i;
            int arr = task >> 10;
            int rem = task & 1023;
            int row = rem >> 4;
            int c   = rem & 15;
            cp_async16(sb + 2*(uint32_t)(AKH + arr*(ABK*AROW) + row*AROW) + c*16,
                       kvsrc[arr] + kb0 + (size_t)(k0 + row)*DD + c*8);
        }
        CP_COMMIT();
        #pragma unroll
        for (int i = 8; i < 16; i++) {
            int task = tid + 256 * i;
            int arr = task >> 10;
            int rem = task & 1023;
            int row = rem >> 4;
            int c   = rem & 15;
            cp_async16(sb + 2*(uint32_t)(AKH + arr*(ABK*AROW) + row*AROW) + c*16,
                       kvsrc[arr] + kb0 + (size_t)(k0 + row)*DD + c*8);
        }
        CP_COMMIT();

        CP_WAIT1();
        __syncthreads();

        float sacc[8][4];
        #pragma unroll
        for (int j = 0; j < 8; j++)
            #pragma unroll
            for (int r = 0; r < 4; r++) sacc[j][r] = 0.f;

        #pragma unroll
        for (int s = 0; s < 8; s++) {
            uint32_t ah[4], al[4];
            ldsm4(ah, qA_h + s*32);
            ldsm4(al, qA_l + s*32);
            #pragma unroll
            for (int jj = 0; jj < 4; jj++) {
                uint32_t kh[4], kl[4];
                uint32_t ka = sb + 2*(uint32_t)(AKH + (16*jj + krow)*AROW) + s*32 + kcolh;
                ldsm4(kh, ka);
                ldsm4(kl, ka + 2*(uint32_t)(AKL - AKH));
                mma_bf16(sacc[2*jj],   ah, &kh[0]);
                mma_bf16(sacc[2*jj],   ah, &kl[0]);
                mma_bf16(sacc[2*jj],   al, &kh[0]);
                mma_bf16(sacc[2*jj+1], ah, &kh[2]);
                mma_bf16(sacc[2*jj+1], ah, &kl[2]);
                mma_bf16(sacc[2*jj+1], al, &kh[2]);
            }
        }

        CP_WAIT0();
        __syncthreads();

        const bool domask = (t >= ntiles - 2);
        float mx0 = -INFINITY, mx1 = -INFINITY;
        #pragma unroll
        for (int j = 0; j < 8; j++) {
            #pragma unroll
            for (int r = 0; r < 4; r++) {
                float sv = sacc[j][r] * ATTN_SCALE;
                if (domask) {
                    int col = k0 + 8*j + (lane & 3)*2 + (r & 1);
                    int qr  = qr0 + ((r >= 2) ? 8 : 0);
                    if (col > qr) sv = -INFINITY;
                }
                sacc[j][r] = sv;
                if (r < 2) mx0 = fmaxf(mx0, sv); else mx1 = fmaxf(mx1, sv);
            }
        }
        mx0 = fmaxf(mx0, __shfl_xor_sync(0xffffffffu, mx0, 1));
        mx0 = fmaxf(mx0, __shfl_xor_sync(0xffffffffu, mx0, 2));
        mx1 = fmaxf(mx1, __shfl_xor_sync(0xffffffffu, mx1, 1));
        mx1 = fmaxf(mx1, __shfl_xor_sync(0xffffffffu, mx1, 2));

        float m0n = fmaxf(m0, mx0), m1n = fmaxf(m1, mx1);
        float a0 = __expf(m0 - m0n), a1 = __expf(m1 - m1n);
        float ls0 = 0.f, ls1 = 0.f;
        #pragma unroll
        for (int j = 0; j < 8; j++) {
            float p0 = __expf(sacc[j][0] - m0n);
            float p1 = __expf(sacc[j][1] - m0n);
            float p2 = __expf(sacc[j][2] - m1n);
            float p3 = __expf(sacc[j][3] - m1n);
            sacc[j][0] = p0; sacc[j][1] = p1; sacc[j][2] = p2; sacc[j][3] = p3;
            ls0 += p0 + p1; ls1 += p2 + p3;
        }
        ls0 += __shfl_xor_sync(0xffffffffu, ls0, 1);
        ls0 += __shfl_xor_sync(0xffffffffu, ls0, 2);
        ls1 += __shfl_xor_sync(0xffffffffu, ls1, 1);
        ls1 += __shfl_xor_sync(0xffffffffu, ls1, 2);

        l0 = l0 * a0 + ls0;
        l1 = l1 * a1 + ls1;
        m0 = m0n; m1 = m1n;
        #pragma unroll
        for (int j = 0; j < 16; j++) {
            oacc[j][0] *= a0; oacc[j][1] *= a0;
            oacc[j][2] *= a1; oacc[j][3] *= a1;
        }

        #pragma unroll
        for (int s2 = 0; s2 < 4; s2++) {
            uint32_t ahp[4], alp[4];
            packsplit(sacc[2*s2][0],   sacc[2*s2][1],   ahp[0], alp[0]);
            packsplit(sacc[2*s2][2],   sacc[2*s2][3],   ahp[1], alp[1]);
            packsplit(sacc[2*s2+1][0], sacc[2*s2+1][1], ahp[2], alp[2]);
            packsplit(sacc[2*s2+1][2], sacc[2*s2+1][3], ahp[3], alp[3]);
            uint32_t va = sb + 2*(uint32_t)(AVH + (16*s2 + vrow)*AROW) + vcolh;
            #pragma unroll
            for (int dd = 0; dd < 8; dd++) {
                uint32_t vh[4], vl[4];
                ldsm4t(vh, va + dd*32);
                ldsm4t(vl, va + dd*32 + 2*(uint32_t)(AVL - AVH));
                mma_bf16(oacc[2*dd],   ahp, &vh[0]);
                mma_bf16(oacc[2*dd],   ahp, &vl[0]);
                mma_bf16(oacc[2*dd],   alp, &vh[0]);
                mma_bf16(oacc[2*dd+1], ahp, &vh[2]);
                mma_bf16(oacc[2*dd+1], ahp, &vl[2]);
                mma_bf16(oacc[2*dd+1], alp, &vh[2]);
            }
        }
    }

    // epilogue: normalize + write fp16 hi/lo ([b,t,h*d] layout for Wp GEMM)
    float i0 = 1.f / l0, i1 = 1.f / l1;
    const int row0 = qbase + w*16 + (lane >> 2);
    const int col0 = (lane & 3)*2;
    #pragma unroll
    for (int j = 0; j < 16; j++) {
        int col = j*8 + col0;
        size_t base0 = ((size_t)(b*TT + row0)*HH + h)*DD + col;
        size_t base1 = base0 + (size_t)8*HH*DD;
        uint32_t hp, lp;
        packsplit_h(oacc[j][0]*i0, oacc[j][1]*i0, hp, lp);
        *(uint32_t*)(Ohi + base0) = hp;
        *(uint32_t*)(Olo + base0) = lp;
        packsplit_h(oacc[j][2]*i1, oacc[j][3]*i1, hp, lp);
        *(uint32_t*)(Ohi + base1) = hp;
        *(uint32_t*)(Olo + base1) = lp;
    }
}

// ---------------- host entry -------------------------------------------------
extern "C" void kernel_launch(void* const* d_in, const int* in_sizes, int n_in,
                              void* d_out, int out_size)
{
    const float* x  = (const float*)d_in[0];
    const float* Wq = (const float*)d_in[1];
    const float* Wk = (const float*)d_in[2];
    const float* Wv = (const float*)d_in[3];
    const float* Wp = (const float*)d_in[4];
    float* out = (float*)d_out;

    float *qkv;
    __half *xh, *xl, *oh, *ol, *wqkv, *wp;
    __nv_bfloat16 *qh, *ql, *kh, *kl, *vh, *vl;
    cudaGetSymbolAddress((void**)&qkv, g_qkv);
    cudaGetSymbolAddress((void**)&xh, g_xh);   cudaGetSymbolAddress((void**)&xl, g_xl);
    cudaGetSymbolAddress((void**)&oh, g_oh);   cudaGetSymbolAddress((void**)&ol, g_ol);
    cudaGetSymbolAddress((void**)&wqkv, g_wqkv);
    cudaGetSymbolAddress((void**)&wp, g_wp);
    cudaGetSymbolAddress((void**)&qh, g_qh);   cudaGetSymbolAddress((void**)&ql, g_ql);
    cudaGetSymbolAddress((void**)&kh, g_kh);   cudaGetSymbolAddress((void**)&kl, g_kl);
    cudaGetSymbolAddress((void**)&vh, g_vh);   cudaGetSymbolAddress((void**)&vl, g_vl);

    cudaFuncSetAttribute(gemm_f16_kernel, cudaFuncAttributeMaxDynamicSharedMemorySize, GEMM_SMEM);
    cudaFuncSetAttribute(attn_mma_kernel, cudaFuncAttributeMaxDynamicSharedMemorySize, ASM_BYTES);

    // (0) split x into fp16 hi/lo
    {
        int n4 = (NROW * CC) / 4;
        split_h_kernel<<<(n4 + 255) / 256, 256>>>((const float4*)x,
            (__half2*)xh, (__half2*)xl, n4);
    }
    // (1-3) transpose + convert weights into combined Wqkv^T (fp16 single)
    transpose_conv_kernel<<<dim3(CC/32, CC/32), dim3(32, 8)>>>(Wq, wqkv, CC, CC);
    transpose_conv_kernel<<<dim3((HKV*DD)/32, CC/32), dim3(32, 8)>>>(
        Wk, wqkv + (size_t)2048 * CC, CC, HKV*DD);
    transpose_conv_kernel<<<dim3((HKV*DD)/32, CC/32), dim3(32, 8)>>>(
        Wv, wqkv + (size_t)3072 * CC, CC, HKV*DD);

    // (4) fused QKV projection: [4096,2048] @ [4096,2048]^T -> [4096,4096]
    gemm_f16_kernel<<<dim3(4096/GBN, NROW/GBM), GEMM_THREADS, GEMM_SMEM>>>(
        xh, xl, wqkv, qkv, NROW, 4096, CC);

    // (5-7) RoPE + split + head-major relayout (bf16 for attention)
    {
        int totq = NROW * HH * 64;
        rope_split_kernel<<<(totq + 255) / 256, 256>>>(qkv, qh, ql, HH, 4096, totq);
        int totk = NROW * HKV * 64;
        rope_split_kernel<<<(totk + 255) / 256, 256>>>(qkv + 2048, kh, kl, HKV, 4096, totk);
        int totv = NROW * HKV * 32;
        v_split_kernel<<<(totv + 255) / 256, 256>>>(qkv + 3072, vh, vl, 4096, totv);
    }

    // (8) attention (bf16 3-pass HMMA), fp16 hi/lo O out
    attn_mma_kernel<<<dim3(TT / ABQ, HH, BB), 256, ASM_BYTES>>>(qh, ql, kh, kl, vh, vl, oh, ol);

    // (9) transpose + convert Wp (deferred)
    transpose_conv_kernel<<<dim3(CC/32, CC/32), dim3(32, 8)>>>(Wp, wp, CC, CC);

    // (10) output projection
    gemm_f16_kernel<<<dim3(CC/GBN, NROW/GBM), GEMM_THREADS, GEMM_SMEM>>>(
        oh, ol, wp, out, NROW, CC, CC);
}

// round 11
// speedup vs baseline: 2.8577x; 1.1082x over previous
#include <cuda_runtime.h>
#include <cuda_bf16.h>
#include <cuda_fp16.h>
#include <math.h>
#include <cstdint>

// Problem constants
#define BB 2
#define TT 2048
#define CC 2048
#define HH 16
#define HKV 8
#define DD 128
#define NROW (BB*TT)          // 4096

// ---------------- scratch (device globals; no allocation allowed) ----------
__device__ float g_qkv[(size_t)NROW * 4096];   // cols: 0-2047 q, 2048-3071 k, 3072-4095 v

__device__ __align__(16) __half g_xh[(size_t)NROW * CC];
__device__ __align__(16) __half g_xl[(size_t)NROW * CC];
__device__ __align__(16) __half g_oh[(size_t)NROW * CC];
__device__ __align__(16) __half g_ol[(size_t)NROW * CC];
__device__ __align__(16) __half g_wqkv[(size_t)4096 * CC];   // [Wq|Wk|Wv]^T
__device__ __align__(16) __half g_wp[(size_t)CC * CC];       // Wp^T

// head-major fp16 Q (hi/lo) and K/V (single) for attention
__device__ __align__(16) __half g_qh[(size_t)BB * HH * TT * DD];
__device__ __align__(16) __half g_ql[(size_t)BB * HH * TT * DD];
__device__ __align__(16) __half g_kf[(size_t)BB * HKV * TT * DD];
__device__ __align__(16) __half g_vf[(size_t)BB * HKV * TT * DD];

// ======================= low-level helpers ==================================
__device__ __forceinline__ uint32_t smem_u32(const void* p) {
    uint32_t a;
    asm("{ .reg .u64 t; cvta.to.shared.u64 t, %1; cvt.u32.u64 %0, t; }"
        : "=r"(a) : "l"(p));
    return a;
}
__device__ __forceinline__ void ldsm4(uint32_t* r, uint32_t addr) {
    asm volatile("ldmatrix.sync.aligned.m8n8.x4.shared.b16 {%0,%1,%2,%3}, [%4];"
        : "=r"(r[0]), "=r"(r[1]), "=r"(r[2]), "=r"(r[3]) : "r"(addr));
}
__device__ __forceinline__ void ldsm4t(uint32_t* r, uint32_t addr) {
    asm volatile("ldmatrix.sync.aligned.m8n8.x4.trans.shared.b16 {%0,%1,%2,%3}, [%4];"
        : "=r"(r[0]), "=r"(r[1]), "=r"(r[2]), "=r"(r[3]) : "r"(addr));
}
__device__ __forceinline__ void mma_f16(float* d, const uint32_t* a, const uint32_t* b) {
    asm volatile(
        "mma.sync.aligned.m16n8k16.row.col.f32.f16.f16.f32 "
        "{%0,%1,%2,%3}, {%4,%5,%6,%7}, {%8,%9}, {%0,%1,%2,%3};"
        : "+f"(d[0]), "+f"(d[1]), "+f"(d[2]), "+f"(d[3])
        : "r"(a[0]), "r"(a[1]), "r"(a[2]), "r"(a[3]), "r"(b[0]), "r"(b[1]));
}
__device__ __forceinline__ void cp_async16(uint32_t dst, const void* src) {
    asm volatile("cp.async.cg.shared.global [%0], [%1], 16;\n" :: "r"(dst), "l"(src));
}
#define CP_COMMIT() asm volatile("cp.async.commit_group;\n" ::: "memory")
#define CP_WAIT3()  asm volatile("cp.async.wait_group 3;\n" ::: "memory")
#define CP_WAIT2()  asm volatile("cp.async.wait_group 2;\n" ::: "memory")
#define CP_WAIT1()  asm volatile("cp.async.wait_group 1;\n" ::: "memory")
#define CP_WAIT0()  asm volatile("cp.async.wait_group 0;\n" ::: "memory")

// fp16 hi/lo pack
__device__ __forceinline__ void packsplit_h(float a, float b, uint32_t& hi, uint32_t& lo) {
    __half ha = __float2half(a), hb = __float2half(b);
    __half2 H; H.x = ha; H.y = hb;
    __half2 L;
    L.x = __float2half(a - __half2float(ha));
    L.y = __float2half(b - __half2float(hb));
    hi = *(uint32_t*)&H; lo = *(uint32_t*)&L;
}

// ======================= conversion kernels =================================
// x -> fp16 hi/lo split
__global__ void split_h_kernel(const float4* __restrict__ in,
                               __half2* __restrict__ hi,
                               __half2* __restrict__ lo, int n4)
{
    int i = blockIdx.x * blockDim.x + threadIdx.x;
    if (i >= n4) return;
    float4 v = in[i];
    __half h0 = __float2half(v.x), h1 = __float2half(v.y);
    __half h2 = __float2half(v.z), h3 = __float2half(v.w);
    __half2 ph0; ph0.x = h0; ph0.y = h1;
    __half2 ph1; ph1.x = h2; ph1.y = h3;
    hi[2*i]   = ph0;
    hi[2*i+1] = ph1;
    __half2 pl0, pl1;
    pl0.x = __float2half(v.x - __half2float(h0));
    pl0.y = __float2half(v.y - __half2float(h1));
    pl1.x = __float2half(v.z - __half2float(h2));
    pl1.y = __float2half(v.w - __half2float(h3));
    lo[2*i]   = pl0;
    lo[2*i+1] = pl1;
}

// W: [K, N] row-major -> T: [N, K] row-major fp16 (single rounding)
__global__ void transpose_conv_kernel(const float* __restrict__ W,
                                      __half* __restrict__ T, int K, int N)
{
    __shared__ float t[32][33];
    int n0 = blockIdx.x * 32, k0 = blockIdx.y * 32;
    int tx = threadIdx.x, ty = threadIdx.y;   // (32, 8)
    #pragma unroll
    for (int j = 0; j < 32; j += 8)
        t[ty + j][tx] = W[(size_t)(k0 + ty + j) * N + n0 + tx];
    __syncthreads();
    #pragma unroll
    for (int j = 0; j < 32; j += 8)
        T[(size_t)(n0 + ty + j) * K + k0 + tx] = __float2half(t[tx][ty + j]);
}

// RoPE + fp16 hi/lo split + relayout [b,t,h,d] -> [b,h,t,d] (Q)
__global__ void rope_split_q_kernel(const float* __restrict__ in,
                                    __half* __restrict__ oh, __half* __restrict__ ol,
                                    int n_heads, int rs, int total)
{
    int idx = blockIdx.x * blockDim.x + threadIdx.x;
    if (idx >= total) return;
    int j = idx & 63;
    int h = (idx >> 6) % n_heads;
    int r = idx / (64 * n_heads);
    int b = r >> 11;
    int t = r & (TT - 1);

    float e = (float)(2 * j) * (1.0f / 128.0f);
    float inv = 1.0f / powf(10000.0f, e);
    float f = (float)t * inv;
    float c = cosf(f), s = sinf(f);

    const float* p = in + (size_t)r * rs + h * DD;
    float x1 = p[j], x2 = p[j + 64];
    float y1 = x1 * c - x2 * s;
    float y2 = x2 * c + x1 * s;

    size_t ob = ((size_t)(b * n_heads + h) * TT + t) * DD + j;
    __half h1 = __float2half(y1);
    __half h2 = __float2half(y2);
    oh[ob]      = h1;
    oh[ob + 64] = h2;
    ol[ob]      = __float2half(y1 - __half2float(h1));
    ol[ob + 64] = __float2half(y2 - __half2float(h2));
}

// RoPE + single fp16 + relayout (K)
__global__ void rope_conv_k_kernel(const float* __restrict__ in,
                                   __half* __restrict__ o,
                                   int n_heads, int rs, int total)
{
    int idx = blockIdx.x * blockDim.x + threadIdx.x;
    if (idx >= total) return;
    int j = idx & 63;
    int h = (idx >> 6) % n_heads;
    int r = idx / (64 * n_heads);
    int b = r >> 11;
    int t = r & (TT - 1);

    float e = (float)(2 * j) * (1.0f / 128.0f);
    float inv = 1.0f / powf(10000.0f, e);
    float f = (float)t * inv;
    float c = cosf(f), s = sinf(f);

    const float* p = in + (size_t)r * rs + h * DD;
    float x1 = p[j], x2 = p[j + 64];

    size_t ob = ((size_t)(b * n_heads + h) * TT + t) * DD + j;
    o[ob]      = __float2half(x1 * c - x2 * s);
    o[ob + 64] = __float2half(x2 * c + x1 * s);
}

// V: single fp16 + relayout [b,t,hk,d] -> [b,hk,t,d]
__global__ void v_conv_kernel(const float* __restrict__ in,
                              __half* __restrict__ o, int rs, int total4)
{
    int idx = blockIdx.x * blockDim.x + threadIdx.x;
    if (idx >= total4) return;
    int c4 = idx & 31;
    int h  = (idx >> 5) & 7;
    int r  = idx >> 8;
    int b  = r >> 11;
    int t  = r & (TT - 1);
    float4 v = *(const float4*)(in + (size_t)r * rs + h * DD + c4 * 4);
    size_t ob = ((size_t)(b * HKV + h) * TT + t) * DD + c4 * 4;
    __half2 p0; p0.x = __float2half(v.x); p0.y = __float2half(v.y);
    __half2 p1; p1.x = __float2half(v.z); p1.y = __float2half(v.w);
    *(__half2*)(o + ob)     = p0;
    *(__half2*)(o + ob + 2) = p1;
}

// ============ HMMA fp16 2-pass GEMM (128x256 CTA, 3-stage pipeline) =========
#define GBM 128
#define GBN 256
#define GBK 32
#define GEMM_THREADS 256
#define ROW_BYTES 80
#define ARR_A (128 * ROW_BYTES)
#define ARR_B (256 * ROW_BYTES)
#define STAGE_BYTES (2*ARR_A + ARR_B)      // 40960
#define OFF_AH 0
#define OFF_AL ARR_A
#define OFF_B  (2*ARR_A)
#define GEMM_SMEM (3 * STAGE_BYTES)        // 122880

__global__ void __launch_bounds__(GEMM_THREADS, 1)
gemm_f16_kernel(const __half* __restrict__ Ahi, const __half* __restrict__ Alo,
                const __half* __restrict__ B,
                float* __restrict__ C, int M, int N, int K)
{
    extern __shared__ char smg[];
    const uint32_t sbase = smem_u32(smg);
    const int tid  = threadIdx.x;
    const int lane = tid & 31;
    const int wid  = tid >> 5;
    const int warp_m = wid >> 2;
    const int warp_n = wid & 3;
    const int m0 = blockIdx.y * GBM;
    const int n0 = blockIdx.x * GBN;

    auto load_stage = [&](int kt) {
        const uint32_t sdst = sbase + (kt % 3) * STAGE_BYTES;
        const int kofs = kt * GBK;
        #pragma unroll
        for (int i = 0; i < 8; i++) {
            int task = tid + GEMM_THREADS * i;
            if (task < 1024) {
                int arr = task >> 9;
                int rem = task & 511;
                int row = rem >> 2, c = rem & 3;
                const __half* gp = (arr ? Alo : Ahi) + (size_t)(m0+row)*K + kofs + c*8;
                cp_async16(sdst + (arr ? OFF_AL : OFF_AH) + row*ROW_BYTES + c*16, gp);
            } else {
                int t2  = task - 1024;
                int row = t2 >> 2, c = t2 & 3;
                const __half* gp = B + (size_t)(n0+row)*K + kofs + c*8;
                cp_async16(sdst + OFF_B + row*ROW_BYTES + c*16, gp);
            }
        }
        CP_COMMIT();
    };

    float acc[4][8][4];
    #pragma unroll
    for (int i = 0; i < 4; i++)
        #pragma unroll
        for (int j = 0; j < 8; j++)
            #pragma unroll
            for (int r = 0; r < 4; r++) acc[i][j][r] = 0.f;

    const int ktiles = K / GBK;

    load_stage(0);
    load_stage(1);

    const uint32_t a_row_b = (uint32_t)(warp_m * 64 + (lane & 15)) * ROW_BYTES
                           + ((lane >> 4) * 16);
    const uint32_t b_row_b = (uint32_t)(warp_n * 64 + ((lane >> 4) & 1) * 8 + (lane & 7)) * ROW_BYTES
                           + (((lane >> 3) & 1) * 16);

    for (int kt = 0; kt < ktiles; kt++) {
        if (kt + 2 < ktiles) { load_stage(kt + 2); CP_WAIT2(); }
        else if (kt + 1 < ktiles) { CP_WAIT1(); }
        else { CP_WAIT0(); }
        __syncthreads();

        const uint32_t st = sbase + (kt % 3) * STAGE_BYTES;
        #pragma unroll
        for (int s = 0; s < 2; s++) {
            const uint32_t koff = s * 32;
            uint32_t ah[4][4], al[4][4];
            #pragma unroll
            for (int mt = 0; mt < 4; mt++) {
                uint32_t ad = st + OFF_AH + a_row_b + mt * (16 * ROW_BYTES) + koff;
                ldsm4(ah[mt], ad);
                ldsm4(al[mt], ad + ARR_A);
            }
            uint32_t bh[4][4];
            #pragma unroll
            for (int np = 0; np < 4; np++) {
                uint32_t bd = st + OFF_B + b_row_b + np * (16 * ROW_BYTES) + koff;
                ldsm4(bh[np], bd);
            }
            #pragma unroll
            for (int mt = 0; mt < 4; mt++)
                #pragma unroll
                for (int nt = 0; nt < 8; nt++) {
                    const uint32_t* bp = &bh[nt >> 1][(nt & 1) * 2];
                    mma_f16(acc[mt][nt], ah[mt], bp);
                    mma_f16(acc[mt][nt], al[mt], bp);
                }
        }
        __syncthreads();
    }

    #pragma unroll
    for (int mt = 0; mt < 4; mt++) {
        int r0 = m0 + warp_m * 64 + mt * 16 + (lane >> 2);
        #pragma unroll
        for (int nt = 0; nt < 8; nt++) {
            int cbase = n0 + warp_n * 64 + nt * 8 + (lane & 3) * 2;
            float2 v0 = make_float2(acc[mt][nt][0], acc[mt][nt][1]);
            float2 v1 = make_float2(acc[mt][nt][2], acc[mt][nt][3]);
            *(float2*)(C + (size_t)r0 * N + cbase)       = v0;
            *(float2*)(C + (size_t)(r0 + 8) * N + cbase) = v1;
        }
    }
}

// ====== Flash attention: fp16 2-pass, Q frags hoisted, double-buffered KV ===
#define ABQ 128
#define ABK 64
#define AROW 136
#define AQH_E 0
#define AQL_E (ABQ*AROW)          // 17408 elems
#define AKV0_E (2*ABQ*AROW)       // 34816 elems
#define KVBUF_E (2*ABK*AROW)      // 17408 elems (K + V)
#define AV_E (ABK*AROW)           // 8704: V offset within buffer
#define ASM_BYTES ((AKV0_E + 2*KVBUF_E)*2)   // 139264
#define ATTN_SCALE 0.08838834764831843f

__global__ void __launch_bounds__(256, 1)
attn_f16_kernel(const __half* __restrict__ Qh, const __half* __restrict__ Ql,
                const __half* __restrict__ Kf, const __half* __restrict__ Vf,
                __half* __restrict__ Ohi, __half* __restrict__ Olo)
{
    extern __shared__ __align__(1024) char smA[];
    const uint32_t sb = smem_u32(smA);

    const int tid  = threadIdx.x;
    const int lane = tid & 31;
    const int w    = tid >> 5;
    const int qi   = gridDim.x - 1 - blockIdx.x;   // big tiles first
    const int h    = blockIdx.y;
    const int b    = blockIdx.z;
    const int hk   = h >> 1;
    const int qbase = qi * ABQ;

    const size_t qb0 = ((size_t)(b * HH + h) * TT + qbase) * DD;
    const size_t kb0 = ((size_t)(b * HKV + hk) * TT) * DD;

    // ---- Q tile: 4096 chunks (128 rows x 16 chunks x {hi,lo}) ----
    #pragma unroll
    for (int i = 0; i < 16; i++) {
        int task = tid + 256 * i;        // 0..4095
        int arr = task >> 11;            // 0 hi, 1 lo
        int rem = task & 2047;
        int row = rem >> 4;              // 0..127
        int c   = rem & 15;
        const __half* src = (arr ? Ql : Qh) + qb0 + (size_t)row * DD + c * 8;
        cp_async16(sb + 2 * (uint32_t)((arr ? AQL_E : AQH_E) + row * AROW) + c * 16, src);
    }
    CP_COMMIT();

    auto load_kv = [&](int t, int buf) {
        const uint32_t base = sb + 2 * (uint32_t)(AKV0_E + buf * KVBUF_E);
        const int k0 = t * ABK;
        #pragma unroll
        for (int i = 0; i < 4; i++) {
            int task = tid + 256 * i;    // 0..1023
            int row = task >> 4, c = task & 15;
            cp_async16(base + 2 * (uint32_t)(row * AROW) + c * 16,
                       Kf + kb0 + (size_t)(k0 + row) * DD + c * 8);
        }
        CP_COMMIT();
        #pragma unroll
        for (int i = 0; i < 4; i++) {
            int task = tid + 256 * i;
            int row = task >> 4, c = task & 15;
            cp_async16(base + 2 * (uint32_t)(AV_E + row * AROW) + c * 16,
                       Vf + kb0 + (size_t)(k0 + row) * DD + c * 8);
        }
        CP_COMMIT();
    };

    load_kv(0, 0);

    CP_WAIT2();          // Q complete (K0,V0 may be in flight)
    __syncthreads();

    // ---- hoist Q fragments (reused every KV tile) ----
    const uint32_t qA_h = sb + 2*(uint32_t)(AQH_E + (w*16 + (lane & 15))*AROW) + (lane >> 4)*16;
    const uint32_t qA_l = qA_h + 2*(uint32_t)(AQL_E - AQH_E);
    uint32_t qfh[8][4], qfl[8][4];
    #pragma unroll
    for (int s = 0; s < 8; s++) {
        ldsm4(qfh[s], qA_h + s*32);
        ldsm4(qfl[s], qA_l + s*32);
    }

    float m0 = -INFINITY, m1 = -INFINITY, l0 = 0.f, l1 = 0.f;
    float oacc[16][4];
    #pragma unroll
    for (int j = 0; j < 16; j++)
        #pragma unroll
        for (int r = 0; r < 4; r++) oacc[j][r] = 0.f;

    const int krow  = ((lane >> 4) & 1)*8 + (lane & 7);
    const int kcolh = ((lane >> 3) & 1)*16;
    const int vrow  = ((lane >> 3) & 1)*8 + (lane & 7);
    const int vcolh = (lane >> 4)*16;

    const int ntiles = 2*qi + 2;
    const int qr0 = qbase + w*16 + (lane >> 2);

    for (int t = 0; t < ntiles; t++) {
        const int k0 = t * ABK;
        const int buf = t & 1;

        if (t + 1 < ntiles) { load_kv(t + 1, buf ^ 1); CP_WAIT3(); }
        else                { CP_WAIT1(); }
        __syncthreads();     // K_t visible to all warps

        const uint32_t kvb = sb + 2 * (uint32_t)(AKV0_E + buf * KVBUF_E);

        // ---- S = Q K^T (2 passes: Qhi·K + Qlo·K) ----
        float sacc[8][4];
        #pragma unroll
        for (int j = 0; j < 8; j++)
            #pragma unroll
            for (int r = 0; r < 4; r++) sacc[j][r] = 0.f;

        #pragma unroll
        for (int s = 0; s < 8; s++) {
            #pragma unroll
            for (int jj = 0; jj < 4; jj++) {
                uint32_t kf[4];
                uint32_t ka = kvb + 2*(uint32_t)((16*jj + krow)*AROW) + s*32 + kcolh;
                ldsm4(kf, ka);
                mma_f16(sacc[2*jj],   qfh[s], &kf[0]);
                mma_f16(sacc[2*jj],   qfl[s], &kf[0]);
                mma_f16(sacc[2*jj+1], qfh[s], &kf[2]);
                mma_f16(sacc[2*jj+1], qfl[s], &kf[2]);
            }
        }

        if (t + 1 < ntiles) CP_WAIT2(); else CP_WAIT0();   // V_t complete
        __syncthreads();

        // ---- online softmax ----
        const bool domask = (t >= ntiles - 2);
        float mx0 = -INFINITY, mx1 = -INFINITY;
        #pragma unroll
        for (int j = 0; j < 8; j++) {
            #pragma unroll
            for (int r = 0; r < 4; r++) {
                float sv = sacc[j][r] * ATTN_SCALE;
                if (domask) {
                    int col = k0 + 8*j + (lane & 3)*2 + (r & 1);
                    int qr  = qr0 + ((r >= 2) ? 8 : 0);
                    if (col > qr) sv = -INFINITY;
                }
                sacc[j][r] = sv;
                if (r < 2) mx0 = fmaxf(mx0, sv); else mx1 = fmaxf(mx1, sv);
            }
        }
        mx0 = fmaxf(mx0, __shfl_xor_sync(0xffffffffu, mx0, 1));
        mx0 = fmaxf(mx0, __shfl_xor_sync(0xffffffffu, mx0, 2));
        mx1 = fmaxf(mx1, __shfl_xor_sync(0xffffffffu, mx1, 1));
        mx1 = fmaxf(mx1, __shfl_xor_sync(0xffffffffu, mx1, 2));

        float m0n = fmaxf(m0, mx0), m1n = fmaxf(m1, mx1);
        float a0 = __expf(m0 - m0n), a1 = __expf(m1 - m1n);
        float ls0 = 0.f, ls1 = 0.f;
        #pragma unroll
        for (int j = 0; j < 8; j++) {
            float p0 = __expf(sacc[j][0] - m0n);
            float p1 = __expf(sacc[j][1] - m0n);
            float p2 = __expf(sacc[j][2] - m1n);
            float p3 = __expf(sacc[j][3] - m1n);
            sacc[j][0] = p0; sacc[j][1] = p1; sacc[j][2] = p2; sacc[j][3] = p3;
            ls0 += p0 + p1; ls1 += p2 + p3;
        }
        ls0 += __shfl_xor_sync(0xffffffffu, ls0, 1);
        ls0 += __shfl_xor_sync(0xffffffffu, ls0, 2);
        ls1 += __shfl_xor_sync(0xffffffffu, ls1, 1);
        ls1 += __shfl_xor_sync(0xffffffffu, ls1, 2);

        l0 = l0 * a0 + ls0;
        l1 = l1 * a1 + ls1;
        m0 = m0n; m1 = m1n;
        #pragma unroll
        for (int j = 0; j < 16; j++) {
            oacc[j][0] *= a0; oacc[j][1] *= a0;
            oacc[j][2] *= a1; oacc[j][3] *= a1;
        }

        // ---- O += P V (2 passes: Phi·V + Plo·V) ----
        #pragma unroll
        for (int s2 = 0; s2 < 4; s2++) {
            uint32_t php[4], plp[4];
            packsplit_h(sacc[2*s2][0],   sacc[2*s2][1],   php[0], plp[0]);
            packsplit_h(sacc[2*s2][2],   sacc[2*s2][3],   php[1], plp[1]);
            packsplit_h(sacc[2*s2+1][0], sacc[2*s2+1][1], php[2], plp[2]);
            packsplit_h(sacc[2*s2+1][2], sacc[2*s2+1][3], php[3], plp[3]);
            uint32_t va = kvb + 2*(uint32_t)(AV_E + (16*s2 + vrow)*AROW) + vcolh;
            #pragma unroll
            for (int dd = 0; dd < 8; dd++) {
                uint32_t vf[4];
                ldsm4t(vf, va + dd*32);
                mma_f16(oacc[2*dd],   php, &vf[0]);
                mma_f16(oacc[2*dd],   plp, &vf[0]);
                mma_f16(oacc[2*dd+1], php, &vf[2]);
                mma_f16(oacc[2*dd+1], plp, &vf[2]);
            }
        }
        __syncthreads();   // all reads of this buffer done before its next overwrite
    }

    // ---- epilogue: normalize + write fp16 hi/lo ([b,t,h*d] for Wp GEMM) ----
    float i0 = 1.f / l0, i1 = 1.f / l1;
    const int row0 = qbase + w*16 + (lane >> 2);
    const int col0 = (lane & 3)*2;
    #pragma unroll
    for (int j = 0; j < 16; j++) {
        int col = j*8 + col0;
        size_t base0 = ((size_t)(b*TT + row0)*HH + h)*DD + col;
        size_t base1 = base0 + (size_t)8*HH*DD;
        uint32_t hp, lp;
        packsplit_h(oacc[j][0]*i0, oacc[j][1]*i0, hp, lp);
        *(uint32_t*)(Ohi + base0) = hp;
        *(uint32_t*)(Olo + base0) = lp;
        packsplit_h(oacc[j][2]*i1, oacc[j][3]*i1, hp, lp);
        *(uint32_t*)(Ohi + base1) = hp;
        *(uint32_t*)(Olo + base1) = lp;
    }
}

// ---------------- host entry -------------------------------------------------
extern "C" void kernel_launch(void* const* d_in, const int* in_sizes, int n_in,
                              void* d_out, int out_size)
{
    const float* x  = (const float*)d_in[0];
    const float* Wq = (const float*)d_in[1];
    const float* Wk = (const float*)d_in[2];
    const float* Wv = (const float*)d_in[3];
    const float* Wp = (const float*)d_in[4];
    float* out = (float*)d_out;

    float *qkv;
    __half *xh, *xl, *oh, *ol, *wqkv, *wp, *qh, *ql, *kf, *vf;
    cudaGetSymbolAddress((void**)&qkv, g_qkv);
    cudaGetSymbolAddress((void**)&xh, g_xh);   cudaGetSymbolAddress((void**)&xl, g_xl);
    cudaGetSymbolAddress((void**)&oh, g_oh);   cudaGetSymbolAddress((void**)&ol, g_ol);
    cudaGetSymbolAddress((void**)&wqkv, g_wqkv);
    cudaGetSymbolAddress((void**)&wp, g_wp);
    cudaGetSymbolAddress((void**)&qh, g_qh);   cudaGetSymbolAddress((void**)&ql, g_ql);
    cudaGetSymbolAddress((void**)&kf, g_kf);   cudaGetSymbolAddress((void**)&vf, g_vf);

    cudaFuncSetAttribute(gemm_f16_kernel, cudaFuncAttributeMaxDynamicSharedMemorySize, GEMM_SMEM);
    cudaFuncSetAttribute(attn_f16_kernel, cudaFuncAttributeMaxDynamicSharedMemorySize, ASM_BYTES);

    // (1) split x into fp16 hi/lo
    {
        int n4 = (NROW * CC) / 4;
        split_h_kernel<<<(n4 + 255) / 256, 256>>>((const float4*)x,
            (__half2*)xh, (__half2*)xl, n4);
    }
    // (2-5) transpose + convert all weights
    transpose_conv_kernel<<<dim3(CC/32, CC/32), dim3(32, 8)>>>(Wq, wqkv, CC, CC);
    transpose_conv_kernel<<<dim3((HKV*DD)/32, CC/32), dim3(32, 8)>>>(
        Wk, wqkv + (size_t)2048 * CC, CC, HKV*DD);
    transpose_conv_kernel<<<dim3((HKV*DD)/32, CC/32), dim3(32, 8)>>>(
        Wv, wqkv + (size_t)3072 * CC, CC, HKV*DD);
    transpose_conv_kernel<<<dim3(CC/32, CC/32), dim3(32, 8)>>>(Wp, wp, CC, CC);

    // (6) fused QKV projection  <- ncu capture slot
    gemm_f16_kernel<<<dim3(4096/GBN, NROW/GBM), GEMM_THREADS, GEMM_SMEM>>>(
        xh, xl, wqkv, qkv, NROW, 4096, CC);

    // (7-9) RoPE + relayout (fp16 for attention)
    {
        int totq = NROW * HH * 64;
        rope_split_q_kernel<<<(totq + 255) / 256, 256>>>(qkv, qh, ql, HH, 4096, totq);
        int totk = NROW * HKV * 64;
        rope_conv_k_kernel<<<(totk + 255) / 256, 256>>>(qkv + 2048, kf, HKV, 4096, totk);
        int totv = NROW * HKV * 32;
        v_conv_kernel<<<(totv + 255) / 256, 256>>>(qkv + 3072, vf, 4096, totv);
    }

    // (10) attention (fp16 2-pass HMMA), fp16 hi/lo O out
    attn_f16_kernel<<<dim3(TT / ABQ, HH, BB), 256, ASM_BYTES>>>(qh, ql, kf, vf, oh, ol);

    // (11) output projection
    gemm_f16_kernel<<<dim3(CC/GBN, NROW/GBM), GEMM_THREADS, GEMM_SMEM>>>(
        oh, ol, wp, out, NROW, CC, CC);
}

// round 12
// speedup vs baseline: 3.8445x; 1.3453x over previous
#include <cuda_runtime.h>
#include <cuda_bf16.h>
#include <cuda_fp16.h>
#include <math.h>
#include <cstdint>

// Problem constants
#define BB 2
#define TT 2048
#define CC 2048
#define HH 16
#define HKV 8
#define DD 128
#define NROW (BB*TT)          // 4096

// ---------------- scratch (device globals; no allocation allowed) ----------
__device__ float g_qkv[(size_t)NROW * 4096];   // cols: 0-2047 q, 2048-3071 k, 3072-4095 v

__device__ __align__(16) __half g_xf[(size_t)NROW * CC];
__device__ __align__(16) __half g_of[(size_t)NROW * CC];
__device__ __align__(16) __half g_wqkv[(size_t)4096 * CC];   // [Wq|Wk|Wv]^T
__device__ __align__(16) __half g_wp[(size_t)CC * CC];       // Wp^T

// head-major fp16 Q (hi/lo) and K/V (single) for attention
__device__ __align__(16) __half g_qh[(size_t)BB * HH * TT * DD];
__device__ __align__(16) __half g_ql[(size_t)BB * HH * TT * DD];
__device__ __align__(16) __half g_kf[(size_t)BB * HKV * TT * DD];
__device__ __align__(16) __half g_vf[(size_t)BB * HKV * TT * DD];

// ======================= low-level helpers ==================================
__device__ __forceinline__ uint32_t smem_u32(const void* p) {
    uint32_t a;
    asm("{ .reg .u64 t; cvta.to.shared.u64 t, %1; cvt.u32.u64 %0, t; }"
        : "=r"(a) : "l"(p));
    return a;
}
__device__ __forceinline__ void ldsm4(uint32_t* r, uint32_t addr) {
    asm volatile("ldmatrix.sync.aligned.m8n8.x4.shared.b16 {%0,%1,%2,%3}, [%4];"
        : "=r"(r[0]), "=r"(r[1]), "=r"(r[2]), "=r"(r[3]) : "r"(addr));
}
__device__ __forceinline__ void ldsm4t(uint32_t* r, uint32_t addr) {
    asm volatile("ldmatrix.sync.aligned.m8n8.x4.trans.shared.b16 {%0,%1,%2,%3}, [%4];"
        : "=r"(r[0]), "=r"(r[1]), "=r"(r[2]), "=r"(r[3]) : "r"(addr));
}
__device__ __forceinline__ void mma_f16(float* d, const uint32_t* a, const uint32_t* b) {
    asm volatile(
        "mma.sync.aligned.m16n8k16.row.col.f32.f16.f16.f32 "
        "{%0,%1,%2,%3}, {%4,%5,%6,%7}, {%8,%9}, {%0,%1,%2,%3};"
        : "+f"(d[0]), "+f"(d[1]), "+f"(d[2]), "+f"(d[3])
        : "r"(a[0]), "r"(a[1]), "r"(a[2]), "r"(a[3]), "r"(b[0]), "r"(b[1]));
}
__device__ __forceinline__ void cp_async16(uint32_t dst, const void* src) {
    asm volatile("cp.async.cg.shared.global [%0], [%1], 16;\n" :: "r"(dst), "l"(src));
}
#define CP_COMMIT() asm volatile("cp.async.commit_group;\n" ::: "memory")
#define CP_WAIT3()  asm volatile("cp.async.wait_group 3;\n" ::: "memory")
#define CP_WAIT2()  asm volatile("cp.async.wait_group 2;\n" ::: "memory")
#define CP_WAIT1()  asm volatile("cp.async.wait_group 1;\n" ::: "memory")
#define CP_WAIT0()  asm volatile("cp.async.wait_group 0;\n" ::: "memory")

// fp16 hi/lo pack
__device__ __forceinline__ void packsplit_h(float a, float b, uint32_t& hi, uint32_t& lo) {
    __half ha = __float2half(a), hb = __float2half(b);
    __half2 H; H.x = ha; H.y = hb;
    __half2 L;
    L.x = __float2half(a - __half2float(ha));
    L.y = __float2half(b - __half2float(hb));
    hi = *(uint32_t*)&H; lo = *(uint32_t*)&L;
}

// ======================= conversion kernels =================================
// fp32 -> fp16 (single rounding)
__global__ void conv_h_kernel(const float4* __restrict__ in,
                              __half2* __restrict__ o, int n4)
{
    int i = blockIdx.x * blockDim.x + threadIdx.x;
    if (i >= n4) return;
    float4 v = in[i];
    __half2 p0; p0.x = __float2half(v.x); p0.y = __float2half(v.y);
    __half2 p1; p1.x = __float2half(v.z); p1.y = __float2half(v.w);
    o[2*i]   = p0;
    o[2*i+1] = p1;
}

// W: [K, N] row-major -> T: [N, K] row-major fp16 (single rounding)
__global__ void transpose_conv_kernel(const float* __restrict__ W,
                                      __half* __restrict__ T, int K, int N)
{
    __shared__ float t[32][33];
    int n0 = blockIdx.x * 32, k0 = blockIdx.y * 32;
    int tx = threadIdx.x, ty = threadIdx.y;   // (32, 8)
    #pragma unroll
    for (int j = 0; j < 32; j += 8)
        t[ty + j][tx] = W[(size_t)(k0 + ty + j) * N + n0 + tx];
    __syncthreads();
    #pragma unroll
    for (int j = 0; j < 32; j += 8)
        T[(size_t)(n0 + ty + j) * K + k0 + tx] = __float2half(t[tx][ty + j]);
}

// RoPE + fp16 hi/lo split + relayout [b,t,h,d] -> [b,h,t,d] (Q)
__global__ void rope_split_q_kernel(const float* __restrict__ in,
                                    __half* __restrict__ oh, __half* __restrict__ ol,
                                    int n_heads, int rs, int total)
{
    int idx = blockIdx.x * blockDim.x + threadIdx.x;
    if (idx >= total) return;
    int j = idx & 63;
    int h = (idx >> 6) % n_heads;
    int r = idx / (64 * n_heads);
    int b = r >> 11;
    int t = r & (TT - 1);

    float e = (float)(2 * j) * (1.0f / 128.0f);
    float inv = 1.0f / powf(10000.0f, e);
    float f = (float)t * inv;
    float c = cosf(f), s = sinf(f);

    const float* p = in + (size_t)r * rs + h * DD;
    float x1 = p[j], x2 = p[j + 64];
    float y1 = x1 * c - x2 * s;
    float y2 = x2 * c + x1 * s;

    size_t ob = ((size_t)(b * n_heads + h) * TT + t) * DD + j;
    __half h1 = __float2half(y1);
    __half h2 = __float2half(y2);
    oh[ob]      = h1;
    oh[ob + 64] = h2;
    ol[ob]      = __float2half(y1 - __half2float(h1));
    ol[ob + 64] = __float2half(y2 - __half2float(h2));
}

// RoPE + single fp16 + relayout (K)
__global__ void rope_conv_k_kernel(const float* __restrict__ in,
                                   __half* __restrict__ o,
                                   int n_heads, int rs, int total)
{
    int idx = blockIdx.x * blockDim.x + threadIdx.x;
    if (idx >= total) return;
    int j = idx & 63;
    int h = (idx >> 6) % n_heads;
    int r = idx / (64 * n_heads);
    int b = r >> 11;
    int t = r & (TT - 1);

    float e = (float)(2 * j) * (1.0f / 128.0f);
    float inv = 1.0f / powf(10000.0f, e);
    float f = (float)t * inv;
    float c = cosf(f), s = sinf(f);

    const float* p = in + (size_t)r * rs + h * DD;
    float x1 = p[j], x2 = p[j + 64];

    size_t ob = ((size_t)(b * n_heads + h) * TT + t) * DD + j;
    o[ob]      = __float2half(x1 * c - x2 * s);
    o[ob + 64] = __float2half(x2 * c + x1 * s);
}

// V: single fp16 + relayout [b,t,hk,d] -> [b,hk,t,d]
__global__ void v_conv_kernel(const float* __restrict__ in,
                              __half* __restrict__ o, int rs, int total4)
{
    int idx = blockIdx.x * blockDim.x + threadIdx.x;
    if (idx >= total4) return;
    int c4 = idx & 31;
    int h  = (idx >> 5) & 7;
    int r  = idx >> 8;
    int b  = r >> 11;
    int t  = r & (TT - 1);
    float4 v = *(const float4*)(in + (size_t)r * rs + h * DD + c4 * 4);
    size_t ob = ((size_t)(b * HKV + h) * TT + t) * DD + c4 * 4;
    __half2 p0; p0.x = __float2half(v.x); p0.y = __float2half(v.y);
    __half2 p1; p1.x = __float2half(v.z); p1.y = __float2half(v.w);
    *(__half2*)(o + ob)     = p0;
    *(__half2*)(o + ob + 2) = p1;
}

// ============ HMMA fp16 1-pass GEMM (128x256 CTA, 3-stage pipeline) =========
// C[M,N] = A[M,K] @ B^T[N,K]; both single fp16.
#define GBM 128
#define GBN 256
#define GBK 32
#define GEMM_THREADS 256
#define ROW_BYTES 80
#define ARR_A (128 * ROW_BYTES)            // 10240
#define ARR_B (256 * ROW_BYTES)            // 20480
#define STAGE_BYTES (ARR_A + ARR_B)        // 30720
#define OFF_A 0
#define OFF_B ARR_A
#define GEMM_SMEM (3 * STAGE_BYTES)        // 92160

__global__ void __launch_bounds__(GEMM_THREADS, 1)
gemm_f16_kernel(const __half* __restrict__ A, const __half* __restrict__ B,
                float* __restrict__ C, int M, int N, int K)
{
    extern __shared__ char smg[];
    const uint32_t sbase = smem_u32(smg);
    const int tid  = threadIdx.x;
    const int lane = tid & 31;
    const int wid  = tid >> 5;
    const int warp_m = wid >> 2;
    const int warp_n = wid & 3;
    const int m0 = blockIdx.y * GBM;
    const int n0 = blockIdx.x * GBN;

    // stage loader: 1536 16B-chunks, 6 per thread
    auto load_stage = [&](int kt) {
        const uint32_t sdst = sbase + (kt % 3) * STAGE_BYTES;
        const int kofs = kt * GBK;
        #pragma unroll
        for (int i = 0; i < 6; i++) {
            int task = tid + GEMM_THREADS * i;   // 0..1535
            if (task < 512) {
                int row = task >> 2, c = task & 3;
                cp_async16(sdst + OFF_A + row*ROW_BYTES + c*16,
                           A + (size_t)(m0+row)*K + kofs + c*8);
            } else {
                int t2 = task - 512;             // 0..1023
                int row = t2 >> 2, c = t2 & 3;
                cp_async16(sdst + OFF_B + row*ROW_BYTES + c*16,
                           B + (size_t)(n0+row)*K + kofs + c*8);
            }
        }
        CP_COMMIT();
    };

    float acc[4][8][4];
    #pragma unroll
    for (int i = 0; i < 4; i++)
        #pragma unroll
        for (int j = 0; j < 8; j++)
            #pragma unroll
            for (int r = 0; r < 4; r++) acc[i][j][r] = 0.f;

    const int ktiles = K / GBK;

    load_stage(0);
    load_stage(1);

    const uint32_t a_row_b = (uint32_t)(warp_m * 64 + (lane & 15)) * ROW_BYTES
                           + ((lane >> 4) * 16);
    const uint32_t b_row_b = (uint32_t)(warp_n * 64 + ((lane >> 4) & 1) * 8 + (lane & 7)) * ROW_BYTES
                           + (((lane >> 3) & 1) * 16);

    for (int kt = 0; kt < ktiles; kt++) {
        if (kt + 2 < ktiles) { load_stage(kt + 2); CP_WAIT2(); }
        else if (kt + 1 < ktiles) { CP_WAIT1(); }
        else { CP_WAIT0(); }
        __syncthreads();

        const uint32_t st = sbase + (kt % 3) * STAGE_BYTES;
        #pragma unroll
        for (int s = 0; s < 2; s++) {
            const uint32_t koff = s * 32;
            uint32_t af[4][4];
            #pragma unroll
            for (int mt = 0; mt < 4; mt++)
                ldsm4(af[mt], st + OFF_A + a_row_b + mt * (16 * ROW_BYTES) + koff);
            uint32_t bf[4][4];
            #pragma unroll
            for (int np = 0; np < 4; np++)
                ldsm4(bf[np], st + OFF_B + b_row_b + np * (16 * ROW_BYTES) + koff);
            #pragma unroll
            for (int mt = 0; mt < 4; mt++)
                #pragma unroll
                for (int nt = 0; nt < 8; nt++)
                    mma_f16(acc[mt][nt], af[mt], &bf[nt >> 1][(nt & 1) * 2]);
        }
        __syncthreads();
    }

    #pragma unroll
    for (int mt = 0; mt < 4; mt++) {
        int r0 = m0 + warp_m * 64 + mt * 16 + (lane >> 2);
        #pragma unroll
        for (int nt = 0; nt < 8; nt++) {
            int cbase = n0 + warp_n * 64 + nt * 8 + (lane & 3) * 2;
            float2 v0 = make_float2(acc[mt][nt][0], acc[mt][nt][1]);
            float2 v1 = make_float2(acc[mt][nt][2], acc[mt][nt][3]);
            *(float2*)(C + (size_t)r0 * N + cbase)       = v0;
            *(float2*)(C + (size_t)(r0 + 8) * N + cbase) = v1;
        }
    }
}

// ====== Flash attention: fp16 2-pass, Q frags hoisted, double-buffered KV ===
#define ABQ 128
#define ABK 64
#define AROW 136
#define AQH_E 0
#define AQL_E (ABQ*AROW)          // 17408 elems
#define AKV0_E (2*ABQ*AROW)       // 34816 elems
#define KVBUF_E (2*ABK*AROW)      // 17408 elems (K + V)
#define AV_E (ABK*AROW)           // 8704: V offset within buffer
#define ASM_BYTES ((AKV0_E + 2*KVBUF_E)*2)   // 139264
#define ATTN_SCALE 0.08838834764831843f

__global__ void __launch_bounds__(256, 1)
attn_f16_kernel(const __half* __restrict__ Qh, const __half* __restrict__ Ql,
                const __half* __restrict__ Kf, const __half* __restrict__ Vf,
                __half* __restrict__ O)
{
    extern __shared__ __align__(1024) char smA[];
    const uint32_t sb = smem_u32(smA);

    const int tid  = threadIdx.x;
    const int lane = tid & 31;
    const int w    = tid >> 5;
    const int qi   = gridDim.x - 1 - blockIdx.x;   // big tiles first
    const int h    = blockIdx.y;
    const int b    = blockIdx.z;
    const int hk   = h >> 1;
    const int qbase = qi * ABQ;

    const size_t qb0 = ((size_t)(b * HH + h) * TT + qbase) * DD;
    const size_t kb0 = ((size_t)(b * HKV + hk) * TT) * DD;

    // ---- Q tile: 4096 chunks (128 rows x 16 chunks x {hi,lo}) ----
    #pragma unroll
    for (int i = 0; i < 16; i++) {
        int task = tid + 256 * i;        // 0..4095
        int arr = task >> 11;            // 0 hi, 1 lo
        int rem = task & 2047;
        int row = rem >> 4;              // 0..127
        int c   = rem & 15;
        const __half* src = (arr ? Ql : Qh) + qb0 + (size_t)row * DD + c * 8;
        cp_async16(sb + 2 * (uint32_t)((arr ? AQL_E : AQH_E) + row * AROW) + c * 16, src);
    }
    CP_COMMIT();

    auto load_kv = [&](int t, int buf) {
        const uint32_t base = sb + 2 * (uint32_t)(AKV0_E + buf * KVBUF_E);
        const int k0 = t * ABK;
        #pragma unroll
        for (int i = 0; i < 4; i++) {
            int task = tid + 256 * i;    // 0..1023
            int row = task >> 4, c = task & 15;
            cp_async16(base + 2 * (uint32_t)(row * AROW) + c * 16,
                       Kf + kb0 + (size_t)(k0 + row) * DD + c * 8);
        }
        CP_COMMIT();
        #pragma unroll
        for (int i = 0; i < 4; i++) {
            int task = tid + 256 * i;
            int row = task >> 4, c = task & 15;
            cp_async16(base + 2 * (uint32_t)(AV_E + row * AROW) + c * 16,
                       Vf + kb0 + (size_t)(k0 + row) * DD + c * 8);
        }
        CP_COMMIT();
    };

    load_kv(0, 0);

    CP_WAIT2();          // Q complete (K0,V0 may be in flight)
    __syncthreads();

    // ---- hoist Q fragments (reused every KV tile) ----
    const uint32_t qA_h = sb + 2*(uint32_t)(AQH_E + (w*16 + (lane & 15))*AROW) + (lane >> 4)*16;
    const uint32_t qA_l = qA_h + 2*(uint32_t)(AQL_E - AQH_E);
    uint32_t qfh[8][4], qfl[8][4];
    #pragma unroll
    for (int s = 0; s < 8; s++) {
        ldsm4(qfh[s], qA_h + s*32);
        ldsm4(qfl[s], qA_l + s*32);
    }

    float m0 = -INFINITY, m1 = -INFINITY, l0 = 0.f, l1 = 0.f;
    float oacc[16][4];
    #pragma unroll
    for (int j = 0; j < 16; j++)
        #pragma unroll
        for (int r = 0; r < 4; r++) oacc[j][r] = 0.f;

    const int krow  = ((lane >> 4) & 1)*8 + (lane & 7);
    const int kcolh = ((lane >> 3) & 1)*16;
    const int vrow  = ((lane >> 3) & 1)*8 + (lane & 7);
    const int vcolh = (lane >> 4)*16;

    const int ntiles = 2*qi + 2;
    const int qr0 = qbase + w*16 + (lane >> 2);

    for (int t = 0; t < ntiles; t++) {
        const int k0 = t * ABK;
        const int buf = t & 1;

        if (t + 1 < ntiles) { load_kv(t + 1, buf ^ 1); CP_WAIT3(); }
        else                { CP_WAIT1(); }
        __syncthreads();     // K_t visible to all warps

        const uint32_t kvb = sb + 2 * (uint32_t)(AKV0_E + buf * KVBUF_E);

        // ---- S = Q K^T (2 passes: Qhi·K + Qlo·K) ----
        float sacc[8][4];
        #pragma unroll
        for (int j = 0; j < 8; j++)
            #pragma unroll
            for (int r = 0; r < 4; r++) sacc[j][r] = 0.f;

        #pragma unroll
        for (int s = 0; s < 8; s++) {
            #pragma unroll
            for (int jj = 0; jj < 4; jj++) {
                uint32_t kf[4];
                uint32_t ka = kvb + 2*(uint32_t)((16*jj + krow)*AROW) + s*32 + kcolh;
                ldsm4(kf, ka);
                mma_f16(sacc[2*jj],   qfh[s], &kf[0]);
                mma_f16(sacc[2*jj],   qfl[s], &kf[0]);
                mma_f16(sacc[2*jj+1], qfh[s], &kf[2]);
                mma_f16(sacc[2*jj+1], qfl[s], &kf[2]);
            }
        }

        if (t + 1 < ntiles) CP_WAIT2(); else CP_WAIT0();   // V_t complete
        __syncthreads();

        // ---- online softmax ----
        const bool domask = (t >= ntiles - 2);
        float mx0 = -INFINITY, mx1 = -INFINITY;
        #pragma unroll
        for (int j = 0; j < 8; j++) {
            #pragma unroll
            for (int r = 0; r < 4; r++) {
                float sv = sacc[j][r] * ATTN_SCALE;
                if (domask) {
                    int col = k0 + 8*j + (lane & 3)*2 + (r & 1);
                    int qr  = qr0 + ((r >= 2) ? 8 : 0);
                    if (col > qr) sv = -INFINITY;
                }
                sacc[j][r] = sv;
                if (r < 2) mx0 = fmaxf(mx0, sv); else mx1 = fmaxf(mx1, sv);
            }
        }
        mx0 = fmaxf(mx0, __shfl_xor_sync(0xffffffffu, mx0, 1));
        mx0 = fmaxf(mx0, __shfl_xor_sync(0xffffffffu, mx0, 2));
        mx1 = fmaxf(mx1, __shfl_xor_sync(0xffffffffu, mx1, 1));
        mx1 = fmaxf(mx1, __shfl_xor_sync(0xffffffffu, mx1, 2));

        float m0n = fmaxf(m0, mx0), m1n = fmaxf(m1, mx1);
        float a0 = __expf(m0 - m0n), a1 = __expf(m1 - m1n);
        float ls0 = 0.f, ls1 = 0.f;
        #pragma unroll
        for (int j = 0; j < 8; j++) {
            float p0 = __expf(sacc[j][0] - m0n);
            float p1 = __expf(sacc[j][1] - m0n);
            float p2 = __expf(sacc[j][2] - m1n);
            float p3 = __expf(sacc[j][3] - m1n);
            sacc[j][0] = p0; sacc[j][1] = p1; sacc[j][2] = p2; sacc[j][3] = p3;
            ls0 += p0 + p1; ls1 += p2 + p3;
        }
        ls0 += __shfl_xor_sync(0xffffffffu, ls0, 1);
        ls0 += __shfl_xor_sync(0xffffffffu, ls0, 2);
        ls1 += __shfl_xor_sync(0xffffffffu, ls1, 1);
        ls1 += __shfl_xor_sync(0xffffffffu, ls1, 2);

        l0 = l0 * a0 + ls0;
        l1 = l1 * a1 + ls1;
        m0 = m0n; m1 = m1n;
        #pragma unroll
        for (int j = 0; j < 16; j++) {
            oacc[j][0] *= a0; oacc[j][1] *= a0;
            oacc[j][2] *= a1; oacc[j][3] *= a1;
        }

        // ---- O += P V (2 passes: Phi·V + Plo·V) ----
        #pragma unroll
        for (int s2 = 0; s2 < 4; s2++) {
            uint32_t php[4], plp[4];
            packsplit_h(sacc[2*s2][0],   sacc[2*s2][1],   php[0], plp[0]);
            packsplit_h(sacc[2*s2][2],   sacc[2*s2][3],   php[1], plp[1]);
            packsplit_h(sacc[2*s2+1][0], sacc[2*s2+1][1], php[2], plp[2]);
            packsplit_h(sacc[2*s2+1][2], sacc[2*s2+1][3], php[3], plp[3]);
            uint32_t va = kvb + 2*(uint32_t)(AV_E + (16*s2 + vrow)*AROW) + vcolh;
            #pragma unroll
            for (int dd = 0; dd < 8; dd++) {
                uint32_t vf[4];
                ldsm4t(vf, va + dd*32);
                mma_f16(oacc[2*dd],   php, &vf[0]);
                mma_f16(oacc[2*dd],   plp, &vf[0]);
                mma_f16(oacc[2*dd+1], php, &vf[2]);
                mma_f16(oacc[2*dd+1], plp, &vf[2]);
            }
        }
        __syncthreads();   // all reads of this buffer done before its next overwrite
    }

    // ---- epilogue: normalize + write single fp16 ([b,t,h*d] for Wp GEMM) ----
    float i0 = 1.f / l0, i1 = 1.f / l1;
    const int row0 = qbase + w*16 + (lane >> 2);
    const int col0 = (lane & 3)*2;
    #pragma unroll
    for (int j = 0; j < 16; j++) {
        int col = j*8 + col0;
        size_t base0 = ((size_t)(b*TT + row0)*HH + h)*DD + col;
        size_t base1 = base0 + (size_t)8*HH*DD;
        __half2 v0; v0.x = __float2half(oacc[j][0]*i0); v0.y = __float2half(oacc[j][1]*i0);
        __half2 v1; v1.x = __float2half(oacc[j][2]*i1); v1.y = __float2half(oacc[j][3]*i1);
        *(__half2*)(O + base0) = v0;
        *(__half2*)(O + base1) = v1;
    }
}

// ---------------- host entry -------------------------------------------------
extern "C" void kernel_launch(void* const* d_in, const int* in_sizes, int n_in,
                              void* d_out, int out_size)
{
    const float* x  = (const float*)d_in[0];
    const float* Wq = (const float*)d_in[1];
    const float* Wk = (const float*)d_in[2];
    const float* Wv = (const float*)d_in[3];
    const float* Wp = (const float*)d_in[4];
    float* out = (float*)d_out;

    float *qkv;
    __half *xf, *of, *wqkv, *wp, *qh, *ql, *kf, *vf;
    cudaGetSymbolAddress((void**)&qkv, g_qkv);
    cudaGetSymbolAddress((void**)&xf, g_xf);
    cudaGetSymbolAddress((void**)&of, g_of);
    cudaGetSymbolAddress((void**)&wqkv, g_wqkv);
    cudaGetSymbolAddress((void**)&wp, g_wp);
    cudaGetSymbolAddress((void**)&qh, g_qh);   cudaGetSymbolAddress((void**)&ql, g_ql);
    cudaGetSymbolAddress((void**)&kf, g_kf);   cudaGetSymbolAddress((void**)&vf, g_vf);

    cudaFuncSetAttribute(gemm_f16_kernel, cudaFuncAttributeMaxDynamicSharedMemorySize, GEMM_SMEM);
    cudaFuncSetAttribute(attn_f16_kernel, cudaFuncAttributeMaxDynamicSharedMemorySize, ASM_BYTES);

    // (1) convert x to fp16
    {
        int n4 = (NROW * CC) / 4;
        conv_h_kernel<<<(n4 + 255) / 256, 256>>>((const float4*)x, (__half2*)xf, n4);
    }
    // (2-5) transpose + convert all weights
    transpose_conv_kernel<<<dim3(CC/32, CC/32), dim3(32, 8)>>>(Wq, wqkv, CC, CC);
    transpose_conv_kernel<<<dim3((HKV*DD)/32, CC/32), dim3(32, 8)>>>(
        Wk, wqkv + (size_t)2048 * CC, CC, HKV*DD);
    transpose_conv_kernel<<<dim3((HKV*DD)/32, CC/32), dim3(32, 8)>>>(
        Wv, wqkv + (size_t)3072 * CC, CC, HKV*DD);
    transpose_conv_kernel<<<dim3(CC/32, CC/32), dim3(32, 8)>>>(Wp, wp, CC, CC);

    // (6) fused QKV projection  <- ncu capture slot
    gemm_f16_kernel<<<dim3(4096/GBN, NROW/GBM), GEMM_THREADS, GEMM_SMEM>>>(
        xf, wqkv, qkv, NROW, 4096, CC);

    // (7-9) RoPE + relayout (fp16 for attention)
    {
        int totq = NROW * HH * 64;
        rope_split_q_kernel<<<(totq + 255) / 256, 256>>>(qkv, qh, ql, HH, 4096, totq);
        int totk = NROW * HKV * 64;
        rope_conv_k_kernel<<<(totk + 255) / 256, 256>>>(qkv + 2048, kf, HKV, 4096, totk);
        int totv = NROW * HKV * 32;
        v_conv_kernel<<<(totv + 255) / 256, 256>>>(qkv + 3072, vf, 4096, totv);
    }

    // (10) attention (fp16 2-pass HMMA), single fp16 O out
    attn_f16_kernel<<<dim3(TT / ABQ, HH, BB), 256, ASM_BYTES>>>(qh, ql, kf, vf, of);

    // (11) output projection (1-pass)
    gemm_f16_kernel<<<dim3(CC/GBN, NROW/GBM), GEMM_THREADS, GEMM_SMEM>>>(
        of, wp, out, NROW, CC, CC);
}

// round 13
// speedup vs baseline: 4.3572x; 1.1334x over previous
#include <cuda_runtime.h>
#include <cuda_bf16.h>
#include <cuda_fp16.h>
#include <math.h>
#include <cstdint>

// Problem constants
#define BB 2
#define TT 2048
#define CC 2048
#define HH 16
#define HKV 8
#define DD 128
#define NROW (BB*TT)          // 4096

// ---------------- scratch (device globals; no allocation allowed) ----------
__device__ float g_qkv[(size_t)NROW * 4096];   // cols: 0-2047 q, 2048-3071 k, 3072-4095 v

__device__ __align__(16) __half g_xf[(size_t)NROW * CC];
__device__ __align__(16) __half g_of[(size_t)NROW * CC];
__device__ __align__(16) __half g_wqkv[(size_t)4096 * CC];   // [Wq|Wk|Wv]^T
__device__ __align__(16) __half g_wp[(size_t)CC * CC];       // Wp^T

// head-major fp16 Q/K/V for attention
__device__ __align__(16) __half g_qf[(size_t)BB * HH * TT * DD];
__device__ __align__(16) __half g_kf[(size_t)BB * HKV * TT * DD];
__device__ __align__(16) __half g_vf[(size_t)BB * HKV * TT * DD];

// ======================= low-level helpers ==================================
__device__ __forceinline__ uint32_t smem_u32(const void* p) {
    uint32_t a;
    asm("{ .reg .u64 t; cvta.to.shared.u64 t, %1; cvt.u32.u64 %0, t; }"
        : "=r"(a) : "l"(p));
    return a;
}
__device__ __forceinline__ void ldsm4(uint32_t* r, uint32_t addr) {
    asm volatile("ldmatrix.sync.aligned.m8n8.x4.shared.b16 {%0,%1,%2,%3}, [%4];"
        : "=r"(r[0]), "=r"(r[1]), "=r"(r[2]), "=r"(r[3]) : "r"(addr));
}
__device__ __forceinline__ void ldsm4t(uint32_t* r, uint32_t addr) {
    asm volatile("ldmatrix.sync.aligned.m8n8.x4.trans.shared.b16 {%0,%1,%2,%3}, [%4];"
        : "=r"(r[0]), "=r"(r[1]), "=r"(r[2]), "=r"(r[3]) : "r"(addr));
}
__device__ __forceinline__ void mma_f16(float* d, const uint32_t* a, const uint32_t* b) {
    asm volatile(
        "mma.sync.aligned.m16n8k16.row.col.f32.f16.f16.f32 "
        "{%0,%1,%2,%3}, {%4,%5,%6,%7}, {%8,%9}, {%0,%1,%2,%3};"
        : "+f"(d[0]), "+f"(d[1]), "+f"(d[2]), "+f"(d[3])
        : "r"(a[0]), "r"(a[1]), "r"(a[2]), "r"(a[3]), "r"(b[0]), "r"(b[1]));
}
__device__ __forceinline__ void cp_async16(uint32_t dst, const void* src) {
    asm volatile("cp.async.cg.shared.global [%0], [%1], 16;\n" :: "r"(dst), "l"(src));
}
#define CP_COMMIT() asm volatile("cp.async.commit_group;\n" ::: "memory")
#define CP_WAIT3()  asm volatile("cp.async.wait_group 3;\n" ::: "memory")
#define CP_WAIT2()  asm volatile("cp.async.wait_group 2;\n" ::: "memory")
#define CP_WAIT1()  asm volatile("cp.async.wait_group 1;\n" ::: "memory")
#define CP_WAIT0()  asm volatile("cp.async.wait_group 0;\n" ::: "memory")

__device__ __forceinline__ uint32_t pack_h2(float a, float b) {
    __half2 H; H.x = __float2half(a); H.y = __float2half(b);
    return *(uint32_t*)&H;
}

// ======================= conversion kernels =================================
// fp32 -> fp16 (single rounding)
__global__ void conv_h_kernel(const float4* __restrict__ in,
                              __half2* __restrict__ o, int n4)
{
    int i = blockIdx.x * blockDim.x + threadIdx.x;
    if (i >= n4) return;
    float4 v = in[i];
    __half2 p0; p0.x = __float2half(v.x); p0.y = __float2half(v.y);
    __half2 p1; p1.x = __float2half(v.z); p1.y = __float2half(v.w);
    o[2*i]   = p0;
    o[2*i+1] = p1;
}

// W: [K, N] row-major -> T: [N, K] row-major fp16 (single rounding)
__global__ void transpose_conv_kernel(const float* __restrict__ W,
                                      __half* __restrict__ T, int K, int N)
{
    __shared__ float t[32][33];
    int n0 = blockIdx.x * 32, k0 = blockIdx.y * 32;
    int tx = threadIdx.x, ty = threadIdx.y;   // (32, 8)
    #pragma unroll
    for (int j = 0; j < 32; j += 8)
        t[ty + j][tx] = W[(size_t)(k0 + ty + j) * N + n0 + tx];
    __syncthreads();
    #pragma unroll
    for (int j = 0; j < 32; j += 8)
        T[(size_t)(n0 + ty + j) * K + k0 + tx] = __float2half(t[tx][ty + j]);
}

// RoPE + single fp16 + relayout [b,t,h,d] -> [b,h,t,d] (Q and K)
__global__ void rope_conv_kernel(const float* __restrict__ in,
                                 __half* __restrict__ o,
                                 int n_heads, int rs, int total)
{
    int idx = blockIdx.x * blockDim.x + threadIdx.x;
    if (idx >= total) return;
    int j = idx & 63;
    int h = (idx >> 6) % n_heads;
    int r = idx / (64 * n_heads);
    int b = r >> 11;
    int t = r & (TT - 1);

    float e = (float)(2 * j) * (1.0f / 128.0f);
    float inv = 1.0f / powf(10000.0f, e);
    float f = (float)t * inv;
    float c = cosf(f), s = sinf(f);

    const float* p = in + (size_t)r * rs + h * DD;
    float x1 = p[j], x2 = p[j + 64];

    size_t ob = ((size_t)(b * n_heads + h) * TT + t) * DD + j;
    o[ob]      = __float2half(x1 * c - x2 * s);
    o[ob + 64] = __float2half(x2 * c + x1 * s);
}

// V: single fp16 + relayout [b,t,hk,d] -> [b,hk,t,d]
__global__ void v_conv_kernel(const float* __restrict__ in,
                              __half* __restrict__ o, int rs, int total4)
{
    int idx = blockIdx.x * blockDim.x + threadIdx.x;
    if (idx >= total4) return;
    int c4 = idx & 31;
    int h  = (idx >> 5) & 7;
    int r  = idx >> 8;
    int b  = r >> 11;
    int t  = r & (TT - 1);
    float4 v = *(const float4*)(in + (size_t)r * rs + h * DD + c4 * 4);
    size_t ob = ((size_t)(b * HKV + h) * TT + t) * DD + c4 * 4;
    __half2 p0; p0.x = __float2half(v.x); p0.y = __float2half(v.y);
    __half2 p1; p1.x = __float2half(v.z); p1.y = __float2half(v.w);
    *(__half2*)(o + ob)     = p0;
    *(__half2*)(o + ob + 2) = p1;
}

// ============ HMMA fp16 1-pass GEMM (128x256 CTA, 3-stage pipeline) =========
#define GBM 128
#define GBN 256
#define GBK 32
#define GEMM_THREADS 256
#define ROW_BYTES 80
#define ARR_A (128 * ROW_BYTES)            // 10240
#define ARR_B (256 * ROW_BYTES)            // 20480
#define STAGE_BYTES (ARR_A + ARR_B)        // 30720
#define OFF_A 0
#define OFF_B ARR_A
#define GEMM_SMEM (3 * STAGE_BYTES)        // 92160

__global__ void __launch_bounds__(GEMM_THREADS, 1)
gemm_f16_kernel(const __half* __restrict__ A, const __half* __restrict__ B,
                float* __restrict__ C, int M, int N, int K)
{
    extern __shared__ char smg[];
    const uint32_t sbase = smem_u32(smg);
    const int tid  = threadIdx.x;
    const int lane = tid & 31;
    const int wid  = tid >> 5;
    const int warp_m = wid >> 2;
    const int warp_n = wid & 3;
    const int m0 = blockIdx.y * GBM;
    const int n0 = blockIdx.x * GBN;

    auto load_stage = [&](int kt) {
        const uint32_t sdst = sbase + (kt % 3) * STAGE_BYTES;
        const int kofs = kt * GBK;
        #pragma unroll
        for (int i = 0; i < 6; i++) {
            int task = tid + GEMM_THREADS * i;   // 0..1535
            if (task < 512) {
                int row = task >> 2, c = task & 3;
                cp_async16(sdst + OFF_A + row*ROW_BYTES + c*16,
                           A + (size_t)(m0+row)*K + kofs + c*8);
            } else {
                int t2 = task - 512;             // 0..1023
                int row = t2 >> 2, c = t2 & 3;
                cp_async16(sdst + OFF_B + row*ROW_BYTES + c*16,
                           B + (size_t)(n0+row)*K + kofs + c*8);
            }
        }
        CP_COMMIT();
    };

    float acc[4][8][4];
    #pragma unroll
    for (int i = 0; i < 4; i++)
        #pragma unroll
        for (int j = 0; j < 8; j++)
            #pragma unroll
            for (int r = 0; r < 4; r++) acc[i][j][r] = 0.f;

    const int ktiles = K / GBK;

    load_stage(0);
    load_stage(1);

    const uint32_t a_row_b = (uint32_t)(warp_m * 64 + (lane & 15)) * ROW_BYTES
                           + ((lane >> 4) * 16);
    const uint32_t b_row_b = (uint32_t)(warp_n * 64 + ((lane >> 4) & 1) * 8 + (lane & 7)) * ROW_BYTES
                           + (((lane >> 3) & 1) * 16);

    for (int kt = 0; kt < ktiles; kt++) {
        if (kt + 2 < ktiles) { load_stage(kt + 2); CP_WAIT2(); }
        else if (kt + 1 < ktiles) { CP_WAIT1(); }
        else { CP_WAIT0(); }
        __syncthreads();

        const uint32_t st = sbase + (kt % 3) * STAGE_BYTES;
        #pragma unroll
        for (int s = 0; s < 2; s++) {
            const uint32_t koff = s * 32;
            uint32_t af[4][4];
            #pragma unroll
            for (int mt = 0; mt < 4; mt++)
                ldsm4(af[mt], st + OFF_A + a_row_b + mt * (16 * ROW_BYTES) + koff);
            uint32_t bf[4][4];
            #pragma unroll
            for (int np = 0; np < 4; np++)
                ldsm4(bf[np], st + OFF_B + b_row_b + np * (16 * ROW_BYTES) + koff);
            #pragma unroll
            for (int mt = 0; mt < 4; mt++)
                #pragma unroll
                for (int nt = 0; nt < 8; nt++)
                    mma_f16(acc[mt][nt], af[mt], &bf[nt >> 1][(nt & 1) * 2]);
        }
        __syncthreads();
    }

    #pragma unroll
    for (int mt = 0; mt < 4; mt++) {
        int r0 = m0 + warp_m * 64 + mt * 16 + (lane >> 2);
        #pragma unroll
        for (int nt = 0; nt < 8; nt++) {
            int cbase = n0 + warp_n * 64 + nt * 8 + (lane & 3) * 2;
            float2 v0 = make_float2(acc[mt][nt][0], acc[mt][nt][1]);
            float2 v1 = make_float2(acc[mt][nt][2], acc[mt][nt][3]);
            *(float2*)(C + (size_t)r0 * N + cbase)       = v0;
            *(float2*)(C + (size_t)(r0 + 8) * N + cbase) = v1;
        }
    }
}

// ====== Flash attention: fp16 1-pass, Q frags hoisted, double-buffered KV ===
#define ABQ 128
#define ABK 64
#define AROW 136
#define AQ_E 0
#define AKV0_E (ABQ*AROW)         // 17408 elems
#define KVBUF_E (2*ABK*AROW)      // 17408 elems (K + V)
#define AV_E (ABK*AROW)           // 8704: V offset within buffer
#define ASM_BYTES ((AKV0_E + 2*KVBUF_E)*2)   // 104448
#define ATTN_SCALE 0.08838834764831843f

__global__ void __launch_bounds__(256, 1)
attn_f16_kernel(const __half* __restrict__ Qf,
                const __half* __restrict__ Kf, const __half* __restrict__ Vf,
                __half* __restrict__ O)
{
    extern __shared__ __align__(1024) char smA[];
    const uint32_t sb = smem_u32(smA);

    const int tid  = threadIdx.x;
    const int lane = tid & 31;
    const int w    = tid >> 5;
    const int qi   = gridDim.x - 1 - blockIdx.x;   // big tiles first
    const int h    = blockIdx.y;
    const int b    = blockIdx.z;
    const int hk   = h >> 1;
    const int qbase = qi * ABQ;

    const size_t qb0 = ((size_t)(b * HH + h) * TT + qbase) * DD;
    const size_t kb0 = ((size_t)(b * HKV + hk) * TT) * DD;

    // ---- Q tile: 2048 chunks (128 rows x 16 chunks) ----
    #pragma unroll
    for (int i = 0; i < 8; i++) {
        int task = tid + 256 * i;        // 0..2047
        int row = task >> 4;             // 0..127
        int c   = task & 15;
        cp_async16(sb + 2 * (uint32_t)(AQ_E + row * AROW) + c * 16,
                   Qf + qb0 + (size_t)row * DD + c * 8);
    }
    CP_COMMIT();

    auto load_kv = [&](int t, int buf) {
        const uint32_t base = sb + 2 * (uint32_t)(AKV0_E + buf * KVBUF_E);
        const int k0 = t * ABK;
        #pragma unroll
        for (int i = 0; i < 4; i++) {
            int task = tid + 256 * i;    // 0..1023
            int row = task >> 4, c = task & 15;
            cp_async16(base + 2 * (uint32_t)(row * AROW) + c * 16,
                       Kf + kb0 + (size_t)(k0 + row) * DD + c * 8);
        }
        CP_COMMIT();
        #pragma unroll
        for (int i = 0; i < 4; i++) {
            int task = tid + 256 * i;
            int row = task >> 4, c = task & 15;
            cp_async16(base + 2 * (uint32_t)(AV_E + row * AROW) + c * 16,
                       Vf + kb0 + (size_t)(k0 + row) * DD + c * 8);
        }
        CP_COMMIT();
    };

    load_kv(0, 0);

    CP_WAIT2();          // Q complete (K0,V0 may be in flight)
    __syncthreads();

    // ---- hoist Q fragments (reused every KV tile) ----
    const uint32_t qA = sb + 2*(uint32_t)(AQ_E + (w*16 + (lane & 15))*AROW) + (lane >> 4)*16;
    uint32_t qf[8][4];
    #pragma unroll
    for (int s = 0; s < 8; s++)
        ldsm4(qf[s], qA + s*32);

    float m0 = -INFINITY, m1 = -INFINITY, l0 = 0.f, l1 = 0.f;
    float oacc[16][4];
    #pragma unroll
    for (int j = 0; j < 16; j++)
        #pragma unroll
        for (int r = 0; r < 4; r++) oacc[j][r] = 0.f;

    const int krow  = ((lane >> 4) & 1)*8 + (lane & 7);
    const int kcolh = ((lane >> 3) & 1)*16;
    const int vrow  = ((lane >> 3) & 1)*8 + (lane & 7);
    const int vcolh = (lane >> 4)*16;

    const int ntiles = 2*qi + 2;
    const int qr0 = qbase + w*16 + (lane >> 2);

    for (int t = 0; t < ntiles; t++) {
        const int k0 = t * ABK;
        const int buf = t & 1;

        if (t + 1 < ntiles) { load_kv(t + 1, buf ^ 1); CP_WAIT3(); }
        else                { CP_WAIT1(); }
        __syncthreads();     // K_t visible to all warps

        const uint32_t kvb = sb + 2 * (uint32_t)(AKV0_E + buf * KVBUF_E);

        // ---- S = Q K^T (single pass) ----
        float sacc[8][4];
        #pragma unroll
        for (int j = 0; j < 8; j++)
            #pragma unroll
            for (int r = 0; r < 4; r++) sacc[j][r] = 0.f;

        #pragma unroll
        for (int s = 0; s < 8; s++) {
            #pragma unroll
            for (int jj = 0; jj < 4; jj++) {
                uint32_t kf[4];
                uint32_t ka = kvb + 2*(uint32_t)((16*jj + krow)*AROW) + s*32 + kcolh;
                ldsm4(kf, ka);
                mma_f16(sacc[2*jj],   qf[s], &kf[0]);
                mma_f16(sacc[2*jj+1], qf[s], &kf[2]);
            }
        }

        if (t + 1 < ntiles) CP_WAIT2(); else CP_WAIT0();   // V_t complete
        __syncthreads();

        // ---- online softmax ----
        const bool domask = (t >= ntiles - 2);
        float mx0 = -INFINITY, mx1 = -INFINITY;
        #pragma unroll
        for (int j = 0; j < 8; j++) {
            #pragma unroll
            for (int r = 0; r < 4; r++) {
                float sv = sacc[j][r] * ATTN_SCALE;
                if (domask) {
                    int col = k0 + 8*j + (lane & 3)*2 + (r & 1);
                    int qr  = qr0 + ((r >= 2) ? 8 : 0);
                    if (col > qr) sv = -INFINITY;
                }
                sacc[j][r] = sv;
                if (r < 2) mx0 = fmaxf(mx0, sv); else mx1 = fmaxf(mx1, sv);
            }
        }
        mx0 = fmaxf(mx0, __shfl_xor_sync(0xffffffffu, mx0, 1));
        mx0 = fmaxf(mx0, __shfl_xor_sync(0xffffffffu, mx0, 2));
        mx1 = fmaxf(mx1, __shfl_xor_sync(0xffffffffu, mx1, 1));
        mx1 = fmaxf(mx1, __shfl_xor_sync(0xffffffffu, mx1, 2));

        float m0n = fmaxf(m0, mx0), m1n = fmaxf(m1, mx1);
        float a0 = __expf(m0 - m0n), a1 = __expf(m1 - m1n);
        float ls0 = 0.f, ls1 = 0.f;
        #pragma unroll
        for (int j = 0; j < 8; j++) {
            float p0 = __expf(sacc[j][0] - m0n);
            float p1 = __expf(sacc[j][1] - m0n);
            float p2 = __expf(sacc[j][2] - m1n);
            float p3 = __expf(sacc[j][3] - m1n);
            sacc[j][0] = p0; sacc[j][1] = p1; sacc[j][2] = p2; sacc[j][3] = p3;
            ls0 += p0 + p1; ls1 += p2 + p3;
        }
        ls0 += __shfl_xor_sync(0xffffffffu, ls0, 1);
        ls0 += __shfl_xor_sync(0xffffffffu, ls0, 2);
        ls1 += __shfl_xor_sync(0xffffffffu, ls1, 1);
        ls1 += __shfl_xor_sync(0xffffffffu, ls1, 2);

        l0 = l0 * a0 + ls0;
        l1 = l1 * a1 + ls1;
        m0 = m0n; m1 = m1n;
        #pragma unroll
        for (int j = 0; j < 16; j++) {
            oacc[j][0] *= a0; oacc[j][1] *= a0;
            oacc[j][2] *= a1; oacc[j][3] *= a1;
        }

        // ---- O += P V (single pass, P single fp16) ----
        #pragma unroll
        for (int s2 = 0; s2 < 4; s2++) {
            uint32_t pp[4];
            pp[0] = pack_h2(sacc[2*s2][0],   sacc[2*s2][1]);
            pp[1] = pack_h2(sacc[2*s2][2],   sacc[2*s2][3]);
            pp[2] = pack_h2(sacc[2*s2+1][0], sacc[2*s2+1][1]);
            pp[3] = pack_h2(sacc[2*s2+1][2], sacc[2*s2+1][3]);
            uint32_t va = kvb + 2*(uint32_t)(AV_E + (16*s2 + vrow)*AROW) + vcolh;
            #pragma unroll
            for (int dd = 0; dd < 8; dd++) {
                uint32_t vf[4];
                ldsm4t(vf, va + dd*32);
                mma_f16(oacc[2*dd],   pp, &vf[0]);
                mma_f16(oacc[2*dd+1], pp, &vf[2]);
            }
        }
        __syncthreads();   // all reads of this buffer done before its next overwrite
    }

    // ---- epilogue: normalize + write single fp16 ([b,t,h*d] for Wp GEMM) ----
    float i0 = 1.f / l0, i1 = 1.f / l1;
    const int row0 = qbase + w*16 + (lane >> 2);
    const int col0 = (lane & 3)*2;
    #pragma unroll
    for (int j = 0; j < 16; j++) {
        int col = j*8 + col0;
        size_t base0 = ((size_t)(b*TT + row0)*HH + h)*DD + col;
        size_t base1 = base0 + (size_t)8*HH*DD;
        __half2 v0; v0.x = __float2half(oacc[j][0]*i0); v0.y = __float2half(oacc[j][1]*i0);
        __half2 v1; v1.x = __float2half(oacc[j][2]*i1); v1.y = __float2half(oacc[j][3]*i1);
        *(__half2*)(O + base0) = v0;
        *(__half2*)(O + base1) = v1;
    }
}

// ---------------- host entry -------------------------------------------------
extern "C" void kernel_launch(void* const* d_in, const int* in_sizes, int n_in,
                              void* d_out, int out_size)
{
    const float* x  = (const float*)d_in[0];
    const float* Wq = (const float*)d_in[1];
    const float* Wk = (const float*)d_in[2];
    const float* Wv = (const float*)d_in[3];
    const float* Wp = (const float*)d_in[4];
    float* out = (float*)d_out;

    float *qkv;
    __half *xf, *of, *wqkv, *wp, *qf, *kf, *vf;
    cudaGetSymbolAddress((void**)&qkv, g_qkv);
    cudaGetSymbolAddress((void**)&xf, g_xf);
    cudaGetSymbolAddress((void**)&of, g_of);
    cudaGetSymbolAddress((void**)&wqkv, g_wqkv);
    cudaGetSymbolAddress((void**)&wp, g_wp);
    cudaGetSymbolAddress((void**)&qf, g_qf);
    cudaGetSymbolAddress((void**)&kf, g_kf);
    cudaGetSymbolAddress((void**)&vf, g_vf);

    cudaFuncSetAttribute(gemm_f16_kernel, cudaFuncAttributeMaxDynamicSharedMemorySize, GEMM_SMEM);
    cudaFuncSetAttribute(attn_f16_kernel, cudaFuncAttributeMaxDynamicSharedMemorySize, ASM_BYTES);

    // (1) convert x to fp16
    {
        int n4 = (NROW * CC) / 4;
        conv_h_kernel<<<(n4 + 255) / 256, 256>>>((const float4*)x, (__half2*)xf, n4);
    }
    // (2-5) transpose + convert all weights
    transpose_conv_kernel<<<dim3(CC/32, CC/32), dim3(32, 8)>>>(Wq, wqkv, CC, CC);
    transpose_conv_kernel<<<dim3((HKV*DD)/32, CC/32), dim3(32, 8)>>>(
        Wk, wqkv + (size_t)2048 * CC, CC, HKV*DD);
    transpose_conv_kernel<<<dim3((HKV*DD)/32, CC/32), dim3(32, 8)>>>(
        Wv, wqkv + (size_t)3072 * CC, CC, HKV*DD);
    transpose_conv_kernel<<<dim3(CC/32, CC/32), dim3(32, 8)>>>(Wp, wp, CC, CC);

    // (6) fused QKV projection
    gemm_f16_kernel<<<dim3(4096/GBN, NROW/GBM), GEMM_THREADS, GEMM_SMEM>>>(
        xf, wqkv, qkv, NROW, 4096, CC);

    // (7-9) RoPE + relayout (fp16 for attention)
    {
        int totq = NROW * HH * 64;
        rope_conv_kernel<<<(totq + 255) / 256, 256>>>(qkv, qf, HH, 4096, totq);
        int totk = NROW * HKV * 64;
        rope_conv_kernel<<<(totk + 255) / 256, 256>>>(qkv + 2048, kf, HKV, 4096, totk);
        int totv = NROW * HKV * 32;
        v_conv_kernel<<<(totv + 255) / 256, 256>>>(qkv + 3072, vf, 4096, totv);
    }

    // (10) attention (fp16 1-pass HMMA), single fp16 O out
    attn_f16_kernel<<<dim3(TT / ABQ, HH, BB), 256, ASM_BYTES>>>(qf, kf, vf, of);

    // (11) output projection (1-pass)
    gemm_f16_kernel<<<dim3(CC/GBN, NROW/GBM), GEMM_THREADS, GEMM_SMEM>>>(
        of, wp, out, NROW, CC, CC);
}

// round 14
// speedup vs baseline: 4.4872x; 1.0298x over previous
#include <cuda_runtime.h>
#include <cuda_bf16.h>
#include <cuda_fp16.h>
#include <math.h>
#include <cstdint>

// Problem constants
#define BB 2
#define TT 2048
#define CC 2048
#define HH 16
#define HKV 8
#define DD 128
#define NROW (BB*TT)          // 4096

// ---------------- scratch (device globals; no allocation allowed) ----------
__device__ __align__(16) __half g_qkvh[(size_t)NROW * 4096]; // fp16: q|k|v cols
__device__ __align__(16) __half g_xf[(size_t)NROW * CC];
__device__ __align__(16) __half g_of[(size_t)NROW * CC];
__device__ __align__(16) __half g_wqkv[(size_t)4096 * CC];   // [Wq|Wk|Wv]^T
__device__ __align__(16) __half g_wp[(size_t)CC * CC];       // Wp^T

// ======================= low-level helpers ==================================
__device__ __forceinline__ uint32_t smem_u32(const void* p) {
    uint32_t a;
    asm("{ .reg .u64 t; cvta.to.shared.u64 t, %1; cvt.u32.u64 %0, t; }"
        : "=r"(a) : "l"(p));
    return a;
}
__device__ __forceinline__ void ldsm4(uint32_t* r, uint32_t addr) {
    asm volatile("ldmatrix.sync.aligned.m8n8.x4.shared.b16 {%0,%1,%2,%3}, [%4];"
        : "=r"(r[0]), "=r"(r[1]), "=r"(r[2]), "=r"(r[3]) : "r"(addr));
}
__device__ __forceinline__ void ldsm4t(uint32_t* r, uint32_t addr) {
    asm volatile("ldmatrix.sync.aligned.m8n8.x4.trans.shared.b16 {%0,%1,%2,%3}, [%4];"
        : "=r"(r[0]), "=r"(r[1]), "=r"(r[2]), "=r"(r[3]) : "r"(addr));
}
__device__ __forceinline__ void mma_f16(float* d, const uint32_t* a, const uint32_t* b) {
    asm volatile(
        "mma.sync.aligned.m16n8k16.row.col.f32.f16.f16.f32 "
        "{%0,%1,%2,%3}, {%4,%5,%6,%7}, {%8,%9}, {%0,%1,%2,%3};"
        : "+f"(d[0]), "+f"(d[1]), "+f"(d[2]), "+f"(d[3])
        : "r"(a[0]), "r"(a[1]), "r"(a[2]), "r"(a[3]), "r"(b[0]), "r"(b[1]));
}
__device__ __forceinline__ void cp_async16(uint32_t dst, const void* src) {
    asm volatile("cp.async.cg.shared.global [%0], [%1], 16;\n" :: "r"(dst), "l"(src));
}
#define CP_COMMIT() asm volatile("cp.async.commit_group;\n" ::: "memory")
#define CP_WAIT3()  asm volatile("cp.async.wait_group 3;\n" ::: "memory")
#define CP_WAIT2()  asm volatile("cp.async.wait_group 2;\n" ::: "memory")
#define CP_WAIT1()  asm volatile("cp.async.wait_group 1;\n" ::: "memory")
#define CP_WAIT0()  asm volatile("cp.async.wait_group 0;\n" ::: "memory")

__device__ __forceinline__ uint32_t pack_h2(float a, float b) {
    __half2 H; H.x = __float2half(a); H.y = __float2half(b);
    return *(uint32_t*)&H;
}

// ======================= conversion kernels =================================
// fp32 -> fp16 (single rounding)
__global__ void conv_h_kernel(const float4* __restrict__ in,
                              __half2* __restrict__ o, int n4)
{
    int i = blockIdx.x * blockDim.x + threadIdx.x;
    if (i >= n4) return;
    float4 v = in[i];
    __half2 p0; p0.x = __float2half(v.x); p0.y = __float2half(v.y);
    __half2 p1; p1.x = __float2half(v.z); p1.y = __float2half(v.w);
    o[2*i]   = p0;
    o[2*i+1] = p1;
}

// W: [K, N] row-major -> T: [N, K] row-major fp16 (single rounding)
__global__ void transpose_conv_kernel(const float* __restrict__ W,
                                      __half* __restrict__ T, int K, int N)
{
    __shared__ float t[32][33];
    int n0 = blockIdx.x * 32, k0 = blockIdx.y * 32;
    int tx = threadIdx.x, ty = threadIdx.y;   // (32, 8)
    #pragma unroll
    for (int j = 0; j < 32; j += 8)
        t[ty + j][tx] = W[(size_t)(k0 + ty + j) * N + n0 + tx];
    __syncthreads();
    #pragma unroll
    for (int j = 0; j < 32; j += 8)
        T[(size_t)(n0 + ty + j) * K + k0 + tx] = __float2half(t[tx][ty + j]);
}

// In-place RoPE on fp16 qkv buffer ([b,t, q(0:2048)|k(2048:3072)|v]).
// Rotates 16 Q heads + 8 K heads; V untouched. total = NROW*24*64.
__global__ void rope_inplace_kernel(__half* __restrict__ qkv, int total)
{
    int idx = blockIdx.x * blockDim.x + threadIdx.x;
    if (idx >= total) return;
    int j  = idx & 63;
    int hh = (idx >> 6) % 24;             // 0..15 Q heads, 16..23 K heads
    int r  = idx / (64 * 24);             // global row
    int t  = r & (TT - 1);

    float e = (float)(2 * j) * (1.0f / 128.0f);
    float inv = 1.0f / powf(10000.0f, e);
    float f = (float)t * inv;
    float c = cosf(f), s = sinf(f);

    size_t base = (size_t)r * 4096 + ((hh < 16) ? hh * DD : 2048 + (hh - 16) * DD);
    float x1 = __half2float(qkv[base + j]);
    float x2 = __half2float(qkv[base + j + 64]);
    qkv[base + j]      = __float2half(x1 * c - x2 * s);
    qkv[base + j + 64] = __float2half(x2 * c + x1 * s);
}

// ============ HMMA fp16 1-pass GEMM (128x256 CTA, 3-stage pipeline) =========
#define GBM 128
#define GBN 256
#define GBK 32
#define GEMM_THREADS 256
#define ROW_BYTES 80
#define ARR_A (128 * ROW_BYTES)            // 10240
#define ARR_B (256 * ROW_BYTES)            // 20480
#define STAGE_BYTES (ARR_A + ARR_B)        // 30720
#define OFF_A 0
#define OFF_B ARR_A
#define GEMM_SMEM (3 * STAGE_BYTES)        // 92160

template<int HALF_OUT>
__global__ void __launch_bounds__(GEMM_THREADS, 1)
gemm_f16_kernel(const __half* __restrict__ A, const __half* __restrict__ B,
                float* __restrict__ C, __half* __restrict__ Ch,
                int M, int N, int K)
{
    extern __shared__ char smg[];
    const uint32_t sbase = smem_u32(smg);
    const int tid  = threadIdx.x;
    const int lane = tid & 31;
    const int wid  = tid >> 5;
    const int warp_m = wid >> 2;
    const int warp_n = wid & 3;
    const int m0 = blockIdx.y * GBM;
    const int n0 = blockIdx.x * GBN;

    auto load_stage = [&](int kt) {
        const uint32_t sdst = sbase + (kt % 3) * STAGE_BYTES;
        const int kofs = kt * GBK;
        #pragma unroll
        for (int i = 0; i < 6; i++) {
            int task = tid + GEMM_THREADS * i;   // 0..1535
            if (task < 512) {
                int row = task >> 2, c = task & 3;
                cp_async16(sdst + OFF_A + row*ROW_BYTES + c*16,
                           A + (size_t)(m0+row)*K + kofs + c*8);
            } else {
                int t2 = task - 512;             // 0..1023
                int row = t2 >> 2, c = t2 & 3;
                cp_async16(sdst + OFF_B + row*ROW_BYTES + c*16,
                           B + (size_t)(n0+row)*K + kofs + c*8);
            }
        }
        CP_COMMIT();
    };

    float acc[4][8][4];
    #pragma unroll
    for (int i = 0; i < 4; i++)
        #pragma unroll
        for (int j = 0; j < 8; j++)
            #pragma unroll
            for (int r = 0; r < 4; r++) acc[i][j][r] = 0.f;

    const int ktiles = K / GBK;

    load_stage(0);
    load_stage(1);

    const uint32_t a_row_b = (uint32_t)(warp_m * 64 + (lane & 15)) * ROW_BYTES
                           + ((lane >> 4) * 16);
    const uint32_t b_row_b = (uint32_t)(warp_n * 64 + ((lane >> 4) & 1) * 8 + (lane & 7)) * ROW_BYTES
                           + (((lane >> 3) & 1) * 16);

    for (int kt = 0; kt < ktiles; kt++) {
        if (kt + 2 < ktiles) { load_stage(kt + 2); CP_WAIT2(); }
        else if (kt + 1 < ktiles) { CP_WAIT1(); }
        else { CP_WAIT0(); }
        __syncthreads();

        const uint32_t st = sbase + (kt % 3) * STAGE_BYTES;
        #pragma unroll
        for (int s = 0; s < 2; s++) {
            const uint32_t koff = s * 32;
            uint32_t af[4][4];
            #pragma unroll
            for (int mt = 0; mt < 4; mt++)
                ldsm4(af[mt], st + OFF_A + a_row_b + mt * (16 * ROW_BYTES) + koff);
            uint32_t bf[4][4];
            #pragma unroll
            for (int np = 0; np < 4; np++)
                ldsm4(bf[np], st + OFF_B + b_row_b + np * (16 * ROW_BYTES) + koff);
            #pragma unroll
            for (int mt = 0; mt < 4; mt++)
                #pragma unroll
                for (int nt = 0; nt < 8; nt++)
                    mma_f16(acc[mt][nt], af[mt], &bf[nt >> 1][(nt & 1) * 2]);
        }
        __syncthreads();
    }

    #pragma unroll
    for (int mt = 0; mt < 4; mt++) {
        int r0 = m0 + warp_m * 64 + mt * 16 + (lane >> 2);
        #pragma unroll
        for (int nt = 0; nt < 8; nt++) {
            int cbase = n0 + warp_n * 64 + nt * 8 + (lane & 3) * 2;
            if (HALF_OUT) {
                __half2 h0; h0.x = __float2half(acc[mt][nt][0]); h0.y = __float2half(acc[mt][nt][1]);
                __half2 h1; h1.x = __float2half(acc[mt][nt][2]); h1.y = __float2half(acc[mt][nt][3]);
                *(__half2*)(Ch + (size_t)r0 * N + cbase)       = h0;
                *(__half2*)(Ch + (size_t)(r0 + 8) * N + cbase) = h1;
            } else {
                *(float2*)(C + (size_t)r0 * N + cbase)       = make_float2(acc[mt][nt][0], acc[mt][nt][1]);
                *(float2*)(C + (size_t)(r0 + 8) * N + cbase) = make_float2(acc[mt][nt][2], acc[mt][nt][3]);
            }
        }
    }
}

// == Flash attention: fp16 1-pass, Q frags hoisted, strided qkv input ========
#define ABQ 128
#define ABK 64
#define AROW 136
#define AQ_E 0
#define AKV0_E (ABQ*AROW)         // 17408 elems
#define KVBUF_E (2*ABK*AROW)      // 17408 elems (K + V)
#define AV_E (ABK*AROW)           // 8704: V offset within buffer
#define ASM_BYTES ((AKV0_E + 2*KVBUF_E)*2)   // 104448
#define ATTN_SCALE 0.08838834764831843f

__global__ void __launch_bounds__(256, 1)
attn_f16_kernel(const __half* __restrict__ QKV, __half* __restrict__ O)
{
    extern __shared__ __align__(1024) char smA[];
    const uint32_t sb = smem_u32(smA);

    const int tid  = threadIdx.x;
    const int lane = tid & 31;
    const int w    = tid >> 5;
    const int qi   = gridDim.x - 1 - blockIdx.x;   // big tiles first
    const int h    = blockIdx.y;
    const int b    = blockIdx.z;
    const int hk   = h >> 1;
    const int qbase = qi * ABQ;

    const __half* Qg = QKV + (size_t)(b*TT + qbase) * 4096 + h * DD;
    const __half* Kg = QKV + (size_t)(b*TT) * 4096 + 2048 + hk * DD;
    const __half* Vg = Kg + 1024;

    // ---- Q tile: 2048 chunks (128 rows x 16 chunks), strided rows ----
    #pragma unroll
    for (int i = 0; i < 8; i++) {
        int task = tid + 256 * i;        // 0..2047
        int row = task >> 4;             // 0..127
        int c   = task & 15;
        cp_async16(sb + 2 * (uint32_t)(AQ_E + row * AROW) + c * 16,
                   Qg + (size_t)row * 4096 + c * 8);
    }
    CP_COMMIT();

    auto load_kv = [&](int t, int buf) {
        const uint32_t base = sb + 2 * (uint32_t)(AKV0_E + buf * KVBUF_E);
        const int k0 = t * ABK;
        #pragma unroll
        for (int i = 0; i < 4; i++) {
            int task = tid + 256 * i;    // 0..1023
            int row = task >> 4, c = task & 15;
            cp_async16(base + 2 * (uint32_t)(row * AROW) + c * 16,
                       Kg + (size_t)(k0 + row) * 4096 + c * 8);
        }
        CP_COMMIT();
        #pragma unroll
        for (int i = 0; i < 4; i++) {
            int task = tid + 256 * i;
            int row = task >> 4, c = task & 15;
            cp_async16(base + 2 * (uint32_t)(AV_E + row * AROW) + c * 16,
                       Vg + (size_t)(k0 + row) * 4096 + c * 8);
        }
        CP_COMMIT();
    };

    load_kv(0, 0);

    CP_WAIT2();          // Q complete (K0,V0 may be in flight)
    __syncthreads();

    // ---- hoist Q fragments (reused every KV tile) ----
    const uint32_t qA = sb + 2*(uint32_t)(AQ_E + (w*16 + (lane & 15))*AROW) + (lane >> 4)*16;
    uint32_t qf[8][4];
    #pragma unroll
    for (int s = 0; s < 8; s++)
        ldsm4(qf[s], qA + s*32);

    float m0 = -INFINITY, m1 = -INFINITY, l0 = 0.f, l1 = 0.f;
    float oacc[16][4];
    #pragma unroll
    for (int j = 0; j < 16; j++)
        #pragma unroll
        for (int r = 0; r < 4; r++) oacc[j][r] = 0.f;

    const int krow  = ((lane >> 4) & 1)*8 + (lane & 7);
    const int kcolh = ((lane >> 3) & 1)*16;
    const int vrow  = ((lane >> 3) & 1)*8 + (lane & 7);
    const int vcolh = (lane >> 4)*16;

    const int ntiles = 2*qi + 2;
    const int qr0 = qbase + w*16 + (lane >> 2);

    for (int t = 0; t < ntiles; t++) {
        const int k0 = t * ABK;
        const int buf = t & 1;

        if (t + 1 < ntiles) { load_kv(t + 1, buf ^ 1); CP_WAIT3(); }
        else                { CP_WAIT1(); }
        __syncthreads();     // K_t visible to all warps

        const uint32_t kvb = sb + 2 * (uint32_t)(AKV0_E + buf * KVBUF_E);

        // ---- S = Q K^T (single pass) ----
        float sacc[8][4];
        #pragma unroll
        for (int j = 0; j < 8; j++)
            #pragma unroll
            for (int r = 0; r < 4; r++) sacc[j][r] = 0.f;

        #pragma unroll
        for (int s = 0; s < 8; s++) {
            #pragma unroll
            for (int jj = 0; jj < 4; jj++) {
                uint32_t kf[4];
                uint32_t ka = kvb + 2*(uint32_t)((16*jj + krow)*AROW) + s*32 + kcolh;
                ldsm4(kf, ka);
                mma_f16(sacc[2*jj],   qf[s], &kf[0]);
                mma_f16(sacc[2*jj+1], qf[s], &kf[2]);
            }
        }

        if (t + 1 < ntiles) CP_WAIT2(); else CP_WAIT0();   // V_t complete
        __syncthreads();

        // ---- online softmax ----
        const bool domask = (t >= ntiles - 2);
        float mx0 = -INFINITY, mx1 = -INFINITY;
        #pragma unroll
        for (int j = 0; j < 8; j++) {
            #pragma unroll
            for (int r = 0; r < 4; r++) {
                float sv = sacc[j][r] * ATTN_SCALE;
                if (domask) {
                    int col = k0 + 8*j + (lane & 3)*2 + (r & 1);
                    int qr  = qr0 + ((r >= 2) ? 8 : 0);
                    if (col > qr) sv = -INFINITY;
                }
                sacc[j][r] = sv;
                if (r < 2) mx0 = fmaxf(mx0, sv); else mx1 = fmaxf(mx1, sv);
            }
        }
        mx0 = fmaxf(mx0, __shfl_xor_sync(0xffffffffu, mx0, 1));
        mx0 = fmaxf(mx0, __shfl_xor_sync(0xffffffffu, mx0, 2));
        mx1 = fmaxf(mx1, __shfl_xor_sync(0xffffffffu, mx1, 1));
        mx1 = fmaxf(mx1, __shfl_xor_sync(0xffffffffu, mx1, 2));

        float m0n = fmaxf(m0, mx0), m1n = fmaxf(m1, mx1);
        float a0 = __expf(m0 - m0n), a1 = __expf(m1 - m1n);
        float ls0 = 0.f, ls1 = 0.f;
        #pragma unroll
        for (int j = 0; j < 8; j++) {
            float p0 = __expf(sacc[j][0] - m0n);
            float p1 = __expf(sacc[j][1] - m0n);
            float p2 = __expf(sacc[j][2] - m1n);
            float p3 = __expf(sacc[j][3] - m1n);
            sacc[j][0] = p0; sacc[j][1] = p1; sacc[j][2] = p2; sacc[j][3] = p3;
            ls0 += p0 + p1; ls1 += p2 + p3;
        }
        ls0 += __shfl_xor_sync(0xffffffffu, ls0, 1);
        ls0 += __shfl_xor_sync(0xffffffffu, ls0, 2);
        ls1 += __shfl_xor_sync(0xffffffffu, ls1, 1);
        ls1 += __shfl_xor_sync(0xffffffffu, ls1, 2);

        l0 = l0 * a0 + ls0;
        l1 = l1 * a1 + ls1;
        m0 = m0n; m1 = m1n;
        #pragma unroll
        for (int j = 0; j < 16; j++) {
            oacc[j][0] *= a0; oacc[j][1] *= a0;
            oacc[j][2] *= a1; oacc[j][3] *= a1;
        }

        // ---- O += P V (single pass) ----
        #pragma unroll
        for (int s2 = 0; s2 < 4; s2++) {
            uint32_t pp[4];
            pp[0] = pack_h2(sacc[2*s2][0],   sacc[2*s2][1]);
            pp[1] = pack_h2(sacc[2*s2][2],   sacc[2*s2][3]);
            pp[2] = pack_h2(sacc[2*s2+1][0], sacc[2*s2+1][1]);
            pp[3] = pack_h2(sacc[2*s2+1][2], sacc[2*s2+1][3]);
            uint32_t va = kvb + 2*(uint32_t)(AV_E + (16*s2 + vrow)*AROW) + vcolh;
            #pragma unroll
            for (int dd = 0; dd < 8; dd++) {
                uint32_t vf[4];
                ldsm4t(vf, va + dd*32);
                mma_f16(oacc[2*dd],   pp, &vf[0]);
                mma_f16(oacc[2*dd+1], pp, &vf[2]);
            }
        }
        __syncthreads();   // all reads of this buffer done before its next overwrite
    }

    // ---- epilogue: normalize + write single fp16 ([b,t,h*d] for Wp GEMM) ----
    float i0 = 1.f / l0, i1 = 1.f / l1;
    const int row0 = qbase + w*16 + (lane >> 2);
    const int col0 = (lane & 3)*2;
    #pragma unroll
    for (int j = 0; j < 16; j++) {
        int col = j*8 + col0;
        size_t base0 = ((size_t)(b*TT + row0)*HH + h)*DD + col;
        size_t base1 = base0 + (size_t)8*HH*DD;
        __half2 v0; v0.x = __float2half(oacc[j][0]*i0); v0.y = __float2half(oacc[j][1]*i0);
        __half2 v1; v1.x = __float2half(oacc[j][2]*i1); v1.y = __float2half(oacc[j][3]*i1);
        *(__half2*)(O + base0) = v0;
        *(__half2*)(O + base1) = v1;
    }
}

// ---------------- host entry -------------------------------------------------
extern "C" void kernel_launch(void* const* d_in, const int* in_sizes, int n_in,
                              void* d_out, int out_size)
{
    const float* x  = (const float*)d_in[0];
    const float* Wq = (const float*)d_in[1];
    const float* Wk = (const float*)d_in[2];
    const float* Wv = (const float*)d_in[3];
    const float* Wp = (const float*)d_in[4];
    float* out = (float*)d_out;

    __half *qkvh, *xf, *of, *wqkv, *wp;
    cudaGetSymbolAddress((void**)&qkvh, g_qkvh);
    cudaGetSymbolAddress((void**)&xf, g_xf);
    cudaGetSymbolAddress((void**)&of, g_of);
    cudaGetSymbolAddress((void**)&wqkv, g_wqkv);
    cudaGetSymbolAddress((void**)&wp, g_wp);

    cudaFuncSetAttribute(gemm_f16_kernel<0>, cudaFuncAttributeMaxDynamicSharedMemorySize, GEMM_SMEM);
    cudaFuncSetAttribute(gemm_f16_kernel<1>, cudaFuncAttributeMaxDynamicSharedMemorySize, GEMM_SMEM);
    cudaFuncSetAttribute(attn_f16_kernel, cudaFuncAttributeMaxDynamicSharedMemorySize, ASM_BYTES);

    // (1) convert x to fp16
    {
        int n4 = (NROW * CC) / 4;
        conv_h_kernel<<<(n4 + 255) / 256, 256>>>((const float4*)x, (__half2*)xf, n4);
    }
    // (2-5) transpose + convert all weights
    transpose_conv_kernel<<<dim3(CC/32, CC/32), dim3(32, 8)>>>(Wq, wqkv, CC, CC);
    transpose_conv_kernel<<<dim3((HKV*DD)/32, CC/32), dim3(32, 8)>>>(
        Wk, wqkv + (size_t)2048 * CC, CC, HKV*DD);
    transpose_conv_kernel<<<dim3((HKV*DD)/32, CC/32), dim3(32, 8)>>>(
        Wv, wqkv + (size_t)3072 * CC, CC, HKV*DD);
    transpose_conv_kernel<<<dim3(CC/32, CC/32), dim3(32, 8)>>>(Wp, wp, CC, CC);

    // (6) fused QKV projection -> fp16 qkv
    gemm_f16_kernel<1><<<dim3(4096/GBN, NROW/GBM), GEMM_THREADS, GEMM_SMEM>>>(
        xf, wqkv, nullptr, qkvh, NROW, 4096, CC);

    // (7) in-place RoPE on Q and K heads
    {
        int tot = NROW * 24 * 64;
        rope_inplace_kernel<<<(tot + 255) / 256, 256>>>(qkvh, tot);
    }

    // (8) attention (fp16 1-pass HMMA), reads strided qkv, fp16 O out
    attn_f16_kernel<<<dim3(TT / ABQ, HH, BB), 256, ASM_BYTES>>>(qkvh, of);

    // (9) output projection (fp32 out)
    gemm_f16_kernel<0><<<dim3(CC/GBN, NROW/GBM), GEMM_THREADS, GEMM_SMEM>>>(
        of, wp, out, nullptr, NROW, CC, CC);
}

// round 15
// speedup vs baseline: 4.5900x; 1.0229x over previous
#include <cuda_runtime.h>
#include <cuda_bf16.h>
#include <cuda_fp16.h>
#include <math.h>
#include <cstdint>

// Problem constants
#define BB 2
#define TT 2048
#define CC 2048
#define HH 16
#define HKV 8
#define DD 128
#define NROW (BB*TT)          // 4096

// ---------------- scratch (device globals; no allocation allowed) ----------
__device__ __align__(16) __half g_qkvh[(size_t)NROW * 4096]; // fp16: q|k|v cols
__device__ __align__(16) __half g_xf[(size_t)NROW * CC];
__device__ __align__(16) __half g_of[(size_t)NROW * CC];
__device__ __align__(16) __half g_wqkv[(size_t)4096 * CC];   // [Wq|Wk|Wv]^T
__device__ __align__(16) __half g_wp[(size_t)CC * CC];       // Wp^T

// ======================= low-level helpers ==================================
__device__ __forceinline__ uint32_t smem_u32(const void* p) {
    uint32_t a;
    asm("{ .reg .u64 t; cvta.to.shared.u64 t, %1; cvt.u32.u64 %0, t; }"
        : "=r"(a) : "l"(p));
    return a;
}
__device__ __forceinline__ void ldsm4(uint32_t* r, uint32_t addr) {
    asm volatile("ldmatrix.sync.aligned.m8n8.x4.shared.b16 {%0,%1,%2,%3}, [%4];"
        : "=r"(r[0]), "=r"(r[1]), "=r"(r[2]), "=r"(r[3]) : "r"(addr));
}
__device__ __forceinline__ void ldsm4t(uint32_t* r, uint32_t addr) {
    asm volatile("ldmatrix.sync.aligned.m8n8.x4.trans.shared.b16 {%0,%1,%2,%3}, [%4];"
        : "=r"(r[0]), "=r"(r[1]), "=r"(r[2]), "=r"(r[3]) : "r"(addr));
}
__device__ __forceinline__ void mma_f16(float* d, const uint32_t* a, const uint32_t* b) {
    asm volatile(
        "mma.sync.aligned.m16n8k16.row.col.f32.f16.f16.f32 "
        "{%0,%1,%2,%3}, {%4,%5,%6,%7}, {%8,%9}, {%0,%1,%2,%3};"
        : "+f"(d[0]), "+f"(d[1]), "+f"(d[2]), "+f"(d[3])
        : "r"(a[0]), "r"(a[1]), "r"(a[2]), "r"(a[3]), "r"(b[0]), "r"(b[1]));
}
__device__ __forceinline__ void cp_async16(uint32_t dst, const void* src) {
    asm volatile("cp.async.cg.shared.global [%0], [%1], 16;\n" :: "r"(dst), "l"(src));
}
#define CP_COMMIT() asm volatile("cp.async.commit_group;\n" ::: "memory")
#define CP_WAIT3()  asm volatile("cp.async.wait_group 3;\n" ::: "memory")
#define CP_WAIT2()  asm volatile("cp.async.wait_group 2;\n" ::: "memory")
#define CP_WAIT1()  asm volatile("cp.async.wait_group 1;\n" ::: "memory")
#define CP_WAIT0()  asm volatile("cp.async.wait_group 0;\n" ::: "memory")

__device__ __forceinline__ uint32_t pack_h2(float a, float b) {
    __half2 H; H.x = __float2half(a); H.y = __float2half(b);
    return *(uint32_t*)&H;
}

// ======================= conversion kernels =================================
// fp32 -> fp16 (single rounding)
__global__ void conv_h_kernel(const float4* __restrict__ in,
                              __half2* __restrict__ o, int n4)
{
    int i = blockIdx.x * blockDim.x + threadIdx.x;
    if (i >= n4) return;
    float4 v = in[i];
    __half2 p0; p0.x = __float2half(v.x); p0.y = __float2half(v.y);
    __half2 p1; p1.x = __float2half(v.z); p1.y = __float2half(v.w);
    o[2*i]   = p0;
    o[2*i+1] = p1;
}

// All 4 weight transposes fused into one launch.
// segments (32x32 blocks): [0,4096) Wq, [4096,6144) Wk, [6144,8192) Wv,
// [8192,12288) Wp.
__global__ void prep_weights_kernel(const float* __restrict__ Wq,
                                    const float* __restrict__ Wk,
                                    const float* __restrict__ Wv,
                                    const float* __restrict__ Wp,
                                    __half* __restrict__ wqkv,
                                    __half* __restrict__ wp)
{
    __shared__ float t[32][33];
    int bid = blockIdx.x;
    const float* W; __half* T; int K, N, lb;
    if (bid < 4096)      { W = Wq; T = wqkv;                        K = CC; N = CC;     lb = bid; }
    else if (bid < 6144) { W = Wk; T = wqkv + (size_t)2048 * CC;    K = CC; N = HKV*DD; lb = bid - 4096; }
    else if (bid < 8192) { W = Wv; T = wqkv + (size_t)3072 * CC;    K = CC; N = HKV*DD; lb = bid - 6144; }
    else                 { W = Wp; T = wp;                          K = CC; N = CC;     lb = bid - 8192; }
    int nbn = N / 32;
    int n0 = (lb % nbn) * 32, k0 = (lb / nbn) * 32;
    int tx = threadIdx.x, ty = threadIdx.y;   // (32, 8)
    #pragma unroll
    for (int j = 0; j < 32; j += 8)
        t[ty + j][tx] = W[(size_t)(k0 + ty + j) * N + n0 + tx];
    __syncthreads();
    #pragma unroll
    for (int j = 0; j < 32; j += 8)
        T[(size_t)(n0 + ty + j) * K + k0 + tx] = __float2half(t[tx][ty + j]);
}

// In-place RoPE on fp16 qkv buffer ([b,t, q(0:2048)|k(2048:3072)|v]).
__global__ void rope_inplace_kernel(__half* __restrict__ qkv, int total)
{
    int idx = blockIdx.x * blockDim.x + threadIdx.x;
    if (idx >= total) return;
    int j  = idx & 63;
    int hh = (idx >> 6) % 24;             // 0..15 Q heads, 16..23 K heads
    int r  = idx / (64 * 24);             // global row
    int t  = r & (TT - 1);

    float e = (float)(2 * j) * (1.0f / 128.0f);
    float inv = 1.0f / powf(10000.0f, e);
    float f = (float)t * inv;
    float c = cosf(f), s = sinf(f);

    size_t base = (size_t)r * 4096 + ((hh < 16) ? hh * DD : 2048 + (hh - 16) * DD);
    float x1 = __half2float(qkv[base + j]);
    float x2 = __half2float(qkv[base + j + 64]);
    qkv[base + j]      = __float2half(x1 * c - x2 * s);
    qkv[base + j + 64] = __float2half(x2 * c + x1 * s);
}

// ============ HMMA fp16 1-pass GEMM (128x256 CTA, 3-stage pipeline) =========
#define GBM 128
#define GBN 256
#define GBK 32
#define GEMM_THREADS 256
#define ROW_BYTES 80
#define ARR_A (128 * ROW_BYTES)            // 10240
#define ARR_B (256 * ROW_BYTES)            // 20480
#define STAGE_BYTES (ARR_A + ARR_B)        // 30720
#define OFF_A 0
#define OFF_B ARR_A
#define GEMM_SMEM (3 * STAGE_BYTES)        // 92160

template<int HALF_OUT>
__global__ void __launch_bounds__(GEMM_THREADS, 1)
gemm_f16_kernel(const __half* __restrict__ A, const __half* __restrict__ B,
                float* __restrict__ C, __half* __restrict__ Ch,
                int M, int N, int K)
{
    extern __shared__ char smg[];
    const uint32_t sbase = smem_u32(smg);
    const int tid  = threadIdx.x;
    const int lane = tid & 31;
    const int wid  = tid >> 5;
    const int warp_m = wid >> 2;
    const int warp_n = wid & 3;
    const int m0 = blockIdx.y * GBM;
    const int n0 = blockIdx.x * GBN;

    auto load_stage = [&](int kt) {
        const uint32_t sdst = sbase + (kt % 3) * STAGE_BYTES;
        const int kofs = kt * GBK;
        #pragma unroll
        for (int i = 0; i < 6; i++) {
            int task = tid + GEMM_THREADS * i;   // 0..1535
            if (task < 512) {
                int row = task >> 2, c = task & 3;
                cp_async16(sdst + OFF_A + row*ROW_BYTES + c*16,
                           A + (size_t)(m0+row)*K + kofs + c*8);
            } else {
                int t2 = task - 512;             // 0..1023
                int row = t2 >> 2, c = t2 & 3;
                cp_async16(sdst + OFF_B + row*ROW_BYTES + c*16,
                           B + (size_t)(n0+row)*K + kofs + c*8);
            }
        }
        CP_COMMIT();
    };

    float acc[4][8][4];
    #pragma unroll
    for (int i = 0; i < 4; i++)
        #pragma unroll
        for (int j = 0; j < 8; j++)
            #pragma unroll
            for (int r = 0; r < 4; r++) acc[i][j][r] = 0.f;

    const int ktiles = K / GBK;

    load_stage(0);
    load_stage(1);

    const uint32_t a_row_b = (uint32_t)(warp_m * 64 + (lane & 15)) * ROW_BYTES
                           + ((lane >> 4) * 16);
    const uint32_t b_row_b = (uint32_t)(warp_n * 64 + ((lane >> 4) & 1) * 8 + (lane & 7)) * ROW_BYTES
                           + (((lane >> 3) & 1) * 16);

    for (int kt = 0; kt < ktiles; kt++) {
        if (kt + 2 < ktiles) { load_stage(kt + 2); CP_WAIT2(); }
        else if (kt + 1 < ktiles) { CP_WAIT1(); }
        else { CP_WAIT0(); }
        __syncthreads();

        const uint32_t st = sbase + (kt % 3) * STAGE_BYTES;
        #pragma unroll
        for (int s = 0; s < 2; s++) {
            const uint32_t koff = s * 32;
            uint32_t af[4][4];
            #pragma unroll
            for (int mt = 0; mt < 4; mt++)
                ldsm4(af[mt], st + OFF_A + a_row_b + mt * (16 * ROW_BYTES) + koff);
            uint32_t bf[4][4];
            #pragma unroll
            for (int np = 0; np < 4; np++)
                ldsm4(bf[np], st + OFF_B + b_row_b + np * (16 * ROW_BYTES) + koff);
            #pragma unroll
            for (int mt = 0; mt < 4; mt++)
                #pragma unroll
                for (int nt = 0; nt < 8; nt++)
                    mma_f16(acc[mt][nt], af[mt], &bf[nt >> 1][(nt & 1) * 2]);
        }
        __syncthreads();
    }

    #pragma unroll
    for (int mt = 0; mt < 4; mt++) {
        int r0 = m0 + warp_m * 64 + mt * 16 + (lane >> 2);
        #pragma unroll
        for (int nt = 0; nt < 8; nt++) {
            int cbase = n0 + warp_n * 64 + nt * 8 + (lane & 3) * 2;
            if (HALF_OUT) {
                __half2 h0; h0.x = __float2half(acc[mt][nt][0]); h0.y = __float2half(acc[mt][nt][1]);
                __half2 h1; h1.x = __float2half(acc[mt][nt][2]); h1.y = __float2half(acc[mt][nt][3]);
                *(__half2*)(Ch + (size_t)r0 * N + cbase)       = h0;
                *(__half2*)(Ch + (size_t)(r0 + 8) * N + cbase) = h1;
            } else {
                *(float2*)(C + (size_t)r0 * N + cbase)       = make_float2(acc[mt][nt][0], acc[mt][nt][1]);
                *(float2*)(C + (size_t)(r0 + 8) * N + cbase) = make_float2(acc[mt][nt][2], acc[mt][nt][3]);
            }
        }
    }
}

// == Flash attention: fp16 1-pass, BK=128, Q frags hoisted, double-buffered ==
#define ABQ 128
#define ABK 128
#define AROW 136
#define AQ_E 0
#define AKV0_E (ABQ*AROW)         // 17408 elems (after Q)
#define AV_E (ABK*AROW)           // V offset within a KV buffer
#define KVBUF_E (2*ABK*AROW)      // 34816 elems (K + V)
#define ASM_BYTES ((AKV0_E + 2*KVBUF_E)*2)   // 174080
// scale * log2(e): softmax computed in base-2 domain
#define ATTN_SCALE2 0.1275258291089229f

__global__ void __launch_bounds__(256, 1)
attn_f16_kernel(const __half* __restrict__ QKV, __half* __restrict__ O)
{
    extern __shared__ __align__(1024) char smA[];
    const uint32_t sb = smem_u32(smA);

    const int tid  = threadIdx.x;
    const int lane = tid & 31;
    const int w    = tid >> 5;
    const int qi   = gridDim.x - 1 - blockIdx.x;   // big tiles first
    const int h    = blockIdx.y;
    const int b    = blockIdx.z;
    const int hk   = h >> 1;
    const int qbase = qi * ABQ;

    const __half* Qg = QKV + (size_t)(b*TT + qbase) * 4096 + h * DD;
    const __half* Kg = QKV + (size_t)(b*TT) * 4096 + 2048 + hk * DD;
    const __half* Vg = Kg + 1024;

    // ---- Q tile: 2048 chunks (128 rows x 16 chunks), strided rows ----
    #pragma unroll
    for (int i = 0; i < 8; i++) {
        int task = tid + 256 * i;        // 0..2047
        int row = task >> 4;             // 0..127
        int c   = task & 15;
        cp_async16(sb + 2 * (uint32_t)(AQ_E + row * AROW) + c * 16,
                   Qg + (size_t)row * 4096 + c * 8);
    }
    CP_COMMIT();

    auto load_kv = [&](int t, int buf) {
        const uint32_t base = sb + 2 * (uint32_t)(AKV0_E + buf * KVBUF_E);
        const int k0 = t * ABK;
        #pragma unroll
        for (int i = 0; i < 8; i++) {
            int task = tid + 256 * i;    // 0..2047
            int row = task >> 4, c = task & 15;
            cp_async16(base + 2 * (uint32_t)(row * AROW) + c * 16,
                       Kg + (size_t)(k0 + row) * 4096 + c * 8);
        }
        CP_COMMIT();
        #pragma unroll
        for (int i = 0; i < 8; i++) {
            int task = tid + 256 * i;
            int row = task >> 4, c = task & 15;
            cp_async16(base + 2 * (uint32_t)(AV_E + row * AROW) + c * 16,
                       Vg + (size_t)(k0 + row) * 4096 + c * 8);
        }
        CP_COMMIT();
    };

    load_kv(0, 0);

    CP_WAIT2();          // Q complete (K0,V0 may be in flight)
    __syncthreads();

    // ---- hoist Q fragments (reused every KV tile) ----
    const uint32_t qA = sb + 2*(uint32_t)(AQ_E + (w*16 + (lane & 15))*AROW) + (lane >> 4)*16;
    uint32_t qf[8][4];
    #pragma unroll
    for (int s = 0; s < 8; s++)
        ldsm4(qf[s], qA + s*32);

    float m0 = -INFINITY, m1 = -INFINITY, l0 = 0.f, l1 = 0.f;
    float oacc[16][4];
    #pragma unroll
    for (int j = 0; j < 16; j++)
        #pragma unroll
        for (int r = 0; r < 4; r++) oacc[j][r] = 0.f;

    const int krow  = ((lane >> 4) & 1)*8 + (lane & 7);
    const int kcolh = ((lane >> 3) & 1)*16;
    const int vrow  = ((lane >> 3) & 1)*8 + (lane & 7);
    const int vcolh = (lane >> 4)*16;

    const int ntiles = qi + 1;
    const int qr0 = qbase + w*16 + (lane >> 2);

    for (int t = 0; t < ntiles; t++) {
        const int k0 = t * ABK;
        const int buf = t & 1;

        if (t + 1 < ntiles) { load_kv(t + 1, buf ^ 1); CP_WAIT3(); }
        else                { CP_WAIT1(); }
        __syncthreads();     // K_t visible to all warps

        const uint32_t kvb = sb + 2 * (uint32_t)(AKV0_E + buf * KVBUF_E);

        // ---- S = Q K^T (single pass, 16 n-subtiles) ----
        float sacc[16][4];
        #pragma unroll
        for (int j = 0; j < 16; j++)
            #pragma unroll
            for (int r = 0; r < 4; r++) sacc[j][r] = 0.f;

        #pragma unroll
        for (int s = 0; s < 8; s++) {
            #pragma unroll
            for (int jj = 0; jj < 8; jj++) {
                uint32_t kf[4];
                uint32_t ka = kvb + 2*(uint32_t)((16*jj + krow)*AROW) + s*32 + kcolh;
                ldsm4(kf, ka);
                mma_f16(sacc[2*jj],   qf[s], &kf[0]);
                mma_f16(sacc[2*jj+1], qf[s], &kf[2]);
            }
        }

        if (t + 1 < ntiles) CP_WAIT2(); else CP_WAIT0();   // V_t complete
        __syncthreads();

        // ---- online softmax (base-2 domain) ----
        const bool domask = (t == ntiles - 1);
        float mx0 = -INFINITY, mx1 = -INFINITY;
        #pragma unroll
        for (int j = 0; j < 16; j++) {
            #pragma unroll
            for (int r = 0; r < 4; r++) {
                float sv = sacc[j][r] * ATTN_SCALE2;
                if (domask) {
                    int col = k0 + 8*j + (lane & 3)*2 + (r & 1);
                    int qr  = qr0 + ((r >= 2) ? 8 : 0);
                    if (col > qr) sv = -INFINITY;
                }
                sacc[j][r] = sv;
                if (r < 2) mx0 = fmaxf(mx0, sv); else mx1 = fmaxf(mx1, sv);
            }
        }
        mx0 = fmaxf(mx0, __shfl_xor_sync(0xffffffffu, mx0, 1));
        mx0 = fmaxf(mx0, __shfl_xor_sync(0xffffffffu, mx0, 2));
        mx1 = fmaxf(mx1, __shfl_xor_sync(0xffffffffu, mx1, 1));
        mx1 = fmaxf(mx1, __shfl_xor_sync(0xffffffffu, mx1, 2));

        float m0n = fmaxf(m0, mx0), m1n = fmaxf(m1, mx1);
        float a0 = exp2f(m0 - m0n), a1 = exp2f(m1 - m1n);
        float ls0 = 0.f, ls1 = 0.f;
        #pragma unroll
        for (int j = 0; j < 16; j++) {
            float p0 = exp2f(sacc[j][0] - m0n);
            float p1 = exp2f(sacc[j][1] - m0n);
            float p2 = exp2f(sacc[j][2] - m1n);
            float p3 = exp2f(sacc[j][3] - m1n);
            sacc[j][0] = p0; sacc[j][1] = p1; sacc[j][2] = p2; sacc[j][3] = p3;
            ls0 += p0 + p1; ls1 += p2 + p3;
        }
        ls0 += __shfl_xor_sync(0xffffffffu, ls0, 1);
        ls0 += __shfl_xor_sync(0xffffffffu, ls0, 2);
        ls1 += __shfl_xor_sync(0xffffffffu, ls1, 1);
        ls1 += __shfl_xor_sync(0xffffffffu, ls1, 2);

        l0 = l0 * a0 + ls0;
        l1 = l1 * a1 + ls1;
        m0 = m0n; m1 = m1n;
        #pragma unroll
        for (int j = 0; j < 16; j++) {
            oacc[j][0] *= a0; oacc[j][1] *= a0;
            oacc[j][2] *= a1; oacc[j][3] *= a1;
        }

        // ---- O += P V (single pass, 8 k16 steps) ----
        #pragma unroll
        for (int s2 = 0; s2 < 8; s2++) {
            uint32_t pp[4];
            pp[0] = pack_h2(sacc[2*s2][0],   sacc[2*s2][1]);
            pp[1] = pack_h2(sacc[2*s2][2],   sacc[2*s2][3]);
            pp[2] = pack_h2(sacc[2*s2+1][0], sacc[2*s2+1][1]);
            pp[3] = pack_h2(sacc[2*s2+1][2], sacc[2*s2+1][3]);
            uint32_t va = kvb + 2*(uint32_t)(AV_E + (16*s2 + vrow)*AROW) + vcolh;
            #pragma unroll
            for (int dd = 0; dd < 8; dd++) {
                uint32_t vf[4];
                ldsm4t(vf, va + dd*32);
                mma_f16(oacc[2*dd],   pp, &vf[0]);
                mma_f16(oacc[2*dd+1], pp, &vf[2]);
            }
        }
        __syncthreads();   // all reads of this buffer done before its next overwrite
    }

    // ---- epilogue: normalize + write single fp16 ([b,t,h*d] for Wp GEMM) ----
    float i0 = 1.f / l0, i1 = 1.f / l1;
    const int row0 = qbase + w*16 + (lane >> 2);
    const int col0 = (lane & 3)*2;
    #pragma unroll
    for (int j = 0; j < 16; j++) {
        int col = j*8 + col0;
        size_t base0 = ((size_t)(b*TT + row0)*HH + h)*DD + col;
        size_t base1 = base0 + (size_t)8*HH*DD;
        __half2 v0; v0.x = __float2half(oacc[j][0]*i0); v0.y = __float2half(oacc[j][1]*i0);
        __half2 v1; v1.x = __float2half(oacc[j][2]*i1); v1.y = __float2half(oacc[j][3]*i1);
        *(__half2*)(O + base0) = v0;
        *(__half2*)(O + base1) = v1;
    }
}

// ---------------- host entry -------------------------------------------------
extern "C" void kernel_launch(void* const* d_in, const int* in_sizes, int n_in,
                              void* d_out, int out_size)
{
    const float* x  = (const float*)d_in[0];
    const float* Wq = (const float*)d_in[1];
    const float* Wk = (const float*)d_in[2];
    const float* Wv = (const float*)d_in[3];
    const float* Wp = (const float*)d_in[4];
    float* out = (float*)d_out;

    __half *qkvh, *xf, *of, *wqkv, *wp;
    cudaGetSymbolAddress((void**)&qkvh, g_qkvh);
    cudaGetSymbolAddress((void**)&xf, g_xf);
    cudaGetSymbolAddress((void**)&of, g_of);
    cudaGetSymbolAddress((void**)&wqkv, g_wqkv);
    cudaGetSymbolAddress((void**)&wp, g_wp);

    cudaFuncSetAttribute(gemm_f16_kernel<0>, cudaFuncAttributeMaxDynamicSharedMemorySize, GEMM_SMEM);
    cudaFuncSetAttribute(gemm_f16_kernel<1>, cudaFuncAttributeMaxDynamicSharedMemorySize, GEMM_SMEM);
    cudaFuncSetAttribute(attn_f16_kernel, cudaFuncAttributeMaxDynamicSharedMemorySize, ASM_BYTES);

    // (1) convert x to fp16
    {
        int n4 = (NROW * CC) / 4;
        conv_h_kernel<<<(n4 + 255) / 256, 256>>>((const float4*)x, (__half2*)xf, n4);
    }
    // (2) all weight transposes in ONE launch
    prep_weights_kernel<<<12288, dim3(32, 8)>>>(Wq, Wk, Wv, Wp, wqkv, wp);

    // (3) fused QKV projection -> fp16 qkv
    gemm_f16_kernel<1><<<dim3(4096/GBN, NROW/GBM), GEMM_THREADS, GEMM_SMEM>>>(
        xf, wqkv, nullptr, qkvh, NROW, 4096, CC);

    // (4) in-place RoPE on Q and K heads
    {
        int tot = NROW * 24 * 64;
        rope_inplace_kernel<<<(tot + 255) / 256, 256>>>(qkvh, tot);
    }

    // (5) attention (fp16 1-pass HMMA, BK=128), fp16 O out
    attn_f16_kernel<<<dim3(TT / ABQ, HH, BB), 256, ASM_BYTES>>>(qkvh, of);

    // (6) output projection (fp32 out)
    gemm_f16_kernel<0><<<dim3(CC/GBN, NROW/GBM), GEMM_THREADS, GEMM_SMEM>>>(
        of, wp, out, nullptr, NROW, CC, CC);
}

// round 17
// speedup vs baseline: 4.7096x; 1.0260x over previous
#include <cuda_runtime.h>
#include <cuda_bf16.h>
#include <cuda_fp16.h>
#include <math.h>
#include <cstdint>

// Problem constants
#define BB 2
#define TT 2048
#define CC 2048
#define HH 16
#define HKV 8
#define DD 128
#define NROW (BB*TT)          // 4096

// ---------------- scratch (device globals; no allocation allowed) ----------
__device__ __align__(16) __half g_qkvh[(size_t)NROW * 4096]; // fp16: q|k|v cols
__device__ __align__(16) __half g_xf[(size_t)NROW * CC];
__device__ __align__(16) __half g_of[(size_t)NROW * CC];
__device__ __align__(16) __half g_wqkv[(size_t)4096 * CC];   // [Wq|Wk|Wv]^T
__device__ __align__(16) __half g_wp[(size_t)CC * CC];       // Wp^T

// ======================= low-level helpers ==================================
__device__ __forceinline__ uint32_t smem_u32(const void* p) {
    uint32_t a;
    asm("{ .reg .u64 t; cvta.to.shared.u64 t, %1; cvt.u32.u64 %0, t; }"
        : "=r"(a) : "l"(p));
    return a;
}
__device__ __forceinline__ void ldsm4(uint32_t* r, uint32_t addr) {
    asm volatile("ldmatrix.sync.aligned.m8n8.x4.shared.b16 {%0,%1,%2,%3}, [%4];"
        : "=r"(r[0]), "=r"(r[1]), "=r"(r[2]), "=r"(r[3]) : "r"(addr));
}
__device__ __forceinline__ void ldsm4t(uint32_t* r, uint32_t addr) {
    asm volatile("ldmatrix.sync.aligned.m8n8.x4.trans.shared.b16 {%0,%1,%2,%3}, [%4];"
        : "=r"(r[0]), "=r"(r[1]), "=r"(r[2]), "=r"(r[3]) : "r"(addr));
}
__device__ __forceinline__ void mma_f16(float* d, const uint32_t* a, const uint32_t* b) {
    asm volatile(
        "mma.sync.aligned.m16n8k16.row.col.f32.f16.f16.f32 "
        "{%0,%1,%2,%3}, {%4,%5,%6,%7}, {%8,%9}, {%0,%1,%2,%3};"
        : "+f"(d[0]), "+f"(d[1]), "+f"(d[2]), "+f"(d[3])
        : "r"(a[0]), "r"(a[1]), "r"(a[2]), "r"(a[3]), "r"(b[0]), "r"(b[1]));
}
__device__ __forceinline__ void cp_async16(uint32_t dst, const void* src) {
    asm volatile("cp.async.cg.shared.global [%0], [%1], 16;\n" :: "r"(dst), "l"(src));
}
#define CP_COMMIT() asm volatile("cp.async.commit_group;\n" ::: "memory")
#define CP_WAIT3()  asm volatile("cp.async.wait_group 3;\n" ::: "memory")
#define CP_WAIT2()  asm volatile("cp.async.wait_group 2;\n" ::: "memory")
#define CP_WAIT1()  asm volatile("cp.async.wait_group 1;\n" ::: "memory")
#define CP_WAIT0()  asm volatile("cp.async.wait_group 0;\n" ::: "memory")

__device__ __forceinline__ uint32_t pack_h2(float a, float b) {
    __half2 H; H.x = __float2half(a); H.y = __float2half(b);
    return *(uint32_t*)&H;
}

// ======================= prep (weights + x) in one launch ====================
// segments (blocks of 256 threads):
//  [0,4096)      Wq 32x32 transpose tiles
//  [4096,6144)   Wk
//  [6144,8192)   Wv
//  [8192,12288)  Wp
//  [12288,16384) x fp32->fp16 (512 float4 per block, 2 per thread)
__global__ void prep_kernel(const float* __restrict__ Wq,
                            const float* __restrict__ Wk,
                            const float* __restrict__ Wv,
                            const float* __restrict__ Wp,
                            const float* __restrict__ x,
                            __half* __restrict__ wqkv,
                            __half* __restrict__ wp,
                            __half* __restrict__ xf)
{
    int bid = blockIdx.x;
    int tx = threadIdx.x, ty = threadIdx.y;   // (32, 8)
    if (bid >= 12288) {
        int tid = ty * 32 + tx;                       // 0..255
        int b0 = (bid - 12288) * 512 + tid;           // float4 index
        #pragma unroll
        for (int rep = 0; rep < 2; rep++) {
            int base = b0 + rep * 256;
            float4 v = ((const float4*)x)[base];
            __half2 p0; p0.x = __float2half(v.x); p0.y = __float2half(v.y);
            __half2 p1; p1.x = __float2half(v.z); p1.y = __float2half(v.w);
            ((__half2*)xf)[2*base]   = p0;
            ((__half2*)xf)[2*base+1] = p1;
        }
        return;
    }
    __shared__ float t[32][33];
    const float* W; __half* T; int K, N, lb;
    if (bid < 4096)      { W = Wq; T = wqkv;                        K = CC; N = CC;     lb = bid; }
    else if (bid < 6144) { W = Wk; T = wqkv + (size_t)2048 * CC;    K = CC; N = HKV*DD; lb = bid - 4096; }
    else if (bid < 8192) { W = Wv; T = wqkv + (size_t)3072 * CC;    K = CC; N = HKV*DD; lb = bid - 6144; }
    else                 { W = Wp; T = wp;                          K = CC; N = CC;     lb = bid - 8192; }
    int nbn = N / 32;
    int n0 = (lb % nbn) * 32, k0 = (lb / nbn) * 32;
    #pragma unroll
    for (int j = 0; j < 32; j += 8)
        t[ty + j][tx] = W[(size_t)(k0 + ty + j) * N + n0 + tx];
    __syncthreads();
    #pragma unroll
    for (int j = 0; j < 32; j += 8)
        T[(size_t)(n0 + ty + j) * K + k0 + tx] = __float2half(t[tx][ty + j]);
}

// In-place RoPE on fp16 qkv buffer ([b,t, q(0:2048)|k(2048:3072)|v]).
// exp2f-based inv_freq + sincosf (shared range reduction).
#define NEG_LOG2_1E4_OVER64 (-0.2076205061795983f)   // -log2(10000)/64
__global__ void rope_inplace_kernel(__half* __restrict__ qkv, int total)
{
    int idx = blockIdx.x * blockDim.x + threadIdx.x;
    if (idx >= total) return;
    int j  = idx & 63;
    int hh = (idx >> 6) % 24;             // 0..15 Q heads, 16..23 K heads
    int r  = idx / (64 * 24);             // global row
    int t  = r & (TT - 1);

    float inv = exp2f((float)j * NEG_LOG2_1E4_OVER64);   // 10000^(-2j/128)
    float f = (float)t * inv;
    float s, c;
    sincosf(f, &s, &c);

    size_t base = (size_t)r * 4096 + ((hh < 16) ? hh * DD : 2048 + (hh - 16) * DD);
    float x1 = __half2float(qkv[base + j]);
    float x2 = __half2float(qkv[base + j + 64]);
    qkv[base + j]      = __float2half(x1 * c - x2 * s);
    qkv[base + j + 64] = __float2half(x2 * c + x1 * s);
}

// ============ HMMA fp16 1-pass GEMM (128x256 CTA, 3-stage pipeline) =========
#define GBM 128
#define GBN 256
#define GBK 32
#define GEMM_THREADS 256
#define ROW_BYTES 80
#define ARR_A (128 * ROW_BYTES)            // 10240
#define ARR_B (256 * ROW_BYTES)            // 20480
#define STAGE_BYTES (ARR_A + ARR_B)        // 30720
#define OFF_A 0
#define OFF_B ARR_A
#define GEMM_SMEM (3 * STAGE_BYTES)        // 92160

template<int HALF_OUT>
__global__ void __launch_bounds__(GEMM_THREADS, 1)
gemm_f16_kernel(const __half* __restrict__ A, const __half* __restrict__ B,
                float* __restrict__ C, __half* __restrict__ Ch,
                int M, int N, int K)
{
    extern __shared__ char smg[];
    const uint32_t sbase = smem_u32(smg);
    const int tid  = threadIdx.x;
    const int lane = tid & 31;
    const int wid  = tid >> 5;
    const int warp_m = wid >> 2;
    const int warp_n = wid & 3;
    const int m0 = blockIdx.y * GBM;
    const int n0 = blockIdx.x * GBN;

    auto load_stage = [&](int kt) {
        const uint32_t sdst = sbase + (kt % 3) * STAGE_BYTES;
        const int kofs = kt * GBK;
        #pragma unroll
        for (int i = 0; i < 6; i++) {
            int task = tid + GEMM_THREADS * i;   // 0..1535
            if (task < 512) {
                int row = task >> 2, c = task & 3;
                cp_async16(sdst + OFF_A + row*ROW_BYTES + c*16,
                           A + (size_t)(m0+row)*K + kofs + c*8);
            } else {
                int t2 = task - 512;             // 0..1023
                int row = t2 >> 2, c = t2 & 3;
                cp_async16(sdst + OFF_B + row*ROW_BYTES + c*16,
                           B + (size_t)(n0+row)*K + kofs + c*8);
            }
        }
        CP_COMMIT();
    };

    float acc[4][8][4];
    #pragma unroll
    for (int i = 0; i < 4; i++)
        #pragma unroll
        for (int j = 0; j < 8; j++)
            #pragma unroll
            for (int r = 0; r < 4; r++) acc[i][j][r] = 0.f;

    const int ktiles = K / GBK;

    load_stage(0);
    load_stage(1);

    const uint32_t a_row_b = (uint32_t)(warp_m * 64 + (lane & 15)) * ROW_BYTES
                           + ((lane >> 4) * 16);
    const uint32_t b_row_b = (uint32_t)(warp_n * 64 + ((lane >> 4) & 1) * 8 + (lane & 7)) * ROW_BYTES
                           + (((lane >> 3) & 1) * 16);

    for (int kt = 0; kt < ktiles; kt++) {
        if (kt + 2 < ktiles) { load_stage(kt + 2); CP_WAIT2(); }
        else if (kt + 1 < ktiles) { CP_WAIT1(); }
        else { CP_WAIT0(); }
        __syncthreads();

        const uint32_t st = sbase + (kt % 3) * STAGE_BYTES;
        #pragma unroll
        for (int s = 0; s < 2; s++) {
            const uint32_t koff = s * 32;
            uint32_t af[4][4];
            #pragma unroll
            for (int mt = 0; mt < 4; mt++)
                ldsm4(af[mt], st + OFF_A + a_row_b + mt * (16 * ROW_BYTES) + koff);
            uint32_t bf[4][4];
            #pragma unroll
            for (int np = 0; np < 4; np++)
                ldsm4(bf[np], st + OFF_B + b_row_b + np * (16 * ROW_BYTES) + koff);
            #pragma unroll
            for (int mt = 0; mt < 4; mt++)
                #pragma unroll
                for (int nt = 0; nt < 8; nt++)
                    mma_f16(acc[mt][nt], af[mt], &bf[nt >> 1][(nt & 1) * 2]);
        }
        __syncthreads();
    }

    #pragma unroll
    for (int mt = 0; mt < 4; mt++) {
        int r0 = m0 + warp_m * 64 + mt * 16 + (lane >> 2);
        #pragma unroll
        for (int nt = 0; nt < 8; nt++) {
            int cbase = n0 + warp_n * 64 + nt * 8 + (lane & 3) * 2;
            if (HALF_OUT) {
                __half2 h0; h0.x = __float2half(acc[mt][nt][0]); h0.y = __float2half(acc[mt][nt][1]);
                __half2 h1; h1.x = __float2half(acc[mt][nt][2]); h1.y = __float2half(acc[mt][nt][3]);
                *(__half2*)(Ch + (size_t)r0 * N + cbase)       = h0;
                *(__half2*)(Ch + (size_t)(r0 + 8) * N + cbase) = h1;
            } else {
                *(float2*)(C + (size_t)r0 * N + cbase)       = make_float2(acc[mt][nt][0], acc[mt][nt][1]);
                *(float2*)(C + (size_t)(r0 + 8) * N + cbase) = make_float2(acc[mt][nt][2], acc[mt][nt][3]);
            }
        }
    }
}

// == Flash attention: fp16 1-pass, BK=128, Q frags hoisted, double-buffered ==
#define ABQ 128
#define ABK 128
#define AROW 136
#define AQ_E 0
#define AKV0_E (ABQ*AROW)         // 17408 elems (after Q)
#define AV_E (ABK*AROW)           // V offset within a KV buffer
#define KVBUF_E (2*ABK*AROW)      // 34816 elems (K + V)
#define ASM_BYTES ((AKV0_E + 2*KVBUF_E)*2)   // 174080
// scale * log2(e): softmax computed in base-2 domain
#define ATTN_SCALE2 0.1275258291089229f

__global__ void __launch_bounds__(256, 1)
attn_f16_kernel(const __half* __restrict__ QKV, __half* __restrict__ O)
{
    extern __shared__ __align__(1024) char smA[];
    const uint32_t sb = smem_u32(smA);

    const int tid  = threadIdx.x;
    const int lane = tid & 31;
    const int w    = tid >> 5;
    const int qi   = gridDim.x - 1 - blockIdx.x;   // big tiles first
    const int h    = blockIdx.y;
    const int b    = blockIdx.z;
    const int hk   = h >> 1;
    const int qbase = qi * ABQ;

    const __half* Qg = QKV + (size_t)(b*TT + qbase) * 4096 + h * DD;
    const __half* Kg = QKV + (size_t)(b*TT) * 4096 + 2048 + hk * DD;
    const __half* Vg = Kg + 1024;

    // ---- Q tile: 2048 chunks (128 rows x 16 chunks), strided rows ----
    #pragma unroll
    for (int i = 0; i < 8; i++) {
        int task = tid + 256 * i;        // 0..2047
        int row = task >> 4;             // 0..127
        int c   = task & 15;
        cp_async16(sb + 2 * (uint32_t)(AQ_E + row * AROW) + c * 16,
                   Qg + (size_t)row * 4096 + c * 8);
    }
    CP_COMMIT();

    auto load_kv = [&](int t, int buf) {
        const uint32_t base = sb + 2 * (uint32_t)(AKV0_E + buf * KVBUF_E);
        const int k0 = t * ABK;
        #pragma unroll
        for (int i = 0; i < 8; i++) {
            int task = tid + 256 * i;    // 0..2047
            int row = task >> 4, c = task & 15;
            cp_async16(base + 2 * (uint32_t)(row * AROW) + c * 16,
                       Kg + (size_t)(k0 + row) * 4096 + c * 8);
        }
        CP_COMMIT();
        #pragma unroll
        for (int i = 0; i < 8; i++) {
            int task = tid + 256 * i;
            int row = task >> 4, c = task & 15;
            cp_async16(base + 2 * (uint32_t)(AV_E + row * AROW) + c * 16,
                       Vg + (size_t)(k0 + row) * 4096 + c * 8);
        }
        CP_COMMIT();
    };

    load_kv(0, 0);

    CP_WAIT2();          // Q complete (K0,V0 may be in flight)
    __syncthreads();

    // ---- hoist Q fragments (reused every KV tile) ----
    const uint32_t qA = sb + 2*(uint32_t)(AQ_E + (w*16 + (lane & 15))*AROW) + (lane >> 4)*16;
    uint32_t qf[8][4];
    #pragma unroll
    for (int s = 0; s < 8; s++)
        ldsm4(qf[s], qA + s*32);

    float m0 = -INFINITY, m1 = -INFINITY, l0 = 0.f, l1 = 0.f;
    float oacc[16][4];
    #pragma unroll
    for (int j = 0; j < 16; j++)
        #pragma unroll
        for (int r = 0; r < 4; r++) oacc[j][r] = 0.f;

    const int krow  = ((lane >> 4) & 1)*8 + (lane & 7);
    const int kcolh = ((lane >> 3) & 1)*16;
    const int vrow  = ((lane >> 3) & 1)*8 + (lane & 7);
    const int vcolh = (lane >> 4)*16;

    const int ntiles = qi + 1;
    const int qr0 = qbase + w*16 + (lane >> 2);

    for (int t = 0; t < ntiles; t++) {
        const int k0 = t * ABK;
        const int buf = t & 1;

        if (t + 1 < ntiles) { load_kv(t + 1, buf ^ 1); CP_WAIT3(); }
        else                { CP_WAIT1(); }
        __syncthreads();     // K_t visible to all warps

        const uint32_t kvb = sb + 2 * (uint32_t)(AKV0_E + buf * KVBUF_E);

        // ---- S = Q K^T (single pass, 16 n-subtiles) ----
        float sacc[16][4];
        #pragma unroll
        for (int j = 0; j < 16; j++)
            #pragma unroll
            for (int r = 0; r < 4; r++) sacc[j][r] = 0.f;

        #pragma unroll
        for (int s = 0; s < 8; s++) {
            #pragma unroll
            for (int jj = 0; jj < 8; jj++) {
                uint32_t kf[4];
                uint32_t ka = kvb + 2*(uint32_t)((16*jj + krow)*AROW) + s*32 + kcolh;
                ldsm4(kf, ka);
                mma_f16(sacc[2*jj],   qf[s], &kf[0]);
                mma_f16(sacc[2*jj+1], qf[s], &kf[2]);
            }
        }

        if (t + 1 < ntiles) CP_WAIT2(); else CP_WAIT0();   // V_t complete
        __syncthreads();

        // ---- online softmax (base-2 domain) ----
        const bool domask = (t == ntiles - 1);
        float mx0 = -INFINITY, mx1 = -INFINITY;
        #pragma unroll
        for (int j = 0; j < 16; j++) {
            #pragma unroll
            for (int r = 0; r < 4; r++) {
                float sv = sacc[j][r] * ATTN_SCALE2;
                if (domask) {
                    int col = k0 + 8*j + (lane & 3)*2 + (r & 1);
                    int qr  = qr0 + ((r >= 2) ? 8 : 0);
                    if (col > qr) sv = -INFINITY;
                }
                sacc[j][r] = sv;
                if (r < 2) mx0 = fmaxf(mx0, sv); else mx1 = fmaxf(mx1, sv);
            }
        }
        mx0 = fmaxf(mx0, __shfl_xor_sync(0xffffffffu, mx0, 1));
        mx0 = fmaxf(mx0, __shfl_xor_sync(0xffffffffu, mx0, 2));
        mx1 = fmaxf(mx1, __shfl_xor_sync(0xffffffffu, mx1, 1));
        mx1 = fmaxf(mx1, __shfl_xor_sync(0xffffffffu, mx1, 2));

        float m0n = fmaxf(m0, mx0), m1n = fmaxf(m1, mx1);
        float a0 = exp2f(m0 - m0n), a1 = exp2f(m1 - m1n);
        float ls0 = 0.f, ls1 = 0.f;
        #pragma unroll
        for (int j = 0; j < 16; j++) {
            float p0 = exp2f(sacc[j][0] - m0n);
            float p1 = exp2f(sacc[j][1] - m0n);
            float p2 = exp2f(sacc[j][2] - m1n);
            float p3 = exp2f(sacc[j][3] - m1n);
            sacc[j][0] = p0; sacc[j][1] = p1; sacc[j][2] = p2; sacc[j][3] = p3;
            ls0 += p0 + p1; ls1 += p2 + p3;
        }
        ls0 += __shfl_xor_sync(0xffffffffu, ls0, 1);
        ls0 += __shfl_xor_sync(0xffffffffu, ls0, 2);
        ls1 += __shfl_xor_sync(0xffffffffu, ls1, 1);
        ls1 += __shfl_xor_sync(0xffffffffu, ls1, 2);

        l0 = l0 * a0 + ls0;
        l1 = l1 * a1 + ls1;
        m0 = m0n; m1 = m1n;
        #pragma unroll
        for (int j = 0; j < 16; j++) {
            oacc[j][0] *= a0; oacc[j][1] *= a0;
            oacc[j][2] *= a1; oacc[j][3] *= a1;
        }

        // ---- O += P V (single pass, 8 k16 steps) ----
        #pragma unroll
        for (int s2 = 0; s2 < 8; s2++) {
            uint32_t pp[4];
            pp[0] = pack_h2(sacc[2*s2][0],   sacc[2*s2][1]);
            pp[1] = pack_h2(sacc[2*s2][2],   sacc[2*s2][3]);
            pp[2] = pack_h2(sacc[2*s2+1][0], sacc[2*s2+1][1]);
            pp[3] = pack_h2(sacc[2*s2+1][2], sacc[2*s2+1][3]);
            uint32_t va = kvb + 2*(uint32_t)(AV_E + (16*s2 + vrow)*AROW) + vcolh;
            #pragma unroll
            for (int dd = 0; dd < 8; dd++) {
                uint32_t vf[4];
                ldsm4t(vf, va + dd*32);
                mma_f16(oacc[2*dd],   pp, &vf[0]);
                mma_f16(oacc[2*dd+1], pp, &vf[2]);
            }
        }
        __syncthreads();   // all reads of this buffer done before its next overwrite
    }

    // ---- epilogue: normalize + write single fp16 ([b,t,h*d] for Wp GEMM) ----
    float i0 = 1.f / l0, i1 = 1.f / l1;
    const int row0 = qbase + w*16 + (lane >> 2);
    const int col0 = (lane & 3)*2;
    #pragma unroll
    for (int j = 0; j < 16; j++) {
        int col = j*8 + col0;
        size_t base0 = ((size_t)(b*TT + row0)*HH + h)*DD + col;
        size_t base1 = base0 + (size_t)8*HH*DD;
        __half2 v0; v0.x = __float2half(oacc[j][0]*i0); v0.y = __float2half(oacc[j][1]*i0);
        __half2 v1; v1.x = __float2half(oacc[j][2]*i1); v1.y = __float2half(oacc[j][3]*i1);
        *(__half2*)(O + base0) = v0;
        *(__half2*)(O + base1) = v1;
    }
}

// ---------------- host entry -------------------------------------------------
extern "C" void kernel_launch(void* const* d_in, const int* in_sizes, int n_in,
                              void* d_out, int out_size)
{
    const float* x  = (const float*)d_in[0];
    const float* Wq = (const float*)d_in[1];
    const float* Wk = (const float*)d_in[2];
    const float* Wv = (const float*)d_in[3];
    const float* Wp = (const float*)d_in[4];
    float* out = (float*)d_out;

    __half *qkvh, *xf, *of, *wqkv, *wp;
    cudaGetSymbolAddress((void**)&qkvh, g_qkvh);
    cudaGetSymbolAddress((void**)&xf, g_xf);
    cudaGetSymbolAddress((void**)&of, g_of);
    cudaGetSymbolAddress((void**)&wqkv, g_wqkv);
    cudaGetSymbolAddress((void**)&wp, g_wp);

    cudaFuncSetAttribute(gemm_f16_kernel<0>, cudaFuncAttributeMaxDynamicSharedMemorySize, GEMM_SMEM);
    cudaFuncSetAttribute(gemm_f16_kernel<1>, cudaFuncAttributeMaxDynamicSharedMemorySize, GEMM_SMEM);
    cudaFuncSetAttribute(attn_f16_kernel, cudaFuncAttributeMaxDynamicSharedMemorySize, ASM_BYTES);

    // (1) all weight transposes + x conversion in ONE launch
    prep_kernel<<<16384, dim3(32, 8)>>>(Wq, Wk, Wv, Wp, x, wqkv, wp, xf);

    // (2) fused QKV projection -> fp16 qkv
    gemm_f16_kernel<1><<<dim3(4096/GBN, NROW/GBM), GEMM_THREADS, GEMM_SMEM>>>(
        xf, wqkv, nullptr, qkvh, NROW, 4096, CC);

    // (3) in-place RoPE on Q and K heads
    {
        int tot = NROW * 24 * 64;
        rope_inplace_kernel<<<(tot + 255) / 256, 256>>>(qkvh, tot);
    }

    // (4) attention (fp16 1-pass HMMA, BK=128), fp16 O out
    attn_f16_kernel<<<dim3(TT / ABQ, HH, BB), 256, ASM_BYTES>>>(qkvh, of);

    // (5) output projection (fp32 out)
    gemm_f16_kernel<0><<<dim3(CC/GBN, NROW/GBM), GEMM_THREADS, GEMM_SMEM>>>(
        of, wp, out, nullptr, NROW, CC, CC);
}